// round 1
// baseline (speedup 1.0000x reference)
#include <cuda_runtime.h>

// Problem constants (match reference)
#define NN   100000
#define HH   128
#define EE   1600000
#define EXTD 768
#define EPSV 1e-5f

// ---------------- scratch (no allocations allowed) ----------------
__device__ float g_dinv[NN];          // degree, then rsqrt(degree)
__device__ float g_norm[EE];          // per-edge symmetric norm
__device__ float g_tmp [NN * HH];     // encoder pre-LN output
__device__ float g_xcat[NN * 2 * HH]; // [emb | feat] concat
__device__ float g_x   [NN * HH];     // current node features
__device__ float g_xw  [NN * HH];     // x @ W
__device__ float g_agg [NN * HH];     // SPMM accumulator

// ---------------- graph prep ----------------
__global__ void k_deg_init() {
    int i = blockIdx.x * blockDim.x + threadIdx.x;
    if (i < NN) g_dinv[i] = 1.0f;  // self-loop counts as 1
}

__global__ void k_degree(const int* __restrict__ dst) {
    int e = blockIdx.x * blockDim.x + threadIdx.x;
    if (e < EE) atomicAdd(&g_dinv[dst[e]], 1.0f);
}

__global__ void k_dinv() {
    int i = blockIdx.x * blockDim.x + threadIdx.x;
    if (i < NN) g_dinv[i] = rsqrtf(g_dinv[i]);
}

__global__ void k_norm(const int* __restrict__ src, const int* __restrict__ dst) {
    int e = blockIdx.x * blockDim.x + threadIdx.x;
    if (e < EE) g_norm[e] = g_dinv[src[e]] * g_dinv[dst[e]];
}

// ---------------- tiled fp32 GEMM: C[M,128] = A[M,K] @ B[K,128] (+bias) ----------------
// BM=64, BN=128, BK=16, 256 threads, each thread computes 8x4 outputs.
template <int K>
__global__ void __launch_bounds__(256)
k_gemm(const float* __restrict__ A, const float* __restrict__ B,
       const float* __restrict__ bias, float* __restrict__ C)
{
    __shared__ float As[16][64];    // k-major for broadcast-friendly reads
    __shared__ float Bs[16][128];

    const int tid = threadIdx.x;
    const int tx  = tid & 31;       // col group: cols tx*4 .. tx*4+3
    const int ty  = tid >> 5;       // row group: rows ty*8 .. ty*8+7
    const int rowBase = blockIdx.x * 64;

    // A tile load mapping: 64 rows x 16 k = 256 float4 (contiguous along k)
    const int aRow = tid >> 2;          // 0..63
    const int aK   = (tid & 3) * 4;     // 0,4,8,12
    // B tile load mapping: 16 x 128 = 2048 floats = 8 per thread (2 float4)
    const int bIdx = tid * 8;
    const int bK   = bIdx >> 7;
    const int bCol = bIdx & 127;

    float acc[8][4];
    #pragma unroll
    for (int i = 0; i < 8; i++)
        #pragma unroll
        for (int j = 0; j < 4; j++) acc[i][j] = 0.0f;

    const int gr = rowBase + aRow;
    const bool aOk = (gr < NN);

    for (int k0 = 0; k0 < K; k0 += 16) {
        // load A tile
        float4 av = make_float4(0.f, 0.f, 0.f, 0.f);
        if (aOk) av = *(const float4*)&A[(long)gr * K + k0 + aK];
        As[aK + 0][aRow] = av.x;
        As[aK + 1][aRow] = av.y;
        As[aK + 2][aRow] = av.z;
        As[aK + 3][aRow] = av.w;
        // load B tile (two float4 per thread)
        *(float4*)&Bs[bK][bCol]     = *(const float4*)&B[(long)(k0 + bK) * 128 + bCol];
        *(float4*)&Bs[bK][bCol + 4] = *(const float4*)&B[(long)(k0 + bK) * 128 + bCol + 4];
        __syncthreads();

        #pragma unroll
        for (int kk = 0; kk < 16; kk++) {
            float4 a0 = *(const float4*)&As[kk][ty * 8];
            float4 a1 = *(const float4*)&As[kk][ty * 8 + 4];
            float4 bq = *(const float4*)&Bs[kk][tx * 4];
            float a[8] = {a0.x, a0.y, a0.z, a0.w, a1.x, a1.y, a1.z, a1.w};
            float b[4] = {bq.x, bq.y, bq.z, bq.w};
            #pragma unroll
            for (int i = 0; i < 8; i++)
                #pragma unroll
                for (int j = 0; j < 4; j++)
                    acc[i][j] = fmaf(a[i], b[j], acc[i][j]);
        }
        __syncthreads();
    }

    float4 bv = make_float4(0.f, 0.f, 0.f, 0.f);
    if (bias) bv = *(const float4*)&bias[tx * 4];

    #pragma unroll
    for (int i = 0; i < 8; i++) {
        int r = rowBase + ty * 8 + i;
        if (r < NN) {
            float4 o;
            o.x = acc[i][0] + bv.x;
            o.y = acc[i][1] + bv.y;
            o.z = acc[i][2] + bv.z;
            o.w = acc[i][3] + bv.w;
            *(float4*)&C[(long)r * 128 + tx * 4] = o;
        }
    }
}

// ---------------- LayerNorm + ReLU on g_tmp, build [emb|feat] concat ----------------
// One warp per node row (128 elems -> 4 per lane).
__global__ void k_ln_concat(const float* __restrict__ emb,
                            const float* __restrict__ lng,
                            const float* __restrict__ lnb)
{
    int w    = (blockIdx.x * blockDim.x + threadIdx.x) >> 5;
    int lane = threadIdx.x & 31;
    if (w >= NN) return;

    float4 v = *(const float4*)&g_tmp[(long)w * 128 + lane * 4];
    float s  = v.x + v.y + v.z + v.w;
    float sq = v.x * v.x + v.y * v.y + v.z * v.z + v.w * v.w;
    #pragma unroll
    for (int o = 16; o > 0; o >>= 1) {
        s  += __shfl_xor_sync(0xffffffffu, s,  o);
        sq += __shfl_xor_sync(0xffffffffu, sq, o);
    }
    float mu  = s * (1.0f / 128.0f);
    float var = sq * (1.0f / 128.0f) - mu * mu;
    float r   = rsqrtf(var + EPSV);

    float4 gg = *(const float4*)&lng[lane * 4];
    float4 bb = *(const float4*)&lnb[lane * 4];
    float4 o;
    o.x = fmaxf((v.x - mu) * r * gg.x + bb.x, 0.0f);
    o.y = fmaxf((v.y - mu) * r * gg.y + bb.y, 0.0f);
    o.z = fmaxf((v.z - mu) * r * gg.z + bb.z, 0.0f);
    o.w = fmaxf((v.w - mu) * r * gg.w + bb.w, 0.0f);

    *(float4*)&g_xcat[(long)w * 256 + 128 + lane * 4] = o;
    *(float4*)&g_xcat[(long)w * 256 + lane * 4] =
        *(const float4*)&emb[(long)w * 128 + lane * 4];
}

// ---------------- agg init: self-loop contribution (replaces memset) ----------------
__global__ void k_agg_init() {
    int t = blockIdx.x * blockDim.x + threadIdx.x;
    if (t >= NN * 32) return;
    int row = t >> 5;
    int c   = (t & 31) * 4;
    float di = g_dinv[row];
    float wt = di * di;
    float4 v = *(const float4*)&g_xw[(long)row * 128 + c];
    v.x *= wt; v.y *= wt; v.z *= wt; v.w *= wt;
    *(float4*)&g_agg[(long)row * 128 + c] = v;
}

// ---------------- SPMM: agg[dst] += norm * xw[src], warp per edge ----------------
__global__ void k_spmm(const int* __restrict__ src, const int* __restrict__ dst) {
    int w = (blockIdx.x * blockDim.x + threadIdx.x) >> 5;
    if (w >= EE) return;
    int lane = threadIdx.x & 31;
    int s = src[w];
    int d = dst[w];
    float nrm = g_norm[w];
    float4 v = *(const float4*)&g_xw[(long)s * 128 + lane * 4];
    float* o = &g_agg[(long)d * 128 + lane * 4];
    atomicAdd(o + 0, nrm * v.x);
    atomicAdd(o + 1, nrm * v.y);
    atomicAdd(o + 2, nrm * v.z);
    atomicAdd(o + 3, nrm * v.w);
}

// ---------------- epilogue: out = act(agg + bias) ----------------
__global__ void k_epi(const float* __restrict__ bias, float* __restrict__ out, int relu) {
    int t = blockIdx.x * blockDim.x + threadIdx.x;
    if (t >= NN * 32) return;
    int row = t >> 5;
    int c   = (t & 31) * 4;
    float4 v  = *(const float4*)&g_agg[(long)row * 128 + c];
    float4 bb = *(const float4*)&bias[c];
    v.x += bb.x; v.y += bb.y; v.z += bb.z; v.w += bb.w;
    if (relu) {
        v.x = fmaxf(v.x, 0.0f); v.y = fmaxf(v.y, 0.0f);
        v.z = fmaxf(v.z, 0.0f); v.w = fmaxf(v.w, 0.0f);
    }
    *(float4*)&out[(long)row * 128 + c] = v;
}

// ---------------- launch ----------------
extern "C" void kernel_launch(void* const* d_in, const int* in_sizes, int n_in,
                              void* d_out, int out_size)
{
    const int*   ei    = (const int*)  d_in[0];   // [2, E] int32
    const float* ext   = (const float*)d_in[1];   // [N, 768]
    const float* emb   = (const float*)d_in[2];   // [N, 128]
    const float* encW  = (const float*)d_in[3];   // [768, 128]
    const float* encB  = (const float*)d_in[4];
    const float* lng   = (const float*)d_in[5];
    const float* lnb   = (const float*)d_in[6];
    const float* projW = (const float*)d_in[7];   // [256, 128]
    const float* projB = (const float*)d_in[8];
    const float* W0    = (const float*)d_in[9];
    const float* b0    = (const float*)d_in[10];
    const float* W1    = (const float*)d_in[11];
    const float* b1    = (const float*)d_in[12];
    const float* W2    = (const float*)d_in[13];
    const float* b2    = (const float*)d_in[14];
    float* out = (float*)d_out;

    const int* src = ei;
    const int* dst = ei + EE;

    float *p_tmp, *p_xcat, *p_x, *p_xw;
    cudaGetSymbolAddress((void**)&p_tmp,  g_tmp);
    cudaGetSymbolAddress((void**)&p_xcat, g_xcat);
    cudaGetSymbolAddress((void**)&p_x,    g_x);
    cudaGetSymbolAddress((void**)&p_xw,   g_xw);

    const int TB = 256;
    const int gN   = (NN + TB - 1) / TB;
    const int gE   = (EE + TB - 1) / TB;
    const int gRow = (NN * 32 + TB - 1) / TB;       // warp-per-row / elem4 kernels
    const int gEdgeWarp = (EE * 32 + TB - 1) / TB;  // warp-per-edge
    const int gGemm = (NN + 63) / 64;

    // graph prep
    k_deg_init<<<gN, TB>>>();
    k_degree<<<gE, TB>>>(dst);
    k_dinv<<<gN, TB>>>();
    k_norm<<<gE, TB>>>(src, dst);

    // encoder: tmp = ext @ encW + encB ; feat = relu(LN(tmp)) ; xcat = [emb|feat]
    k_gemm<EXTD><<<gGemm, TB>>>(ext, encW, encB, p_tmp);
    k_ln_concat<<<gRow, TB>>>(emb, lng, lnb);

    // projection: x = xcat @ projW + projB
    k_gemm<2 * HH><<<gGemm, TB>>>(p_xcat, projW, projB, p_x);

    // layer 0
    k_gemm<HH><<<gGemm, TB>>>(p_x, W0, nullptr, p_xw);
    k_agg_init<<<gRow, TB>>>();
    k_spmm<<<gEdgeWarp, TB>>>(src, dst);
    k_epi<<<gRow, TB>>>(b0, p_x, 1);

    // layer 1
    k_gemm<HH><<<gGemm, TB>>>(p_x, W1, nullptr, p_xw);
    k_agg_init<<<gRow, TB>>>();
    k_spmm<<<gEdgeWarp, TB>>>(src, dst);
    k_epi<<<gRow, TB>>>(b1, p_x, 1);

    // layer 2 (no relu, write d_out)
    k_gemm<HH><<<gGemm, TB>>>(p_x, W2, nullptr, p_xw);
    k_agg_init<<<gRow, TB>>>();
    k_spmm<<<gEdgeWarp, TB>>>(src, dst);
    k_epi<<<gRow, TB>>>(b2, out, 0);
}

// round 3
// speedup vs baseline: 1.5085x; 1.5085x over previous
#include <cuda_runtime.h>
#include <cuda_bf16.h>
#include <cstdint>

// Problem constants
#define NN   100000
#define HH   128
#define EE   1600000
#define EXTD 768
#define EPSV 1e-5f

// ================= device scratch (no allocations allowed) =================
__device__ float g_dinv[NN];
__device__ float g_norm[EE];
__device__ float g_tmp [NN * HH];
__device__ float g_xcat[NN * 2 * HH];
__device__ float g_x   [NN * HH];
__device__ float g_xw  [NN * HH];
__device__ float g_agg [NN * HH];

// split-bf16 transposed weights: [N=128 rows][K cols]
__device__ __nv_bfloat16 g_bh_enc [128 * 768];
__device__ __nv_bfloat16 g_bl_enc [128 * 768];
__device__ __nv_bfloat16 g_bh_proj[128 * 256];
__device__ __nv_bfloat16 g_bl_proj[128 * 256];
__device__ __nv_bfloat16 g_bh_w0  [128 * 128];
__device__ __nv_bfloat16 g_bl_w0  [128 * 128];
__device__ __nv_bfloat16 g_bh_w1  [128 * 128];
__device__ __nv_bfloat16 g_bl_w1  [128 * 128];
__device__ __nv_bfloat16 g_bh_w2  [128 * 128];
__device__ __nv_bfloat16 g_bl_w2  [128 * 128];

// ================= helpers =================
__device__ __forceinline__ uint32_t smem_u32(const void* p) {
    uint32_t a;
    asm("{ .reg .u64 t; cvta.to.shared.u64 t, %1; cvt.u32.u64 %0, t; }" : "=r"(a) : "l"(p));
    return a;
}
__device__ __forceinline__ uint32_t sw128(uint32_t o) { return o ^ ((o >> 3) & 0x70); }

__device__ __forceinline__ void ldsm_x4(uint32_t* r, uint32_t addr) {
    asm volatile("ldmatrix.sync.aligned.m8n8.x4.shared.b16 {%0,%1,%2,%3}, [%4];"
        : "=r"(r[0]), "=r"(r[1]), "=r"(r[2]), "=r"(r[3]) : "r"(addr));
}
__device__ __forceinline__ void mma16816(float* c, const uint32_t* a, const uint32_t* b) {
    asm volatile(
        "mma.sync.aligned.m16n8k16.row.col.f32.bf16.bf16.f32 "
        "{%0,%1,%2,%3}, {%4,%5,%6,%7}, {%8,%9}, {%0,%1,%2,%3};"
        : "+f"(c[0]), "+f"(c[1]), "+f"(c[2]), "+f"(c[3])
        : "r"(a[0]), "r"(a[1]), "r"(a[2]), "r"(a[3]), "r"(b[0]), "r"(b[1]));
}

__device__ __forceinline__ uint32_t packbf2(float a, float b, float* ra, float* rb) {
    __nv_bfloat16 ha = __float2bfloat16_rn(a), hb = __float2bfloat16_rn(b);
    if (ra) { *ra = a - __bfloat162float(ha); *rb = b - __bfloat162float(hb); }
    return (uint32_t)__bfloat16_as_ushort(ha) | ((uint32_t)__bfloat16_as_ushort(hb) << 16);
}

// ================= graph prep =================
__global__ void k_deg_init() {
    int i = blockIdx.x * blockDim.x + threadIdx.x;
    if (i < NN) g_dinv[i] = 1.0f;
}
__global__ void k_degree(const int* __restrict__ dst) {
    int e = blockIdx.x * blockDim.x + threadIdx.x;
    if (e < EE) atomicAdd(&g_dinv[dst[e]], 1.0f);
}
__global__ void k_dinv() {
    int i = blockIdx.x * blockDim.x + threadIdx.x;
    if (i < NN) g_dinv[i] = rsqrtf(g_dinv[i]);
}
__global__ void k_norm(const int* __restrict__ src, const int* __restrict__ dst) {
    int e = blockIdx.x * blockDim.x + threadIdx.x;
    if (e < EE) g_norm[e] = g_dinv[src[e]] * g_dinv[dst[e]];
}

// ================= weight split: W[K][128] -> Bh/Bl [128][K] bf16 =================
__global__ void k_split(const float* __restrict__ W, int K,
                        __nv_bfloat16* __restrict__ Bh, __nv_bfloat16* __restrict__ Bl) {
    int idx = blockIdx.x * blockDim.x + threadIdx.x;
    if (idx >= K * 128) return;
    int k = idx >> 7;
    int n = idx & 127;
    float w = W[idx];
    __nv_bfloat16 h = __float2bfloat16_rn(w);
    float r = w - __bfloat162float(h);
    Bh[n * K + k] = h;
    Bl[n * K + k] = __float2bfloat16_rn(r);
}

// ================= mma.sync split-bf16 GEMM: C[M,128] = A[M,K] @ W[K,128] =================
// 128-row tile per CTA, K chunks of 64, 256 threads (8 warps, each 32x64).
#define TILE_B 16384   // 128 rows x 64 bf16 x 2B = 128B/row
#define GEMM_DYN (4 * TILE_B + 1024)

__global__ void __launch_bounds__(256)
k_gemm_mma(const float* __restrict__ A, int K,
           const __nv_bfloat16* __restrict__ Bh, const __nv_bfloat16* __restrict__ Bl,
           const float* __restrict__ bias, int relu, int aggInit,
           float* __restrict__ C)
{
    extern __shared__ char dyn[];
    const int tid = threadIdx.x;
    const int rowBase = blockIdx.x * 128;

    // 1024-align dynamic smem
    uint32_t dynb = smem_u32(dyn);
    char* sm = dyn + (((dynb + 1023u) & ~1023u) - dynb);
    char* sAh = sm;
    char* sAl = sm + TILE_B;
    char* sBh = sm + 2 * TILE_B;
    char* sBl = sm + 3 * TILE_B;
    const uint32_t uAh = smem_u32(sAh), uAl = smem_u32(sAl);
    const uint32_t uBh = smem_u32(sBh), uBl = smem_u32(sBl);

    const int lane = tid & 31;
    const int warp = tid >> 5;
    const int mBase = (warp & 3) * 32;   // 2 m-tiles of 16
    const int nBase = (warp >> 2) * 64;  // 8 n-tiles of 8

    // ldmatrix lane address components
    const int aRowL = (lane & 7) + ((lane & 8) ? 8 : 0);   // within 16-row m-tile
    const int aKbL  = (lane & 16) ? 16 : 0;                // second k-half bytes
    const int bRowL = (lane & 7) + ((lane & 16) ? 8 : 0);  // within 16-n pair
    const int bKbL  = (lane & 8) ? 16 : 0;

    float acc[2][8][4];
    #pragma unroll
    for (int mt = 0; mt < 2; mt++)
        #pragma unroll
        for (int nt = 0; nt < 8; nt++)
            #pragma unroll
            for (int j = 0; j < 4; j++) acc[mt][nt][j] = 0.0f;

    const int nChunks = K >> 6;

    for (int c = 0; c < nChunks; c++) {
        const int k0 = c * 64;

        // ---- stage A chunk: fp32 -> hi/lo bf16, swizzled (coalesced: 16 thr/row) ----
        #pragma unroll
        for (int i = 0; i < 8; i++) {
            int fidx = i * 256 + tid;        // 0..2047 float4 units
            int r    = fidx >> 4;            // row 0..127
            int kq   = fidx & 15;            // float4 within 64-k chunk
            int gr   = rowBase + r;
            float4 f = make_float4(0.f, 0.f, 0.f, 0.f);
            if (gr < NN) f = *(const float4*)&A[(size_t)gr * K + k0 + kq * 4];
            float r0, r1, r2, r3;
            uint32_t h0 = packbf2(f.x, f.y, &r0, &r1);
            uint32_t h1 = packbf2(f.z, f.w, &r2, &r3);
            uint32_t l0 = packbf2(r0, r1, nullptr, nullptr);
            uint32_t l1 = packbf2(r2, r3, nullptr, nullptr);
            uint32_t off = sw128((uint32_t)(r * 128 + kq * 8));
            *(uint2*)(sAh + off) = make_uint2(h0, h1);
            *(uint2*)(sAl + off) = make_uint2(l0, l1);
        }

        // ---- stage B chunk: pre-split bf16, coalesced uint4, swizzled ----
        #pragma unroll
        for (int i = 0; i < 4; i++) {
            int uidx = i * 256 + tid;        // 0..1023 uint4 units
            int n    = uidx >> 3;            // 0..127
            int kq   = uidx & 7;             // uint4 (8 bf16) within row
            uint4 vh = *(const uint4*)(Bh + (size_t)n * K + k0 + kq * 8);
            uint4 vl = *(const uint4*)(Bl + (size_t)n * K + k0 + kq * 8);
            uint32_t off = sw128((uint32_t)(n * 128 + kq * 16));
            *(uint4*)(sBh + off) = vh;
            *(uint4*)(sBl + off) = vl;
        }
        __syncthreads();

        // ---- compute: 4 k16-steps, splits Ah*Bh + Al*Bh + Ah*Bl ----
        #pragma unroll
        for (int ks = 0; ks < 4; ks++) {
            const int kb = ks * 32;
            uint32_t af[2][4], bf[4][4];

            #pragma unroll
            for (int p = 0; p < 4; p++)
                ldsm_x4(bf[p], uBh + sw128((uint32_t)((nBase + p * 16 + bRowL) * 128 + kb + bKbL)));
            #pragma unroll
            for (int mt = 0; mt < 2; mt++)
                ldsm_x4(af[mt], uAh + sw128((uint32_t)((mBase + mt * 16 + aRowL) * 128 + kb + aKbL)));
            #pragma unroll
            for (int mt = 0; mt < 2; mt++)
                #pragma unroll
                for (int p = 0; p < 4; p++) {
                    mma16816(acc[mt][2 * p],     af[mt], &bf[p][0]);
                    mma16816(acc[mt][2 * p + 1], af[mt], &bf[p][2]);
                }

            #pragma unroll
            for (int mt = 0; mt < 2; mt++)
                ldsm_x4(af[mt], uAl + sw128((uint32_t)((mBase + mt * 16 + aRowL) * 128 + kb + aKbL)));
            #pragma unroll
            for (int mt = 0; mt < 2; mt++)
                #pragma unroll
                for (int p = 0; p < 4; p++) {
                    mma16816(acc[mt][2 * p],     af[mt], &bf[p][0]);
                    mma16816(acc[mt][2 * p + 1], af[mt], &bf[p][2]);
                }

            #pragma unroll
            for (int mt = 0; mt < 2; mt++)
                ldsm_x4(af[mt], uAh + sw128((uint32_t)((mBase + mt * 16 + aRowL) * 128 + kb + aKbL)));
            #pragma unroll
            for (int p = 0; p < 4; p++)
                ldsm_x4(bf[p], uBl + sw128((uint32_t)((nBase + p * 16 + bRowL) * 128 + kb + bKbL)));
            #pragma unroll
            for (int mt = 0; mt < 2; mt++)
                #pragma unroll
                for (int p = 0; p < 4; p++) {
                    mma16816(acc[mt][2 * p],     af[mt], &bf[p][0]);
                    mma16816(acc[mt][2 * p + 1], af[mt], &bf[p][2]);
                }
        }
        __syncthreads();
    }

    // ---- epilogue: registers -> gmem, fused bias/relu/agg-init ----
    const int rL = lane >> 2;
    const int cL = (lane & 3) * 2;
    #pragma unroll
    for (int mt = 0; mt < 2; mt++) {
        #pragma unroll
        for (int half = 0; half < 2; half++) {   // c pair (0,1) row, (2,3) row+8
            int row = rowBase + mBase + mt * 16 + rL + half * 8;
            if (row >= NN) continue;
            float wt = 0.0f;
            if (aggInit) { float d = g_dinv[row]; wt = d * d; }
            #pragma unroll
            for (int nt = 0; nt < 8; nt++) {
                int col = nBase + nt * 8 + cL;
                float v0 = acc[mt][nt][half * 2];
                float v1 = acc[mt][nt][half * 2 + 1];
                if (bias) { v0 += bias[col]; v1 += bias[col + 1]; }
                if (relu) { v0 = fmaxf(v0, 0.f); v1 = fmaxf(v1, 0.f); }
                *(float2*)&C[(size_t)row * 128 + col] = make_float2(v0, v1);
                if (aggInit)
                    *(float2*)&g_agg[(size_t)row * 128 + col] = make_float2(v0 * wt, v1 * wt);
            }
        }
    }
}

// ================= LayerNorm+ReLU on g_tmp -> build [emb|feat] concat =================
__global__ void k_ln_concat(const float* __restrict__ emb,
                            const float* __restrict__ lng,
                            const float* __restrict__ lnb)
{
    int w    = (blockIdx.x * blockDim.x + threadIdx.x) >> 5;
    int lane = threadIdx.x & 31;
    if (w >= NN) return;

    float4 v = *(const float4*)&g_tmp[(size_t)w * 128 + lane * 4];
    float s  = v.x + v.y + v.z + v.w;
    float sq = v.x * v.x + v.y * v.y + v.z * v.z + v.w * v.w;
    #pragma unroll
    for (int o = 16; o > 0; o >>= 1) {
        s  += __shfl_xor_sync(0xffffffffu, s,  o);
        sq += __shfl_xor_sync(0xffffffffu, sq, o);
    }
    float mu  = s * (1.0f / 128.0f);
    float var = sq * (1.0f / 128.0f) - mu * mu;
    float r   = rsqrtf(var + EPSV);

    float4 gg = *(const float4*)&lng[lane * 4];
    float4 bb = *(const float4*)&lnb[lane * 4];
    float4 o;
    o.x = fmaxf((v.x - mu) * r * gg.x + bb.x, 0.0f);
    o.y = fmaxf((v.y - mu) * r * gg.y + bb.y, 0.0f);
    o.z = fmaxf((v.z - mu) * r * gg.z + bb.z, 0.0f);
    o.w = fmaxf((v.w - mu) * r * gg.w + bb.w, 0.0f);

    *(float4*)&g_xcat[(size_t)w * 256 + 128 + lane * 4] = o;
    *(float4*)&g_xcat[(size_t)w * 256 + lane * 4] =
        *(const float4*)&emb[(size_t)w * 128 + lane * 4];
}

// ================= SPMM: agg[dst] += norm * xw[src], warp per edge, red.v4 =================
__global__ void k_spmm(const int* __restrict__ src, const int* __restrict__ dst) {
    int w = (blockIdx.x * blockDim.x + threadIdx.x) >> 5;
    if (w >= EE) return;
    int lane = threadIdx.x & 31;
    int s = src[w];
    int d = dst[w];
    float nrm = g_norm[w];
    float4 v = *(const float4*)&g_xw[(size_t)s * 128 + lane * 4];
    float* o = &g_agg[(size_t)d * 128 + lane * 4];
    asm volatile("red.global.add.v4.f32 [%0], {%1, %2, %3, %4};"
                 :: "l"(o), "f"(nrm * v.x), "f"(nrm * v.y), "f"(nrm * v.z), "f"(nrm * v.w)
                 : "memory");
}

// ================= epilogue: out = act(agg + bias) =================
__global__ void k_epi(const float* __restrict__ bias, float* __restrict__ out, int relu) {
    int t = blockIdx.x * blockDim.x + threadIdx.x;
    if (t >= NN * 32) return;
    int row = t >> 5;
    int c   = (t & 31) * 4;
    float4 v  = *(const float4*)&g_agg[(size_t)row * 128 + c];
    float4 bb = *(const float4*)&bias[c];
    v.x += bb.x; v.y += bb.y; v.z += bb.z; v.w += bb.w;
    if (relu) {
        v.x = fmaxf(v.x, 0.0f); v.y = fmaxf(v.y, 0.0f);
        v.z = fmaxf(v.z, 0.0f); v.w = fmaxf(v.w, 0.0f);
    }
    *(float4*)&out[(size_t)row * 128 + c] = v;
}

// ================= launch =================
extern "C" void kernel_launch(void* const* d_in, const int* in_sizes, int n_in,
                              void* d_out, int out_size)
{
    (void)in_sizes; (void)n_in; (void)out_size;
    const int*   ei    = (const int*)  d_in[0];
    const float* ext   = (const float*)d_in[1];
    const float* emb   = (const float*)d_in[2];
    const float* encW  = (const float*)d_in[3];
    const float* encB  = (const float*)d_in[4];
    const float* lng   = (const float*)d_in[5];
    const float* lnb   = (const float*)d_in[6];
    const float* projW = (const float*)d_in[7];
    const float* projB = (const float*)d_in[8];
    const float* W0    = (const float*)d_in[9];
    const float* b0    = (const float*)d_in[10];
    const float* W1    = (const float*)d_in[11];
    const float* b1    = (const float*)d_in[12];
    const float* W2    = (const float*)d_in[13];
    const float* b2    = (const float*)d_in[14];
    float* out = (float*)d_out;

    const int* src = ei;
    const int* dst = ei + EE;

    float *p_tmp, *p_xcat, *p_x, *p_xw;
    cudaGetSymbolAddress((void**)&p_tmp,  g_tmp);
    cudaGetSymbolAddress((void**)&p_xcat, g_xcat);
    cudaGetSymbolAddress((void**)&p_x,    g_x);
    cudaGetSymbolAddress((void**)&p_xw,   g_xw);

    __nv_bfloat16 *bh_enc, *bl_enc, *bh_proj, *bl_proj, *bh_w0, *bl_w0, *bh_w1, *bl_w1, *bh_w2, *bl_w2;
    cudaGetSymbolAddress((void**)&bh_enc,  g_bh_enc);
    cudaGetSymbolAddress((void**)&bl_enc,  g_bl_enc);
    cudaGetSymbolAddress((void**)&bh_proj, g_bh_proj);
    cudaGetSymbolAddress((void**)&bl_proj, g_bl_proj);
    cudaGetSymbolAddress((void**)&bh_w0,   g_bh_w0);
    cudaGetSymbolAddress((void**)&bl_w0,   g_bl_w0);
    cudaGetSymbolAddress((void**)&bh_w1,   g_bh_w1);
    cudaGetSymbolAddress((void**)&bl_w1,   g_bl_w1);
    cudaGetSymbolAddress((void**)&bh_w2,   g_bh_w2);
    cudaGetSymbolAddress((void**)&bl_w2,   g_bl_w2);

    cudaFuncSetAttribute(k_gemm_mma, cudaFuncAttributeMaxDynamicSharedMemorySize, GEMM_DYN);

    const int TB = 256;
    const int gN        = (NN + TB - 1) / TB;
    const int gE        = (EE + TB - 1) / TB;
    const int gRow      = (NN * 32 + TB - 1) / TB;
    const int gEdgeWarp = (EE * 32 + TB - 1) / TB;
    const int gGemm     = (NN + 127) / 128;

    // graph prep
    k_deg_init<<<gN, TB>>>();
    k_degree<<<gE, TB>>>(dst);
    k_dinv<<<gN, TB>>>();
    k_norm<<<gE, TB>>>(src, dst);

    // split weights (transposed bf16 hi/lo)
    k_split<<<(768 * 128 + TB - 1) / TB, TB>>>(encW,  768, bh_enc,  bl_enc);
    k_split<<<(256 * 128 + TB - 1) / TB, TB>>>(projW, 256, bh_proj, bl_proj);
    k_split<<<(128 * 128 + TB - 1) / TB, TB>>>(W0,    128, bh_w0,   bl_w0);
    k_split<<<(128 * 128 + TB - 1) / TB, TB>>>(W1,    128, bh_w1,   bl_w1);
    k_split<<<(128 * 128 + TB - 1) / TB, TB>>>(W2,    128, bh_w2,   bl_w2);

    // encoder GEMM + LN/concat
    k_gemm_mma<<<gGemm, TB, GEMM_DYN>>>(ext, 768, bh_enc, bl_enc, encB, 0, 0, p_tmp);
    k_ln_concat<<<gRow, TB>>>(emb, lng, lnb);

    // projection
    k_gemm_mma<<<gGemm, TB, GEMM_DYN>>>(p_xcat, 256, bh_proj, bl_proj, projB, 0, 0, p_x);

    // layer 0
    k_gemm_mma<<<gGemm, TB, GEMM_DYN>>>(p_x, 128, bh_w0, bl_w0, nullptr, 0, 1, p_xw);
    k_spmm<<<gEdgeWarp, TB>>>(src, dst);
    k_epi<<<gRow, TB>>>(b0, p_x, 1);

    // layer 1
    k_gemm_mma<<<gGemm, TB, GEMM_DYN>>>(p_x, 128, bh_w1, bl_w1, nullptr, 0, 1, p_xw);
    k_spmm<<<gEdgeWarp, TB>>>(src, dst);
    k_epi<<<gRow, TB>>>(b1, p_x, 1);

    // layer 2 (no relu, write d_out)
    k_gemm_mma<<<gGemm, TB, GEMM_DYN>>>(p_x, 128, bh_w2, bl_w2, nullptr, 0, 1, p_xw);
    k_spmm<<<gEdgeWarp, TB>>>(src, dst);
    k_epi<<<gRow, TB>>>(b2, out, 0);
}

// round 4
// speedup vs baseline: 2.1992x; 1.4578x over previous
#include <cuda_runtime.h>
#include <cuda_bf16.h>
#include <cstdint>

// Problem constants
#define NN   100000
#define HH   128
#define EE   1600000
#define EXTD 768
#define EPSV 1e-5f

// ================= device scratch (no allocations allowed) =================
__device__ float g_dinv[NN];
__device__ int   g_degi[NN];
__device__ int   g_cursor[NN];
__device__ int   g_rowptr[NN + 1];
__device__ int   g_bsum[128];
__device__ int   g_bsumx[128];
__device__ int2  g_epack[EE];          // (src, norm-bits) sorted by dst
__device__ float g_tmp [NN * HH];
__device__ float g_xcat[NN * 2 * HH];
__device__ float g_x   [NN * HH];
__device__ float g_xw  [NN * HH];

// split-bf16 transposed weights: [N=128 rows][K cols]
__device__ __nv_bfloat16 g_bh_enc [128 * 768];
__device__ __nv_bfloat16 g_bl_enc [128 * 768];
__device__ __nv_bfloat16 g_bh_proj[128 * 256];
__device__ __nv_bfloat16 g_bl_proj[128 * 256];
__device__ __nv_bfloat16 g_bh_w0  [128 * 128];
__device__ __nv_bfloat16 g_bl_w0  [128 * 128];
__device__ __nv_bfloat16 g_bh_w1  [128 * 128];
__device__ __nv_bfloat16 g_bl_w1  [128 * 128];
__device__ __nv_bfloat16 g_bh_w2  [128 * 128];
__device__ __nv_bfloat16 g_bl_w2  [128 * 128];

// ================= helpers =================
__device__ __forceinline__ uint32_t smem_u32(const void* p) {
    uint32_t a;
    asm("{ .reg .u64 t; cvta.to.shared.u64 t, %1; cvt.u32.u64 %0, t; }" : "=r"(a) : "l"(p));
    return a;
}
__device__ __forceinline__ uint32_t sw128(uint32_t o) { return o ^ ((o >> 3) & 0x70); }

__device__ __forceinline__ void ldsm_x4(uint32_t* r, uint32_t addr) {
    asm volatile("ldmatrix.sync.aligned.m8n8.x4.shared.b16 {%0,%1,%2,%3}, [%4];"
        : "=r"(r[0]), "=r"(r[1]), "=r"(r[2]), "=r"(r[3]) : "r"(addr));
}
__device__ __forceinline__ void mma16816(float* c, const uint32_t* a, const uint32_t* b) {
    asm volatile(
        "mma.sync.aligned.m16n8k16.row.col.f32.bf16.bf16.f32 "
        "{%0,%1,%2,%3}, {%4,%5,%6,%7}, {%8,%9}, {%0,%1,%2,%3};"
        : "+f"(c[0]), "+f"(c[1]), "+f"(c[2]), "+f"(c[3])
        : "r"(a[0]), "r"(a[1]), "r"(a[2]), "r"(a[3]), "r"(b[0]), "r"(b[1]));
}

__device__ __forceinline__ uint32_t packbf2(float a, float b, float* ra, float* rb) {
    __nv_bfloat16 ha = __float2bfloat16_rn(a), hb = __float2bfloat16_rn(b);
    if (ra) { *ra = a - __bfloat162float(ha); *rb = b - __bfloat162float(hb); }
    return (uint32_t)__bfloat16_as_ushort(ha) | ((uint32_t)__bfloat16_as_ushort(hb) << 16);
}

// ================= graph prep: CSR build =================
__global__ void k_zero() {
    int i = blockIdx.x * blockDim.x + threadIdx.x;
    if (i < NN) { g_degi[i] = 0; g_cursor[i] = 0; }
}
__global__ void k_degree(const int* __restrict__ dst) {
    int e = blockIdx.x * blockDim.x + threadIdx.x;
    if (e < EE) atomicAdd(&g_degi[dst[e]], 1);
}
__global__ void k_dinv() {
    int i = blockIdx.x * blockDim.x + threadIdx.x;
    if (i < NN) g_dinv[i] = rsqrtf((float)(g_degi[i] + 1));  // +1 self-loop
}

// block-wise exclusive scan of g_degi -> g_rowptr (partial), block totals -> g_bsum
#define SCAN_T 256
#define SCAN_NB ((NN + SCAN_T * 4 - 1) / (SCAN_T * 4))   // 98
__global__ void __launch_bounds__(SCAN_T) k_scan1() {
    __shared__ int s[SCAN_T];
    int t = threadIdx.x;
    int base = blockIdx.x * SCAN_T * 4 + t * 4;
    int v[4];
    #pragma unroll
    for (int j = 0; j < 4; j++) v[j] = (base + j < NN) ? g_degi[base + j] : 0;
    int tsum = v[0] + v[1] + v[2] + v[3];
    s[t] = tsum; __syncthreads();
    #pragma unroll
    for (int off = 1; off < SCAN_T; off <<= 1) {
        int x = (t >= off) ? s[t - off] : 0;
        __syncthreads();
        s[t] += x;
        __syncthreads();
    }
    int run = s[t] - tsum;   // exclusive
    #pragma unroll
    for (int j = 0; j < 4; j++) {
        if (base + j < NN) g_rowptr[base + j] = run;
        run += v[j];
    }
    if (t == SCAN_T - 1) g_bsum[blockIdx.x] = s[SCAN_T - 1];
}
__global__ void __launch_bounds__(128) k_scan2() {
    __shared__ int s[128];
    int t = threadIdx.x;
    int v = (t < SCAN_NB) ? g_bsum[t] : 0;
    s[t] = v; __syncthreads();
    #pragma unroll
    for (int off = 1; off < 128; off <<= 1) {
        int x = (t >= off) ? s[t - off] : 0;
        __syncthreads();
        s[t] += x;
        __syncthreads();
    }
    if (t < SCAN_NB) g_bsumx[t] = s[t] - v;  // exclusive block offsets
}
__global__ void k_scan3() {
    int i = blockIdx.x * blockDim.x + threadIdx.x;
    if (i < NN) g_rowptr[i] += g_bsumx[i / (SCAN_T * 4)];
    if (i == 0) g_rowptr[NN] = EE;
}
__global__ void k_scatter(const int* __restrict__ src, const int* __restrict__ dst) {
    int e = blockIdx.x * blockDim.x + threadIdx.x;
    if (e >= EE) return;
    int d = dst[e];
    int s = src[e];
    int pos = g_rowptr[d] + atomicAdd(&g_cursor[d], 1);
    float nm = g_dinv[s] * g_dinv[d];
    g_epack[pos] = make_int2(s, __float_as_int(nm));
}

// ================= weight split: W[K][128] -> Bh/Bl [128][K] bf16 =================
__global__ void k_split(const float* __restrict__ W, int K,
                        __nv_bfloat16* __restrict__ Bh, __nv_bfloat16* __restrict__ Bl) {
    int idx = blockIdx.x * blockDim.x + threadIdx.x;
    if (idx >= K * 128) return;
    int k = idx >> 7;
    int n = idx & 127;
    float w = W[idx];
    __nv_bfloat16 h = __float2bfloat16_rn(w);
    float r = w - __bfloat162float(h);
    Bh[n * K + k] = h;
    Bl[n * K + k] = __float2bfloat16_rn(r);
}

// ================= mma.sync split-bf16 GEMM: C[M,128] = A[M,K] @ W[K,128] =================
#define TILE_B 16384
#define GEMM_DYN (4 * TILE_B + 1024)

__global__ void __launch_bounds__(256)
k_gemm_mma(const float* __restrict__ A, int K,
           const __nv_bfloat16* __restrict__ Bh, const __nv_bfloat16* __restrict__ Bl,
           const float* __restrict__ bias, int relu,
           float* __restrict__ C)
{
    extern __shared__ char dyn[];
    const int tid = threadIdx.x;
    const int rowBase = blockIdx.x * 128;

    uint32_t dynb = smem_u32(dyn);
    char* sm = dyn + (((dynb + 1023u) & ~1023u) - dynb);
    char* sAh = sm;
    char* sAl = sm + TILE_B;
    char* sBh = sm + 2 * TILE_B;
    char* sBl = sm + 3 * TILE_B;
    const uint32_t uAh = smem_u32(sAh), uAl = smem_u32(sAl);
    const uint32_t uBh = smem_u32(sBh), uBl = smem_u32(sBl);

    const int lane = tid & 31;
    const int warp = tid >> 5;
    const int mBase = (warp & 3) * 32;
    const int nBase = (warp >> 2) * 64;

    const int aRowL = (lane & 7) + ((lane & 8) ? 8 : 0);
    const int aKbL  = (lane & 16) ? 16 : 0;
    const int bRowL = (lane & 7) + ((lane & 16) ? 8 : 0);
    const int bKbL  = (lane & 8) ? 16 : 0;

    float acc[2][8][4];
    #pragma unroll
    for (int mt = 0; mt < 2; mt++)
        #pragma unroll
        for (int nt = 0; nt < 8; nt++)
            #pragma unroll
            for (int j = 0; j < 4; j++) acc[mt][nt][j] = 0.0f;

    const int nChunks = K >> 6;

    for (int c = 0; c < nChunks; c++) {
        const int k0 = c * 64;

        #pragma unroll
        for (int i = 0; i < 8; i++) {
            int fidx = i * 256 + tid;
            int r    = fidx >> 4;
            int kq   = fidx & 15;
            int gr   = rowBase + r;
            float4 f = make_float4(0.f, 0.f, 0.f, 0.f);
            if (gr < NN) f = *(const float4*)&A[(size_t)gr * K + k0 + kq * 4];
            float r0, r1, r2, r3;
            uint32_t h0 = packbf2(f.x, f.y, &r0, &r1);
            uint32_t h1 = packbf2(f.z, f.w, &r2, &r3);
            uint32_t l0 = packbf2(r0, r1, nullptr, nullptr);
            uint32_t l1 = packbf2(r2, r3, nullptr, nullptr);
            uint32_t off = sw128((uint32_t)(r * 128 + kq * 8));
            *(uint2*)(sAh + off) = make_uint2(h0, h1);
            *(uint2*)(sAl + off) = make_uint2(l0, l1);
        }

        #pragma unroll
        for (int i = 0; i < 4; i++) {
            int uidx = i * 256 + tid;
            int n    = uidx >> 3;
            int kq   = uidx & 7;
            uint4 vh = *(const uint4*)(Bh + (size_t)n * K + k0 + kq * 8);
            uint4 vl = *(const uint4*)(Bl + (size_t)n * K + k0 + kq * 8);
            uint32_t off = sw128((uint32_t)(n * 128 + kq * 16));
            *(uint4*)(sBh + off) = vh;
            *(uint4*)(sBl + off) = vl;
        }
        __syncthreads();

        #pragma unroll
        for (int ks = 0; ks < 4; ks++) {
            const int kb = ks * 32;
            uint32_t af[2][4], bf[4][4];

            #pragma unroll
            for (int p = 0; p < 4; p++)
                ldsm_x4(bf[p], uBh + sw128((uint32_t)((nBase + p * 16 + bRowL) * 128 + kb + bKbL)));
            #pragma unroll
            for (int mt = 0; mt < 2; mt++)
                ldsm_x4(af[mt], uAh + sw128((uint32_t)((mBase + mt * 16 + aRowL) * 128 + kb + aKbL)));
            #pragma unroll
            for (int mt = 0; mt < 2; mt++)
                #pragma unroll
                for (int p = 0; p < 4; p++) {
                    mma16816(acc[mt][2 * p],     af[mt], &bf[p][0]);
                    mma16816(acc[mt][2 * p + 1], af[mt], &bf[p][2]);
                }

            #pragma unroll
            for (int mt = 0; mt < 2; mt++)
                ldsm_x4(af[mt], uAl + sw128((uint32_t)((mBase + mt * 16 + aRowL) * 128 + kb + aKbL)));
            #pragma unroll
            for (int mt = 0; mt < 2; mt++)
                #pragma unroll
                for (int p = 0; p < 4; p++) {
                    mma16816(acc[mt][2 * p],     af[mt], &bf[p][0]);
                    mma16816(acc[mt][2 * p + 1], af[mt], &bf[p][2]);
                }

            #pragma unroll
            for (int mt = 0; mt < 2; mt++)
                ldsm_x4(af[mt], uAh + sw128((uint32_t)((mBase + mt * 16 + aRowL) * 128 + kb + aKbL)));
            #pragma unroll
            for (int p = 0; p < 4; p++)
                ldsm_x4(bf[p], uBl + sw128((uint32_t)((nBase + p * 16 + bRowL) * 128 + kb + bKbL)));
            #pragma unroll
            for (int mt = 0; mt < 2; mt++)
                #pragma unroll
                for (int p = 0; p < 4; p++) {
                    mma16816(acc[mt][2 * p],     af[mt], &bf[p][0]);
                    mma16816(acc[mt][2 * p + 1], af[mt], &bf[p][2]);
                }
        }
        __syncthreads();
    }

    const int rL = lane >> 2;
    const int cL = (lane & 3) * 2;
    #pragma unroll
    for (int mt = 0; mt < 2; mt++) {
        #pragma unroll
        for (int half = 0; half < 2; half++) {
            int row = rowBase + mBase + mt * 16 + rL + half * 8;
            if (row >= NN) continue;
            #pragma unroll
            for (int nt = 0; nt < 8; nt++) {
                int col = nBase + nt * 8 + cL;
                float v0 = acc[mt][nt][half * 2];
                float v1 = acc[mt][nt][half * 2 + 1];
                if (bias) { v0 += bias[col]; v1 += bias[col + 1]; }
                if (relu) { v0 = fmaxf(v0, 0.f); v1 = fmaxf(v1, 0.f); }
                *(float2*)&C[(size_t)row * 128 + col] = make_float2(v0, v1);
            }
        }
    }
}

// ================= LayerNorm+ReLU on g_tmp -> build [emb|feat] concat =================
__global__ void k_ln_concat(const float* __restrict__ emb,
                            const float* __restrict__ lng,
                            const float* __restrict__ lnb)
{
    int w    = (blockIdx.x * blockDim.x + threadIdx.x) >> 5;
    int lane = threadIdx.x & 31;
    if (w >= NN) return;

    float4 v = *(const float4*)&g_tmp[(size_t)w * 128 + lane * 4];
    float s  = v.x + v.y + v.z + v.w;
    float sq = v.x * v.x + v.y * v.y + v.z * v.z + v.w * v.w;
    #pragma unroll
    for (int o = 16; o > 0; o >>= 1) {
        s  += __shfl_xor_sync(0xffffffffu, s,  o);
        sq += __shfl_xor_sync(0xffffffffu, sq, o);
    }
    float mu  = s * (1.0f / 128.0f);
    float var = sq * (1.0f / 128.0f) - mu * mu;
    float r   = rsqrtf(var + EPSV);

    float4 gg = *(const float4*)&lng[lane * 4];
    float4 bb = *(const float4*)&lnb[lane * 4];
    float4 o;
    o.x = fmaxf((v.x - mu) * r * gg.x + bb.x, 0.0f);
    o.y = fmaxf((v.y - mu) * r * gg.y + bb.y, 0.0f);
    o.z = fmaxf((v.z - mu) * r * gg.z + bb.z, 0.0f);
    o.w = fmaxf((v.w - mu) * r * gg.w + bb.w, 0.0f);

    *(float4*)&g_xcat[(size_t)w * 256 + 128 + lane * 4] = o;
    *(float4*)&g_xcat[(size_t)w * 256 + lane * 4] =
        *(const float4*)&emb[(size_t)w * 128 + lane * 4];
}

// ================= fused CSR SPMM: out[d] = act(dinv^2*xw[d] + sum norm*xw[src] + b) =====
__global__ void __launch_bounds__(256)
k_spmm_csr(const float* __restrict__ bias, float* __restrict__ out, int relu)
{
    int w = (blockIdx.x * blockDim.x + threadIdx.x) >> 5;
    if (w >= NN) return;
    int lane = threadIdx.x & 31;
    int c = lane * 4;

    float di = g_dinv[w];
    float wt = di * di;
    float4 acc = *(const float4*)&g_xw[(size_t)w * 128 + c];
    acc.x *= wt; acc.y *= wt; acc.z *= wt; acc.w *= wt;

    int start = g_rowptr[w];
    int end   = g_rowptr[w + 1];
    for (int base = start; base < end; base += 32) {
        int2 p = make_int2(0, 0);
        if (base + lane < end) p = g_epack[base + lane];
        int n = min(32, end - base);
        for (int j = 0; j < n; j++) {
            int   s  = __shfl_sync(0xffffffffu, p.x, j);
            float nm = __int_as_float(__shfl_sync(0xffffffffu, p.y, j));
            float4 v = *(const float4*)&g_xw[(size_t)s * 128 + c];
            acc.x = fmaf(nm, v.x, acc.x);
            acc.y = fmaf(nm, v.y, acc.y);
            acc.z = fmaf(nm, v.z, acc.z);
            acc.w = fmaf(nm, v.w, acc.w);
        }
    }

    float4 bb = *(const float4*)&bias[c];
    acc.x += bb.x; acc.y += bb.y; acc.z += bb.z; acc.w += bb.w;
    if (relu) {
        acc.x = fmaxf(acc.x, 0.f); acc.y = fmaxf(acc.y, 0.f);
        acc.z = fmaxf(acc.z, 0.f); acc.w = fmaxf(acc.w, 0.f);
    }
    *(float4*)&out[(size_t)w * 128 + c] = acc;
}

// ================= launch =================
extern "C" void kernel_launch(void* const* d_in, const int* in_sizes, int n_in,
                              void* d_out, int out_size)
{
    (void)in_sizes; (void)n_in; (void)out_size;
    const int*   ei    = (const int*)  d_in[0];
    const float* ext   = (const float*)d_in[1];
    const float* emb   = (const float*)d_in[2];
    const float* encW  = (const float*)d_in[3];
    const float* encB  = (const float*)d_in[4];
    const float* lng   = (const float*)d_in[5];
    const float* lnb   = (const float*)d_in[6];
    const float* projW = (const float*)d_in[7];
    const float* projB = (const float*)d_in[8];
    const float* W0    = (const float*)d_in[9];
    const float* b0    = (const float*)d_in[10];
    const float* W1    = (const float*)d_in[11];
    const float* b1    = (const float*)d_in[12];
    const float* W2    = (const float*)d_in[13];
    const float* b2    = (const float*)d_in[14];
    float* out = (float*)d_out;

    const int* src = ei;
    const int* dst = ei + EE;

    float *p_tmp, *p_xcat, *p_x, *p_xw;
    cudaGetSymbolAddress((void**)&p_tmp,  g_tmp);
    cudaGetSymbolAddress((void**)&p_xcat, g_xcat);
    cudaGetSymbolAddress((void**)&p_x,    g_x);
    cudaGetSymbolAddress((void**)&p_xw,   g_xw);

    __nv_bfloat16 *bh_enc, *bl_enc, *bh_proj, *bl_proj, *bh_w0, *bl_w0, *bh_w1, *bl_w1, *bh_w2, *bl_w2;
    cudaGetSymbolAddress((void**)&bh_enc,  g_bh_enc);
    cudaGetSymbolAddress((void**)&bl_enc,  g_bl_enc);
    cudaGetSymbolAddress((void**)&bh_proj, g_bh_proj);
    cudaGetSymbolAddress((void**)&bl_proj, g_bl_proj);
    cudaGetSymbolAddress((void**)&bh_w0,   g_bh_w0);
    cudaGetSymbolAddress((void**)&bl_w0,   g_bl_w0);
    cudaGetSymbolAddress((void**)&bh_w1,   g_bh_w1);
    cudaGetSymbolAddress((void**)&bl_w1,   g_bl_w1);
    cudaGetSymbolAddress((void**)&bh_w2,   g_bh_w2);
    cudaGetSymbolAddress((void**)&bl_w2,   g_bl_w2);

    cudaFuncSetAttribute(k_gemm_mma, cudaFuncAttributeMaxDynamicSharedMemorySize, GEMM_DYN);

    const int TB = 256;
    const int gN     = (NN + TB - 1) / TB;
    const int gE     = (EE + TB - 1) / TB;
    const int gRow   = (NN * 32 + TB - 1) / TB;   // warp-per-node kernels
    const int gGemm  = (NN + 127) / 128;

    // ---- CSR build ----
    k_zero<<<gN, TB>>>();
    k_degree<<<gE, TB>>>(dst);
    k_dinv<<<gN, TB>>>();
    k_scan1<<<SCAN_NB, SCAN_T>>>();
    k_scan2<<<1, 128>>>();
    k_scan3<<<gN, TB>>>();
    k_scatter<<<gE, TB>>>(src, dst);

    // ---- weight splits ----
    k_split<<<(768 * 128 + TB - 1) / TB, TB>>>(encW,  768, bh_enc,  bl_enc);
    k_split<<<(256 * 128 + TB - 1) / TB, TB>>>(projW, 256, bh_proj, bl_proj);
    k_split<<<(128 * 128 + TB - 1) / TB, TB>>>(W0,    128, bh_w0,   bl_w0);
    k_split<<<(128 * 128 + TB - 1) / TB, TB>>>(W1,    128, bh_w1,   bl_w1);
    k_split<<<(128 * 128 + TB - 1) / TB, TB>>>(W2,    128, bh_w2,   bl_w2);

    // ---- encoder + concat + projection ----
    k_gemm_mma<<<gGemm, TB, GEMM_DYN>>>(ext, 768, bh_enc, bl_enc, encB, 0, p_tmp);
    k_ln_concat<<<gRow, TB>>>(emb, lng, lnb);
    k_gemm_mma<<<gGemm, TB, GEMM_DYN>>>(p_xcat, 256, bh_proj, bl_proj, projB, 0, p_x);

    // ---- GCN layers (SPMM fused with self-loop/bias/relu) ----
    k_gemm_mma<<<gGemm, TB, GEMM_DYN>>>(p_x, 128, bh_w0, bl_w0, nullptr, 0, p_xw);
    k_spmm_csr<<<gRow, TB>>>(b0, p_x, 1);

    k_gemm_mma<<<gGemm, TB, GEMM_DYN>>>(p_x, 128, bh_w1, bl_w1, nullptr, 0, p_xw);
    k_spmm_csr<<<gRow, TB>>>(b1, p_x, 1);

    k_gemm_mma<<<gGemm, TB, GEMM_DYN>>>(p_x, 128, bh_w2, bl_w2, nullptr, 0, p_xw);
    k_spmm_csr<<<gRow, TB>>>(b2, out, 0);
}

// round 5
// speedup vs baseline: 3.1990x; 1.4546x over previous
#include <cuda_runtime.h>
#include <cuda_bf16.h>
#include <cstdint>

// Problem constants
#define NN   100000
#define HH   128
#define EE   1600000
#define EXTD 768
#define EPSV 1e-5f

// ================= device scratch (no allocations allowed) =================
__device__ float g_dinv[NN];
__device__ int   g_degi[NN];
__device__ int   g_cursor[NN];
__device__ int   g_rowptr[NN + 1];
__device__ int   g_bsum[128];
__device__ int   g_bsumx[128];
__device__ int2  g_epack[EE];          // (src, norm-bits) sorted by dst
__device__ float g_tmp [NN * HH];      // encoder out, then LN+ReLU in place
__device__ float g_x   [NN * HH];
__device__ float g_xw  [NN * HH];

// split-bf16 transposed weights: [N=128 rows][K cols]
__device__ __nv_bfloat16 g_bh_enc [128 * 768];
__device__ __nv_bfloat16 g_bl_enc [128 * 768];
__device__ __nv_bfloat16 g_bh_proj[128 * 256];
__device__ __nv_bfloat16 g_bl_proj[128 * 256];
__device__ __nv_bfloat16 g_bh_w0  [128 * 128];
__device__ __nv_bfloat16 g_bl_w0  [128 * 128];
__device__ __nv_bfloat16 g_bh_w1  [128 * 128];
__device__ __nv_bfloat16 g_bl_w1  [128 * 128];
__device__ __nv_bfloat16 g_bh_w2  [128 * 128];
__device__ __nv_bfloat16 g_bl_w2  [128 * 128];

// ================= helpers =================
__device__ __forceinline__ uint32_t smem_u32(const void* p) {
    uint32_t a;
    asm("{ .reg .u64 t; cvta.to.shared.u64 t, %1; cvt.u32.u64 %0, t; }" : "=r"(a) : "l"(p));
    return a;
}
__device__ __forceinline__ uint32_t sw128(uint32_t o) { return o ^ ((o >> 3) & 0x70); }

__device__ __forceinline__ void ldsm_x4(uint32_t* r, uint32_t addr) {
    asm volatile("ldmatrix.sync.aligned.m8n8.x4.shared.b16 {%0,%1,%2,%3}, [%4];"
        : "=r"(r[0]), "=r"(r[1]), "=r"(r[2]), "=r"(r[3]) : "r"(addr));
}
__device__ __forceinline__ void mma16816(float* c, const uint32_t* a, const uint32_t* b) {
    asm volatile(
        "mma.sync.aligned.m16n8k16.row.col.f32.bf16.bf16.f32 "
        "{%0,%1,%2,%3}, {%4,%5,%6,%7}, {%8,%9}, {%0,%1,%2,%3};"
        : "+f"(c[0]), "+f"(c[1]), "+f"(c[2]), "+f"(c[3])
        : "r"(a[0]), "r"(a[1]), "r"(a[2]), "r"(a[3]), "r"(b[0]), "r"(b[1]));
}
#define CP_ASYNC16(smem, gptr) \
    asm volatile("cp.async.cg.shared.global [%0], [%1], 16;" :: "r"(smem), "l"(gptr))
#define CP_WAIT_ALL() asm volatile("cp.async.wait_all;" ::: "memory")

__device__ __forceinline__ uint32_t packbf2(float a, float b, float* ra, float* rb) {
    __nv_bfloat16 ha = __float2bfloat16_rn(a), hb = __float2bfloat16_rn(b);
    if (ra) { *ra = a - __bfloat162float(ha); *rb = b - __bfloat162float(hb); }
    return (uint32_t)__bfloat16_as_ushort(ha) | ((uint32_t)__bfloat16_as_ushort(hb) << 16);
}

// ================= graph prep: CSR build =================
__global__ void k_zero() {
    int i = blockIdx.x * blockDim.x + threadIdx.x;
    if (i < NN) { g_degi[i] = 0; g_cursor[i] = 0; }
}
__global__ void k_degree(const int* __restrict__ dst) {
    int e = blockIdx.x * blockDim.x + threadIdx.x;
    if (e < EE) atomicAdd(&g_degi[dst[e]], 1);
}
__global__ void k_dinv() {
    int i = blockIdx.x * blockDim.x + threadIdx.x;
    if (i < NN) g_dinv[i] = rsqrtf((float)(g_degi[i] + 1));  // +1 self-loop
}

#define SCAN_T 256
#define SCAN_NB ((NN + SCAN_T * 4 - 1) / (SCAN_T * 4))   // 98
__global__ void __launch_bounds__(SCAN_T) k_scan1() {
    __shared__ int s[SCAN_T];
    int t = threadIdx.x;
    int base = blockIdx.x * SCAN_T * 4 + t * 4;
    int v[4];
    #pragma unroll
    for (int j = 0; j < 4; j++) v[j] = (base + j < NN) ? g_degi[base + j] : 0;
    int tsum = v[0] + v[1] + v[2] + v[3];
    s[t] = tsum; __syncthreads();
    #pragma unroll
    for (int off = 1; off < SCAN_T; off <<= 1) {
        int x = (t >= off) ? s[t - off] : 0;
        __syncthreads();
        s[t] += x;
        __syncthreads();
    }
    int run = s[t] - tsum;
    #pragma unroll
    for (int j = 0; j < 4; j++) {
        if (base + j < NN) g_rowptr[base + j] = run;
        run += v[j];
    }
    if (t == SCAN_T - 1) g_bsum[blockIdx.x] = s[SCAN_T - 1];
}
__global__ void __launch_bounds__(128) k_scan2() {
    __shared__ int s[128];
    int t = threadIdx.x;
    int v = (t < SCAN_NB) ? g_bsum[t] : 0;
    s[t] = v; __syncthreads();
    #pragma unroll
    for (int off = 1; off < 128; off <<= 1) {
        int x = (t >= off) ? s[t - off] : 0;
        __syncthreads();
        s[t] += x;
        __syncthreads();
    }
    if (t < SCAN_NB) g_bsumx[t] = s[t] - v;
}
__global__ void k_scan3() {
    int i = blockIdx.x * blockDim.x + threadIdx.x;
    if (i < NN) g_rowptr[i] += g_bsumx[i / (SCAN_T * 4)];
    if (i == 0) g_rowptr[NN] = EE;
}
__global__ void k_scatter(const int* __restrict__ src, const int* __restrict__ dst) {
    int e = blockIdx.x * blockDim.x + threadIdx.x;
    if (e >= EE) return;
    int d = dst[e];
    int s = src[e];
    int pos = g_rowptr[d] + atomicAdd(&g_cursor[d], 1);
    float nm = g_dinv[s] * g_dinv[d];
    g_epack[pos] = make_int2(s, __float_as_int(nm));
}

// ================= weight split: W[K][128] -> Bh/Bl [128][K] bf16 =================
__global__ void k_split(const float* __restrict__ W, int K,
                        __nv_bfloat16* __restrict__ Bh, __nv_bfloat16* __restrict__ Bl) {
    int idx = blockIdx.x * blockDim.x + threadIdx.x;
    if (idx >= K * 128) return;
    int k = idx >> 7;
    int n = idx & 127;
    float w = W[idx];
    __nv_bfloat16 h = __float2bfloat16_rn(w);
    float r = w - __bfloat162float(h);
    Bh[n * K + k] = h;
    Bl[n * K + k] = __float2bfloat16_rn(r);
}

// ============ pipelined mma.sync split-bf16 GEMM: C[M,128] = [Aa|Ab] @ W[K,128] ============
// A chunks k0 < kSplit read from Aa, else Ab (for the concat-proj GEMM).
#define TILE_B 16384
#define GEMM_DYN (4 * TILE_B + 1024)

__global__ void __launch_bounds__(256, 1)
k_gemm_mma(const float* __restrict__ Aa, int strideA,
           const float* __restrict__ Ab, int strideB, int kSplit, int K,
           const __nv_bfloat16* __restrict__ Bh, const __nv_bfloat16* __restrict__ Bl,
           const float* __restrict__ bias, int relu,
           float* __restrict__ C)
{
    extern __shared__ char dyn[];
    const int tid = threadIdx.x;
    const int rowBase = blockIdx.x * 128;

    uint32_t dynb = smem_u32(dyn);
    char* sm = dyn + (((dynb + 1023u) & ~1023u) - dynb);
    char* sAh = sm;
    char* sAl = sm + TILE_B;
    char* sBh = sm + 2 * TILE_B;
    char* sBl = sm + 3 * TILE_B;
    const uint32_t uAh = smem_u32(sAh), uAl = smem_u32(sAl);
    const uint32_t uBh = smem_u32(sBh), uBl = smem_u32(sBl);

    const int lane = tid & 31;
    const int warp = tid >> 5;
    const int mBase = (warp & 3) * 32;
    const int nBase = (warp >> 2) * 64;

    const int aRowL = (lane & 7) + ((lane & 8) ? 8 : 0);
    const int aKbL  = (lane & 16) ? 16 : 0;
    const int bRowL = (lane & 7) + ((lane & 16) ? 8 : 0);
    const int bKbL  = (lane & 8) ? 16 : 0;

    float acc[2][8][4];
    #pragma unroll
    for (int mt = 0; mt < 2; mt++)
        #pragma unroll
        for (int nt = 0; nt < 8; nt++)
            #pragma unroll
            for (int j = 0; j < 4; j++) acc[mt][nt][j] = 0.0f;

    const int nChunks = K >> 6;
    float4 aF[8];

    auto prefetchA = [&](int c) {
        int k0 = c * 64;
        const float* base; int stride; int koff;
        if (k0 < kSplit) { base = Aa; stride = strideA; koff = k0; }
        else             { base = Ab; stride = strideB; koff = k0 - kSplit; }
        #pragma unroll
        for (int i = 0; i < 8; i++) {
            int fidx = i * 256 + tid;
            int r    = fidx >> 4;
            int kq   = fidx & 15;
            int gr   = rowBase + r;
            aF[i] = make_float4(0.f, 0.f, 0.f, 0.f);
            if (gr < NN) aF[i] = *(const float4*)(base + (size_t)gr * stride + koff + kq * 4);
        }
    };

    prefetchA(0);

    for (int c = 0; c < nChunks; c++) {
        const int k0 = c * 64;

        // ---- B tiles via cp.async (no reg round-trip) ----
        #pragma unroll
        for (int i = 0; i < 4; i++) {
            int uidx = i * 256 + tid;
            int n    = uidx >> 3;
            int kq   = uidx & 7;
            uint32_t off = sw128((uint32_t)(n * 128 + kq * 16));
            CP_ASYNC16(uBh + off, (const char*)(Bh + (size_t)n * K + k0 + kq * 8));
            CP_ASYNC16(uBl + off, (const char*)(Bl + (size_t)n * K + k0 + kq * 8));
        }

        // ---- convert prefetched A regs -> hi/lo bf16 smem (overlaps B latency) ----
        #pragma unroll
        for (int i = 0; i < 8; i++) {
            int fidx = i * 256 + tid;
            int r    = fidx >> 4;
            int kq   = fidx & 15;
            float r0, r1, r2, r3;
            uint32_t h0 = packbf2(aF[i].x, aF[i].y, &r0, &r1);
            uint32_t h1 = packbf2(aF[i].z, aF[i].w, &r2, &r3);
            uint32_t l0 = packbf2(r0, r1, nullptr, nullptr);
            uint32_t l1 = packbf2(r2, r3, nullptr, nullptr);
            uint32_t off = sw128((uint32_t)(r * 128 + kq * 8));
            *(uint2*)(sAh + off) = make_uint2(h0, h1);
            *(uint2*)(sAl + off) = make_uint2(l0, l1);
        }

        CP_WAIT_ALL();
        __syncthreads();

        // ---- prefetch next A chunk (retires during compute) ----
        if (c + 1 < nChunks) prefetchA(c + 1);

        // ---- compute: 4 k16-steps; Ah*Bh + Al*Bh + Ah*Bl, 12 ldsm/step ----
        #pragma unroll
        for (int ks = 0; ks < 4; ks++) {
            const int kb = ks * 32;
            uint32_t ah[2][4], al[2][4], bq[4][4];

            #pragma unroll
            for (int mt = 0; mt < 2; mt++)
                ldsm_x4(ah[mt], uAh + sw128((uint32_t)((mBase + mt * 16 + aRowL) * 128 + kb + aKbL)));
            #pragma unroll
            for (int mt = 0; mt < 2; mt++)
                ldsm_x4(al[mt], uAl + sw128((uint32_t)((mBase + mt * 16 + aRowL) * 128 + kb + aKbL)));
            #pragma unroll
            for (int p = 0; p < 4; p++)
                ldsm_x4(bq[p], uBh + sw128((uint32_t)((nBase + p * 16 + bRowL) * 128 + kb + bKbL)));

            #pragma unroll
            for (int mt = 0; mt < 2; mt++)
                #pragma unroll
                for (int p = 0; p < 4; p++) {
                    mma16816(acc[mt][2 * p],     ah[mt], &bq[p][0]);
                    mma16816(acc[mt][2 * p + 1], ah[mt], &bq[p][2]);
                }
            #pragma unroll
            for (int mt = 0; mt < 2; mt++)
                #pragma unroll
                for (int p = 0; p < 4; p++) {
                    mma16816(acc[mt][2 * p],     al[mt], &bq[p][0]);
                    mma16816(acc[mt][2 * p + 1], al[mt], &bq[p][2]);
                }

            #pragma unroll
            for (int p = 0; p < 4; p++)
                ldsm_x4(bq[p], uBl + sw128((uint32_t)((nBase + p * 16 + bRowL) * 128 + kb + bKbL)));
            #pragma unroll
            for (int mt = 0; mt < 2; mt++)
                #pragma unroll
                for (int p = 0; p < 4; p++) {
                    mma16816(acc[mt][2 * p],     ah[mt], &bq[p][0]);
                    mma16816(acc[mt][2 * p + 1], ah[mt], &bq[p][2]);
                }
        }
        __syncthreads();
    }

    // ---- epilogue: registers -> gmem, fused bias/relu ----
    const int rL = lane >> 2;
    const int cL = (lane & 3) * 2;
    #pragma unroll
    for (int mt = 0; mt < 2; mt++) {
        #pragma unroll
        for (int half = 0; half < 2; half++) {
            int row = rowBase + mBase + mt * 16 + rL + half * 8;
            if (row >= NN) continue;
            #pragma unroll
            for (int nt = 0; nt < 8; nt++) {
                int col = nBase + nt * 8 + cL;
                float v0 = acc[mt][nt][half * 2];
                float v1 = acc[mt][nt][half * 2 + 1];
                if (bias) { v0 += bias[col]; v1 += bias[col + 1]; }
                if (relu) { v0 = fmaxf(v0, 0.f); v1 = fmaxf(v1, 0.f); }
                *(float2*)&C[(size_t)row * 128 + col] = make_float2(v0, v1);
            }
        }
    }
}

// ================= LayerNorm+ReLU on g_tmp (in place) =================
__global__ void k_ln(const float* __restrict__ lng, const float* __restrict__ lnb)
{
    int w    = (blockIdx.x * blockDim.x + threadIdx.x) >> 5;
    int lane = threadIdx.x & 31;
    if (w >= NN) return;

    float4 v = *(const float4*)&g_tmp[(size_t)w * 128 + lane * 4];
    float s  = v.x + v.y + v.z + v.w;
    float sq = v.x * v.x + v.y * v.y + v.z * v.z + v.w * v.w;
    #pragma unroll
    for (int o = 16; o > 0; o >>= 1) {
        s  += __shfl_xor_sync(0xffffffffu, s,  o);
        sq += __shfl_xor_sync(0xffffffffu, sq, o);
    }
    float mu  = s * (1.0f / 128.0f);
    float var = sq * (1.0f / 128.0f) - mu * mu;
    float r   = rsqrtf(var + EPSV);

    float4 gg = *(const float4*)&lng[lane * 4];
    float4 bb = *(const float4*)&lnb[lane * 4];
    float4 o;
    o.x = fmaxf((v.x - mu) * r * gg.x + bb.x, 0.0f);
    o.y = fmaxf((v.y - mu) * r * gg.y + bb.y, 0.0f);
    o.z = fmaxf((v.z - mu) * r * gg.z + bb.z, 0.0f);
    o.w = fmaxf((v.w - mu) * r * gg.w + bb.w, 0.0f);
    *(float4*)&g_tmp[(size_t)w * 128 + lane * 4] = o;
}

// ====== fused CSR SPMM: out[d] = act(dinv^2*xw[d] + sum norm*xw[src] + b) ======
__global__ void __launch_bounds__(256)
k_spmm_csr(const float* __restrict__ bias, float* __restrict__ out, int relu)
{
    int w = (blockIdx.x * blockDim.x + threadIdx.x) >> 5;
    if (w >= NN) return;
    int lane = threadIdx.x & 31;
    int c = lane * 4;

    float di = g_dinv[w];
    float wt = di * di;
    float4 acc = *(const float4*)&g_xw[(size_t)w * 128 + c];
    acc.x *= wt; acc.y *= wt; acc.z *= wt; acc.w *= wt;

    int start = g_rowptr[w];
    int end   = g_rowptr[w + 1];
    for (int base = start; base < end; base += 32) {
        int rem = end - base;
        int2 p = make_int2(0, 0);
        if (lane < rem) p = g_epack[base + lane];
        if (rem >= 32) {
            #pragma unroll
            for (int j = 0; j < 32; j++) {
                int   s  = __shfl_sync(0xffffffffu, p.x, j);
                float nm = __int_as_float(__shfl_sync(0xffffffffu, p.y, j));
                float4 v = *(const float4*)&g_xw[(size_t)s * 128 + c];
                acc.x = fmaf(nm, v.x, acc.x);
                acc.y = fmaf(nm, v.y, acc.y);
                acc.z = fmaf(nm, v.z, acc.z);
                acc.w = fmaf(nm, v.w, acc.w);
            }
        } else {
            for (int j = 0; j < rem; j++) {
                int   s  = __shfl_sync(0xffffffffu, p.x, j);
                float nm = __int_as_float(__shfl_sync(0xffffffffu, p.y, j));
                float4 v = *(const float4*)&g_xw[(size_t)s * 128 + c];
                acc.x = fmaf(nm, v.x, acc.x);
                acc.y = fmaf(nm, v.y, acc.y);
                acc.z = fmaf(nm, v.z, acc.z);
                acc.w = fmaf(nm, v.w, acc.w);
            }
        }
    }

    float4 bb = *(const float4*)&bias[c];
    acc.x += bb.x; acc.y += bb.y; acc.z += bb.z; acc.w += bb.w;
    if (relu) {
        acc.x = fmaxf(acc.x, 0.f); acc.y = fmaxf(acc.y, 0.f);
        acc.z = fmaxf(acc.z, 0.f); acc.w = fmaxf(acc.w, 0.f);
    }
    *(float4*)&out[(size_t)w * 128 + c] = acc;
}

// ================= launch =================
extern "C" void kernel_launch(void* const* d_in, const int* in_sizes, int n_in,
                              void* d_out, int out_size)
{
    (void)in_sizes; (void)n_in; (void)out_size;
    const int*   ei    = (const int*)  d_in[0];
    const float* ext   = (const float*)d_in[1];
    const float* emb   = (const float*)d_in[2];
    const float* encW  = (const float*)d_in[3];
    const float* encB  = (const float*)d_in[4];
    const float* lng   = (const float*)d_in[5];
    const float* lnb   = (const float*)d_in[6];
    const float* projW = (const float*)d_in[7];
    const float* projB = (const float*)d_in[8];
    const float* W0    = (const float*)d_in[9];
    const float* b0    = (const float*)d_in[10];
    const float* W1    = (const float*)d_in[11];
    const float* b1    = (const float*)d_in[12];
    const float* W2    = (const float*)d_in[13];
    const float* b2    = (const float*)d_in[14];
    float* out = (float*)d_out;

    const int* src = ei;
    const int* dst = ei + EE;

    float *p_tmp, *p_x, *p_xw;
    cudaGetSymbolAddress((void**)&p_tmp, g_tmp);
    cudaGetSymbolAddress((void**)&p_x,   g_x);
    cudaGetSymbolAddress((void**)&p_xw,  g_xw);

    __nv_bfloat16 *bh_enc, *bl_enc, *bh_proj, *bl_proj, *bh_w0, *bl_w0, *bh_w1, *bl_w1, *bh_w2, *bl_w2;
    cudaGetSymbolAddress((void**)&bh_enc,  g_bh_enc);
    cudaGetSymbolAddress((void**)&bl_enc,  g_bl_enc);
    cudaGetSymbolAddress((void**)&bh_proj, g_bh_proj);
    cudaGetSymbolAddress((void**)&bl_proj, g_bl_proj);
    cudaGetSymbolAddress((void**)&bh_w0,   g_bh_w0);
    cudaGetSymbolAddress((void**)&bl_w0,   g_bl_w0);
    cudaGetSymbolAddress((void**)&bh_w1,   g_bh_w1);
    cudaGetSymbolAddress((void**)&bl_w1,   g_bl_w1);
    cudaGetSymbolAddress((void**)&bh_w2,   g_bh_w2);
    cudaGetSymbolAddress((void**)&bl_w2,   g_bl_w2);

    cudaFuncSetAttribute(k_gemm_mma, cudaFuncAttributeMaxDynamicSharedMemorySize, GEMM_DYN);

    const int TB = 256;
    const int gN     = (NN + TB - 1) / TB;
    const int gE     = (EE + TB - 1) / TB;
    const int gRow   = (NN * 32 + TB - 1) / TB;
    const int gGemm  = (NN + 127) / 128;

    // ---- CSR build ----
    k_zero<<<gN, TB>>>();
    k_degree<<<gE, TB>>>(dst);
    k_dinv<<<gN, TB>>>();
    k_scan1<<<SCAN_NB, SCAN_T>>>();
    k_scan2<<<1, 128>>>();
    k_scan3<<<gN, TB>>>();
    k_scatter<<<gE, TB>>>(src, dst);

    // ---- weight splits ----
    k_split<<<(768 * 128 + TB - 1) / TB, TB>>>(encW,  768, bh_enc,  bl_enc);
    k_split<<<(256 * 128 + TB - 1) / TB, TB>>>(projW, 256, bh_proj, bl_proj);
    k_split<<<(128 * 128 + TB - 1) / TB, TB>>>(W0,    128, bh_w0,   bl_w0);
    k_split<<<(128 * 128 + TB - 1) / TB, TB>>>(W1,    128, bh_w1,   bl_w1);
    k_split<<<(128 * 128 + TB - 1) / TB, TB>>>(W2,    128, bh_w2,   bl_w2);

    // ---- encoder GEMM -> LN(in place) ----
    k_gemm_mma<<<gGemm, TB, GEMM_DYN>>>(ext, EXTD, ext, EXTD, EXTD, EXTD,
                                        bh_enc, bl_enc, encB, 0, p_tmp);
    k_ln<<<gRow, TB>>>(lng, lnb);

    // ---- projection: A = [emb | ln(feat)] read directly by k-range ----
    k_gemm_mma<<<gGemm, TB, GEMM_DYN>>>(emb, HH, p_tmp, HH, HH, 2 * HH,
                                        bh_proj, bl_proj, projB, 0, p_x);

    // ---- GCN layers ----
    k_gemm_mma<<<gGemm, TB, GEMM_DYN>>>(p_x, HH, p_x, HH, HH, HH,
                                        bh_w0, bl_w0, nullptr, 0, p_xw);
    k_spmm_csr<<<gRow, TB>>>(b0, p_x, 1);

    k_gemm_mma<<<gGemm, TB, GEMM_DYN>>>(p_x, HH, p_x, HH, HH, HH,
                                        bh_w1, bl_w1, nullptr, 0, p_xw);
    k_spmm_csr<<<gRow, TB>>>(b1, p_x, 1);

    k_gemm_mma<<<gGemm, TB, GEMM_DYN>>>(p_x, HH, p_x, HH, HH, HH,
                                        bh_w2, bl_w2, nullptr, 0, p_xw);
    k_spmm_csr<<<gRow, TB>>>(b2, out, 0);
}

// round 6
// speedup vs baseline: 3.3150x; 1.0363x over previous
#include <cuda_runtime.h>
#include <cuda_bf16.h>
#include <cstdint>

// Problem constants
#define NN   100000
#define HH   128
#define EE   1600000
#define EXTD 768
#define EPSV 1e-5f

// ================= device scratch (no allocations allowed) =================
__device__ float g_dinv[NN];
__device__ int   g_degi[NN];
__device__ int   g_cursor[NN];
__device__ int   g_rowptr[NN + 1];
__device__ int   g_bsum[128];
__device__ int   g_bsumx[128];
__device__ int2  g_epack[EE];          // (src, norm-bits) sorted by dst
__device__ float g_tmp [NN * HH];      // encoder LN+ReLU output
__device__ float g_x   [NN * HH];
__device__ float g_xw  [NN * HH];

// split-bf16 transposed weights: [N=128 rows][K cols]
__device__ __nv_bfloat16 g_bh_enc [128 * 768];
__device__ __nv_bfloat16 g_bl_enc [128 * 768];
__device__ __nv_bfloat16 g_bh_proj[128 * 256];
__device__ __nv_bfloat16 g_bl_proj[128 * 256];
__device__ __nv_bfloat16 g_bh_w0  [128 * 128];
__device__ __nv_bfloat16 g_bl_w0  [128 * 128];
__device__ __nv_bfloat16 g_bh_w1  [128 * 128];
__device__ __nv_bfloat16 g_bl_w1  [128 * 128];
__device__ __nv_bfloat16 g_bh_w2  [128 * 128];
__device__ __nv_bfloat16 g_bl_w2  [128 * 128];

// ================= helpers =================
__device__ __forceinline__ uint32_t smem_u32(const void* p) {
    uint32_t a;
    asm("{ .reg .u64 t; cvta.to.shared.u64 t, %1; cvt.u32.u64 %0, t; }" : "=r"(a) : "l"(p));
    return a;
}
__device__ __forceinline__ uint32_t sw128(uint32_t o) { return o ^ ((o >> 3) & 0x70); }

__device__ __forceinline__ void ldsm_x4(uint32_t* r, uint32_t addr) {
    asm volatile("ldmatrix.sync.aligned.m8n8.x4.shared.b16 {%0,%1,%2,%3}, [%4];"
        : "=r"(r[0]), "=r"(r[1]), "=r"(r[2]), "=r"(r[3]) : "r"(addr));
}
__device__ __forceinline__ void mma16816(float* c, const uint32_t* a, const uint32_t* b) {
    asm volatile(
        "mma.sync.aligned.m16n8k16.row.col.f32.bf16.bf16.f32 "
        "{%0,%1,%2,%3}, {%4,%5,%6,%7}, {%8,%9}, {%0,%1,%2,%3};"
        : "+f"(c[0]), "+f"(c[1]), "+f"(c[2]), "+f"(c[3])
        : "r"(a[0]), "r"(a[1]), "r"(a[2]), "r"(a[3]), "r"(b[0]), "r"(b[1]));
}
#define CP_ASYNC16(smem, gptr) \
    asm volatile("cp.async.cg.shared.global [%0], [%1], 16;" :: "r"(smem), "l"(gptr))

__device__ __forceinline__ uint32_t packbf2(float a, float b, float* ra, float* rb) {
    __nv_bfloat16 ha = __float2bfloat16_rn(a), hb = __float2bfloat16_rn(b);
    if (ra) { *ra = a - __bfloat162float(ha); *rb = b - __bfloat162float(hb); }
    return (uint32_t)__bfloat16_as_ushort(ha) | ((uint32_t)__bfloat16_as_ushort(hb) << 16);
}

// ================= graph prep: CSR build =================
__global__ void k_zero() {
    int i = blockIdx.x * blockDim.x + threadIdx.x;
    if (i < NN) { g_degi[i] = 0; g_cursor[i] = 0; }
}
__global__ void k_degree(const int* __restrict__ dst) {
    int e = blockIdx.x * blockDim.x + threadIdx.x;
    if (e < EE) atomicAdd(&g_degi[dst[e]], 1);
}

#define SCAN_T 256
#define SCAN_NB ((NN + SCAN_T * 4 - 1) / (SCAN_T * 4))   // 98
__global__ void __launch_bounds__(SCAN_T) k_scan1() {
    __shared__ int s[SCAN_T];
    int t = threadIdx.x;
    int base = blockIdx.x * SCAN_T * 4 + t * 4;
    int v[4];
    #pragma unroll
    for (int j = 0; j < 4; j++) {
        v[j] = (base + j < NN) ? g_degi[base + j] : 0;
        if (base + j < NN) g_dinv[base + j] = rsqrtf((float)(v[j] + 1));  // +1 self-loop
    }
    int tsum = v[0] + v[1] + v[2] + v[3];
    s[t] = tsum; __syncthreads();
    #pragma unroll
    for (int off = 1; off < SCAN_T; off <<= 1) {
        int x = (t >= off) ? s[t - off] : 0;
        __syncthreads();
        s[t] += x;
        __syncthreads();
    }
    int run = s[t] - tsum;
    #pragma unroll
    for (int j = 0; j < 4; j++) {
        if (base + j < NN) g_rowptr[base + j] = run;
        run += v[j];
    }
    if (t == SCAN_T - 1) g_bsum[blockIdx.x] = s[SCAN_T - 1];
}
__global__ void __launch_bounds__(128) k_scan2() {
    __shared__ int s[128];
    int t = threadIdx.x;
    int v = (t < SCAN_NB) ? g_bsum[t] : 0;
    s[t] = v; __syncthreads();
    #pragma unroll
    for (int off = 1; off < 128; off <<= 1) {
        int x = (t >= off) ? s[t - off] : 0;
        __syncthreads();
        s[t] += x;
        __syncthreads();
    }
    if (t < SCAN_NB) g_bsumx[t] = s[t] - v;
}
__global__ void k_scan3() {
    int i = blockIdx.x * blockDim.x + threadIdx.x;
    if (i < NN) g_rowptr[i] += g_bsumx[i / (SCAN_T * 4)];
    if (i == 0) g_rowptr[NN] = EE;
}
__global__ void k_scatter(const int* __restrict__ src, const int* __restrict__ dst) {
    int e = blockIdx.x * blockDim.x + threadIdx.x;
    if (e >= EE) return;
    int d = dst[e];
    int s = src[e];
    int pos = g_rowptr[d] + atomicAdd(&g_cursor[d], 1);
    float nm = g_dinv[s] * g_dinv[d];
    g_epack[pos] = make_int2(s, __float_as_int(nm));
}

// ================= weight split: W[K][128] -> Bh/Bl [128][K] bf16 =================
__global__ void k_split(const float* __restrict__ W, int K,
                        __nv_bfloat16* __restrict__ Bh, __nv_bfloat16* __restrict__ Bl) {
    int idx = blockIdx.x * blockDim.x + threadIdx.x;
    if (idx >= K * 128) return;
    int k = idx >> 7;
    int n = idx & 127;
    float w = W[idx];
    __nv_bfloat16 h = __float2bfloat16_rn(w);
    float r = w - __bfloat162float(h);
    Bh[n * K + k] = h;
    Bl[n * K + k] = __float2bfloat16_rn(r);
}

// ============ pipelined mma.sync split-bf16 GEMM: C[M,128] = [Aa|Ab] @ W[K,128] ============
// B double-buffered via cp.async groups. Optional fused LayerNorm+ReLU epilogue.
#define TILE_B 16384
#define GEMM_DYN (6 * TILE_B + 1024)

__global__ void __launch_bounds__(256, 1)
k_gemm_mma(const float* __restrict__ Aa, int strideA,
           const float* __restrict__ Ab, int strideB, int kSplit, int K,
           const __nv_bfloat16* __restrict__ Bh, const __nv_bfloat16* __restrict__ Bl,
           const float* __restrict__ bias, int relu,
           const float* __restrict__ lnG, const float* __restrict__ lnB,
           float* __restrict__ C)
{
    extern __shared__ char dyn[];
    const int tid = threadIdx.x;
    const int rowBase = blockIdx.x * 128;

    uint32_t dynb = smem_u32(dyn);
    char* sm = dyn + (((dynb + 1023u) & ~1023u) - dynb);
    char* sAh = sm;
    char* sAl = sm + TILE_B;
    const uint32_t uAh = smem_u32(sAh), uAl = smem_u32(sAl);
    const uint32_t uB0 = smem_u32(sm + 2 * TILE_B);   // buf0: h at +0, l at +TILE_B

    const int lane = tid & 31;
    const int warp = tid >> 5;
    const int mBase = (warp & 3) * 32;
    const int nBase = (warp >> 2) * 64;

    const int aRowL = (lane & 7) + ((lane & 8) ? 8 : 0);
    const int aKbL  = (lane & 16) ? 16 : 0;
    const int bRowL = (lane & 7) + ((lane & 16) ? 8 : 0);
    const int bKbL  = (lane & 8) ? 16 : 0;

    float acc[2][8][4];
    #pragma unroll
    for (int mt = 0; mt < 2; mt++)
        #pragma unroll
        for (int nt = 0; nt < 8; nt++)
            #pragma unroll
            for (int j = 0; j < 4; j++) acc[mt][nt][j] = 0.0f;

    const int nChunks = K >> 6;
    float4 aF[8];

    auto prefetchA = [&](int c) {
        int k0 = c * 64;
        const float* base; int stride; int koff;
        if (k0 < kSplit) { base = Aa; stride = strideA; koff = k0; }
        else             { base = Ab; stride = strideB; koff = k0 - kSplit; }
        #pragma unroll
        for (int i = 0; i < 8; i++) {
            int fidx = i * 256 + tid;
            int r    = fidx >> 4;
            int kq   = fidx & 15;
            int gr   = rowBase + r;
            aF[i] = make_float4(0.f, 0.f, 0.f, 0.f);
            if (gr < NN) aF[i] = *(const float4*)(base + (size_t)gr * stride + koff + kq * 4);
        }
    };

    auto issueB = [&](int c, int buf) {
        int k0 = c * 64;
        uint32_t dst = uB0 + (uint32_t)buf * (2 * TILE_B);
        #pragma unroll
        for (int i = 0; i < 4; i++) {
            int uidx = i * 256 + tid;
            int n    = uidx >> 3;
            int kq   = uidx & 7;
            uint32_t off = sw128((uint32_t)(n * 128 + kq * 16));
            CP_ASYNC16(dst + off,          (const char*)(Bh + (size_t)n * K + k0 + kq * 8));
            CP_ASYNC16(dst + TILE_B + off, (const char*)(Bl + (size_t)n * K + k0 + kq * 8));
        }
        asm volatile("cp.async.commit_group;" ::: "memory");
    };

    issueB(0, 0);
    prefetchA(0);

    for (int c = 0; c < nChunks; c++) {
        const int buf = c & 1;

        // ---- convert prefetched A regs -> hi/lo bf16 smem (overlaps B[c] arrival) ----
        #pragma unroll
        for (int i = 0; i < 8; i++) {
            int fidx = i * 256 + tid;
            int r    = fidx >> 4;
            int kq   = fidx & 15;
            float r0, r1, r2, r3;
            uint32_t h0 = packbf2(aF[i].x, aF[i].y, &r0, &r1);
            uint32_t h1 = packbf2(aF[i].z, aF[i].w, &r2, &r3);
            uint32_t l0 = packbf2(r0, r1, nullptr, nullptr);
            uint32_t l1 = packbf2(r2, r3, nullptr, nullptr);
            uint32_t off = sw128((uint32_t)(r * 128 + kq * 8));
            *(uint2*)(sAh + off) = make_uint2(h0, h1);
            *(uint2*)(sAl + off) = make_uint2(l0, l1);
        }

        // ---- kick B[c+1] into other buffer, then wait only for B[c] ----
        if (c + 1 < nChunks) {
            issueB(c + 1, buf ^ 1);
            asm volatile("cp.async.wait_group 1;" ::: "memory");
        } else {
            asm volatile("cp.async.wait_group 0;" ::: "memory");
        }
        __syncthreads();

        // ---- prefetch next A chunk (retires during compute) ----
        if (c + 1 < nChunks) prefetchA(c + 1);

        const uint32_t uBh = uB0 + (uint32_t)buf * (2 * TILE_B);
        const uint32_t uBl = uBh + TILE_B;

        // ---- compute: 4 k16-steps; Ah*Bh + Al*Bh + Ah*Bl ----
        #pragma unroll
        for (int ks = 0; ks < 4; ks++) {
            const int kb = ks * 32;
            uint32_t ah[2][4], al[2][4], bq[4][4];

            #pragma unroll
            for (int mt = 0; mt < 2; mt++)
                ldsm_x4(ah[mt], uAh + sw128((uint32_t)((mBase + mt * 16 + aRowL) * 128 + kb + aKbL)));
            #pragma unroll
            for (int mt = 0; mt < 2; mt++)
                ldsm_x4(al[mt], uAl + sw128((uint32_t)((mBase + mt * 16 + aRowL) * 128 + kb + aKbL)));
            #pragma unroll
            for (int p = 0; p < 4; p++)
                ldsm_x4(bq[p], uBh + sw128((uint32_t)((nBase + p * 16 + bRowL) * 128 + kb + bKbL)));

            #pragma unroll
            for (int mt = 0; mt < 2; mt++)
                #pragma unroll
                for (int p = 0; p < 4; p++) {
                    mma16816(acc[mt][2 * p],     ah[mt], &bq[p][0]);
                    mma16816(acc[mt][2 * p + 1], ah[mt], &bq[p][2]);
                }
            #pragma unroll
            for (int mt = 0; mt < 2; mt++)
                #pragma unroll
                for (int p = 0; p < 4; p++) {
                    mma16816(acc[mt][2 * p],     al[mt], &bq[p][0]);
                    mma16816(acc[mt][2 * p + 1], al[mt], &bq[p][2]);
                }

            #pragma unroll
            for (int p = 0; p < 4; p++)
                ldsm_x4(bq[p], uBl + sw128((uint32_t)((nBase + p * 16 + bRowL) * 128 + kb + bKbL)));
            #pragma unroll
            for (int mt = 0; mt < 2; mt++)
                #pragma unroll
                for (int p = 0; p < 4; p++) {
                    mma16816(acc[mt][2 * p],     ah[mt], &bq[p][0]);
                    mma16816(acc[mt][2 * p + 1], ah[mt], &bq[p][2]);
                }
        }
        __syncthreads();
    }

    const int rL = lane >> 2;
    const int cL = (lane & 3) * 2;

    if (lnG) {
        // ---- fused LayerNorm + ReLU epilogue (bias added pre-LN) ----
        float* ssum = (float*)sm;            // [128][2]
        float* ssq  = (float*)(sm + 1024);   // [128][2]
        const int half = warp >> 2;

        #pragma unroll
        for (int mt = 0; mt < 2; mt++)
            #pragma unroll
            for (int hr = 0; hr < 2; hr++) {
                int lr = mBase + mt * 16 + rL + hr * 8;
                float s = 0.f, q = 0.f;
                #pragma unroll
                for (int nt = 0; nt < 8; nt++)
                    #pragma unroll
                    for (int cc = 0; cc < 2; cc++) {
                        float v = acc[mt][nt][hr * 2 + cc] + bias[nBase + nt * 8 + cL + cc];
                        s += v; q += v * v;
                    }
                s += __shfl_xor_sync(0xffffffffu, s, 1);
                q += __shfl_xor_sync(0xffffffffu, q, 1);
                s += __shfl_xor_sync(0xffffffffu, s, 2);
                q += __shfl_xor_sync(0xffffffffu, q, 2);
                if ((lane & 3) == 0) { ssum[lr * 2 + half] = s; ssq[lr * 2 + half] = q; }
            }
        __syncthreads();

        #pragma unroll
        for (int mt = 0; mt < 2; mt++)
            #pragma unroll
            for (int hr = 0; hr < 2; hr++) {
                int lr  = mBase + mt * 16 + rL + hr * 8;
                int row = rowBase + lr;
                float s = ssum[lr * 2] + ssum[lr * 2 + 1];
                float q = ssq [lr * 2] + ssq [lr * 2 + 1];
                float mu  = s * (1.0f / 128.0f);
                float var = q * (1.0f / 128.0f) - mu * mu;
                float rst = rsqrtf(var + EPSV);
                if (row < NN) {
                    #pragma unroll
                    for (int nt = 0; nt < 8; nt++) {
                        int col = nBase + nt * 8 + cL;
                        float v0 = acc[mt][nt][hr * 2]     + bias[col];
                        float v1 = acc[mt][nt][hr * 2 + 1] + bias[col + 1];
                        v0 = fmaxf((v0 - mu) * rst * lnG[col]     + lnB[col],     0.f);
                        v1 = fmaxf((v1 - mu) * rst * lnG[col + 1] + lnB[col + 1], 0.f);
                        *(float2*)&C[(size_t)row * 128 + col] = make_float2(v0, v1);
                    }
                }
            }
        return;
    }

    // ---- standard epilogue: bias/relu ----
    #pragma unroll
    for (int mt = 0; mt < 2; mt++) {
        #pragma unroll
        for (int hr = 0; hr < 2; hr++) {
            int row = rowBase + mBase + mt * 16 + rL + hr * 8;
            if (row >= NN) continue;
            #pragma unroll
            for (int nt = 0; nt < 8; nt++) {
                int col = nBase + nt * 8 + cL;
                float v0 = acc[mt][nt][hr * 2];
                float v1 = acc[mt][nt][hr * 2 + 1];
                if (bias) { v0 += bias[col]; v1 += bias[col + 1]; }
                if (relu) { v0 = fmaxf(v0, 0.f); v1 = fmaxf(v1, 0.f); }
                *(float2*)&C[(size_t)row * 128 + col] = make_float2(v0, v1);
            }
        }
    }
}

// ====== fused CSR SPMM: out[d] = act(dinv^2*xw[d] + sum norm*xw[src] + b) ======
__global__ void __launch_bounds__(256)
k_spmm_csr(const float* __restrict__ bias, float* __restrict__ out, int relu)
{
    int w = (blockIdx.x * blockDim.x + threadIdx.x) >> 5;
    if (w >= NN) return;
    int lane = threadIdx.x & 31;
    int c = lane * 4;

    float di = g_dinv[w];
    float wt = di * di;
    float4 acc = *(const float4*)&g_xw[(size_t)w * 128 + c];
    acc.x *= wt; acc.y *= wt; acc.z *= wt; acc.w *= wt;

    int start = g_rowptr[w];
    int end   = g_rowptr[w + 1];
    for (int base = start; base < end; base += 32) {
        int rem = end - base;
        int2 p = make_int2(0, 0);
        if (lane < rem) p = g_epack[base + lane];
        if (rem >= 32) {
            #pragma unroll
            for (int j = 0; j < 32; j++) {
                int   s  = __shfl_sync(0xffffffffu, p.x, j);
                float nm = __int_as_float(__shfl_sync(0xffffffffu, p.y, j));
                float4 v = *(const float4*)&g_xw[(size_t)s * 128 + c];
                acc.x = fmaf(nm, v.x, acc.x);
                acc.y = fmaf(nm, v.y, acc.y);
                acc.z = fmaf(nm, v.z, acc.z);
                acc.w = fmaf(nm, v.w, acc.w);
            }
        } else {
            for (int j = 0; j < rem; j++) {
                int   s  = __shfl_sync(0xffffffffu, p.x, j);
                float nm = __int_as_float(__shfl_sync(0xffffffffu, p.y, j));
                float4 v = *(const float4*)&g_xw[(size_t)s * 128 + c];
                acc.x = fmaf(nm, v.x, acc.x);
                acc.y = fmaf(nm, v.y, acc.y);
                acc.z = fmaf(nm, v.z, acc.z);
                acc.w = fmaf(nm, v.w, acc.w);
            }
        }
    }

    float4 bb = *(const float4*)&bias[c];
    acc.x += bb.x; acc.y += bb.y; acc.z += bb.z; acc.w += bb.w;
    if (relu) {
        acc.x = fmaxf(acc.x, 0.f); acc.y = fmaxf(acc.y, 0.f);
        acc.z = fmaxf(acc.z, 0.f); acc.w = fmaxf(acc.w, 0.f);
    }
    *(float4*)&out[(size_t)w * 128 + c] = acc;
}

// ================= launch =================
extern "C" void kernel_launch(void* const* d_in, const int* in_sizes, int n_in,
                              void* d_out, int out_size)
{
    (void)in_sizes; (void)n_in; (void)out_size;
    const int*   ei    = (const int*)  d_in[0];
    const float* ext   = (const float*)d_in[1];
    const float* emb   = (const float*)d_in[2];
    const float* encW  = (const float*)d_in[3];
    const float* encB  = (const float*)d_in[4];
    const float* lng   = (const float*)d_in[5];
    const float* lnb   = (const float*)d_in[6];
    const float* projW = (const float*)d_in[7];
    const float* projB = (const float*)d_in[8];
    const float* W0    = (const float*)d_in[9];
    const float* b0    = (const float*)d_in[10];
    const float* W1    = (const float*)d_in[11];
    const float* b1    = (const float*)d_in[12];
    const float* W2    = (const float*)d_in[13];
    const float* b2    = (const float*)d_in[14];
    float* out = (float*)d_out;

    const int* src = ei;
    const int* dst = ei + EE;

    float *p_tmp, *p_x, *p_xw;
    cudaGetSymbolAddress((void**)&p_tmp, g_tmp);
    cudaGetSymbolAddress((void**)&p_x,   g_x);
    cudaGetSymbolAddress((void**)&p_xw,  g_xw);

    __nv_bfloat16 *bh_enc, *bl_enc, *bh_proj, *bl_proj, *bh_w0, *bl_w0, *bh_w1, *bl_w1, *bh_w2, *bl_w2;
    cudaGetSymbolAddress((void**)&bh_enc,  g_bh_enc);
    cudaGetSymbolAddress((void**)&bl_enc,  g_bl_enc);
    cudaGetSymbolAddress((void**)&bh_proj, g_bh_proj);
    cudaGetSymbolAddress((void**)&bl_proj, g_bl_proj);
    cudaGetSymbolAddress((void**)&bh_w0,   g_bh_w0);
    cudaGetSymbolAddress((void**)&bl_w0,   g_bl_w0);
    cudaGetSymbolAddress((void**)&bh_w1,   g_bh_w1);
    cudaGetSymbolAddress((void**)&bl_w1,   g_bl_w1);
    cudaGetSymbolAddress((void**)&bh_w2,   g_bh_w2);
    cudaGetSymbolAddress((void**)&bl_w2,   g_bl_w2);

    cudaFuncSetAttribute(k_gemm_mma, cudaFuncAttributeMaxDynamicSharedMemorySize, GEMM_DYN);

    const int TB = 256;
    const int gN     = (NN + TB - 1) / TB;
    const int gE     = (EE + TB - 1) / TB;
    const int gRow   = (NN * 32 + TB - 1) / TB;
    const int gGemm  = (NN + 127) / 128;

    // ---- CSR build ----
    k_zero<<<gN, TB>>>();
    k_degree<<<gE, TB>>>(dst);
    k_scan1<<<SCAN_NB, SCAN_T>>>();
    k_scan2<<<1, 128>>>();
    k_scan3<<<gN, TB>>>();
    k_scatter<<<gE, TB>>>(src, dst);

    // ---- weight splits ----
    k_split<<<(768 * 128 + TB - 1) / TB, TB>>>(encW,  768, bh_enc,  bl_enc);
    k_split<<<(256 * 128 + TB - 1) / TB, TB>>>(projW, 256, bh_proj, bl_proj);
    k_split<<<(128 * 128 + TB - 1) / TB, TB>>>(W0,    128, bh_w0,   bl_w0);
    k_split<<<(128 * 128 + TB - 1) / TB, TB>>>(W1,    128, bh_w1,   bl_w1);
    k_split<<<(128 * 128 + TB - 1) / TB, TB>>>(W2,    128, bh_w2,   bl_w2);

    // ---- encoder GEMM with fused LN+ReLU ----
    k_gemm_mma<<<gGemm, TB, GEMM_DYN>>>(ext, EXTD, ext, EXTD, EXTD, EXTD,
                                        bh_enc, bl_enc, encB, 0, lng, lnb, p_tmp);

    // ---- projection: A = [emb | feat] read directly by k-range ----
    k_gemm_mma<<<gGemm, TB, GEMM_DYN>>>(emb, HH, p_tmp, HH, HH, 2 * HH,
                                        bh_proj, bl_proj, projB, 0, nullptr, nullptr, p_x);

    // ---- GCN layers ----
    k_gemm_mma<<<gGemm, TB, GEMM_DYN>>>(p_x, HH, p_x, HH, HH, HH,
                                        bh_w0, bl_w0, nullptr, 0, nullptr, nullptr, p_xw);
    k_spmm_csr<<<gRow, TB>>>(b0, p_x, 1);

    k_gemm_mma<<<gGemm, TB, GEMM_DYN>>>(p_x, HH, p_x, HH, HH, HH,
                                        bh_w1, bl_w1, nullptr, 0, nullptr, nullptr, p_xw);
    k_spmm_csr<<<gRow, TB>>>(b1, p_x, 1);

    k_gemm_mma<<<gGemm, TB, GEMM_DYN>>>(p_x, HH, p_x, HH, HH, HH,
                                        bh_w2, bl_w2, nullptr, 0, nullptr, nullptr, p_xw);
    k_spmm_csr<<<gRow, TB>>>(b2, out, 0);
}

// round 7
// speedup vs baseline: 3.3925x; 1.0234x over previous
#include <cuda_runtime.h>
#include <cuda_bf16.h>
#include <cstdint>

// Problem constants
#define NN   100000
#define HH   128
#define EE   1600000
#define EXTD 768
#define EPSV 1e-5f

// ================= device scratch (no allocations allowed) =================
__device__ float g_dinv[NN];
__device__ int   g_degi[NN];
__device__ int   g_cursor[NN];
__device__ int   g_rowptr[NN + 1];
__device__ int   g_bsum[128];
__device__ int   g_bsumx[128];
__device__ int2  g_epack[EE];          // (src, norm-bits) sorted by dst
__device__ float g_tmp [NN * HH];      // encoder LN+ReLU output
__device__ float g_x   [NN * HH];
__device__ float g_xw  [NN * HH];

// split-bf16 transposed weights: [N=128 rows][K cols]
__device__ __nv_bfloat16 g_bh_enc [128 * 768];
__device__ __nv_bfloat16 g_bl_enc [128 * 768];
__device__ __nv_bfloat16 g_bh_proj[128 * 256];
__device__ __nv_bfloat16 g_bl_proj[128 * 256];
__device__ __nv_bfloat16 g_bh_w0  [128 * 128];
__device__ __nv_bfloat16 g_bl_w0  [128 * 128];
__device__ __nv_bfloat16 g_bh_w1  [128 * 128];
__device__ __nv_bfloat16 g_bl_w1  [128 * 128];
__device__ __nv_bfloat16 g_bh_w2  [128 * 128];
__device__ __nv_bfloat16 g_bl_w2  [128 * 128];

// ================= helpers =================
__device__ __forceinline__ uint32_t smem_u32(const void* p) {
    uint32_t a;
    asm("{ .reg .u64 t; cvta.to.shared.u64 t, %1; cvt.u32.u64 %0, t; }" : "=r"(a) : "l"(p));
    return a;
}
__device__ __forceinline__ uint32_t sw128(uint32_t o) { return o ^ ((o >> 3) & 0x70); }

__device__ __forceinline__ void ldsm_x4(uint32_t* r, uint32_t addr) {
    asm volatile("ldmatrix.sync.aligned.m8n8.x4.shared.b16 {%0,%1,%2,%3}, [%4];"
        : "=r"(r[0]), "=r"(r[1]), "=r"(r[2]), "=r"(r[3]) : "r"(addr));
}
__device__ __forceinline__ void mma16816(float* c, const uint32_t* a, const uint32_t* b) {
    asm volatile(
        "mma.sync.aligned.m16n8k16.row.col.f32.bf16.bf16.f32 "
        "{%0,%1,%2,%3}, {%4,%5,%6,%7}, {%8,%9}, {%0,%1,%2,%3};"
        : "+f"(c[0]), "+f"(c[1]), "+f"(c[2]), "+f"(c[3])
        : "r"(a[0]), "r"(a[1]), "r"(a[2]), "r"(a[3]), "r"(b[0]), "r"(b[1]));
}
#define CP_ASYNC16(smem, gptr) \
    asm volatile("cp.async.cg.shared.global [%0], [%1], 16;" :: "r"(smem), "l"(gptr))

__device__ __forceinline__ uint32_t packbf2(float a, float b, float* ra, float* rb) {
    __nv_bfloat16 ha = __float2bfloat16_rn(a), hb = __float2bfloat16_rn(b);
    if (ra) { *ra = a - __bfloat162float(ha); *rb = b - __bfloat162float(hb); }
    return (uint32_t)__bfloat16_as_ushort(ha) | ((uint32_t)__bfloat16_as_ushort(hb) << 16);
}

// ================= graph prep: CSR build =================
__global__ void k_zero() {
    int i = blockIdx.x * blockDim.x + threadIdx.x;
    if (i < NN) { g_degi[i] = 0; g_cursor[i] = 0; }
}
__global__ void k_degree(const int* __restrict__ dst) {
    int e = blockIdx.x * blockDim.x + threadIdx.x;
    if (e < EE) atomicAdd(&g_degi[dst[e]], 1);
}

#define SCAN_T 256
#define SCAN_NB ((NN + SCAN_T * 4 - 1) / (SCAN_T * 4))   // 98
__global__ void __launch_bounds__(SCAN_T) k_scan1() {
    __shared__ int s[SCAN_T];
    int t = threadIdx.x;
    int base = blockIdx.x * SCAN_T * 4 + t * 4;
    int v[4];
    #pragma unroll
    for (int j = 0; j < 4; j++) {
        v[j] = (base + j < NN) ? g_degi[base + j] : 0;
        if (base + j < NN) g_dinv[base + j] = rsqrtf((float)(v[j] + 1));  // +1 self-loop
    }
    int tsum = v[0] + v[1] + v[2] + v[3];
    s[t] = tsum; __syncthreads();
    #pragma unroll
    for (int off = 1; off < SCAN_T; off <<= 1) {
        int x = (t >= off) ? s[t - off] : 0;
        __syncthreads();
        s[t] += x;
        __syncthreads();
    }
    int run = s[t] - tsum;
    #pragma unroll
    for (int j = 0; j < 4; j++) {
        if (base + j < NN) g_rowptr[base + j] = run;
        run += v[j];
    }
    if (t == SCAN_T - 1) g_bsum[blockIdx.x] = s[SCAN_T - 1];
}
__global__ void __launch_bounds__(128) k_scan2() {
    __shared__ int s[128];
    int t = threadIdx.x;
    int v = (t < SCAN_NB) ? g_bsum[t] : 0;
    s[t] = v; __syncthreads();
    #pragma unroll
    for (int off = 1; off < 128; off <<= 1) {
        int x = (t >= off) ? s[t - off] : 0;
        __syncthreads();
        s[t] += x;
        __syncthreads();
    }
    if (t < SCAN_NB) g_bsumx[t] = s[t] - v;
}
__global__ void k_scan3() {
    int i = blockIdx.x * blockDim.x + threadIdx.x;
    if (i < NN) g_rowptr[i] += g_bsumx[i / (SCAN_T * 4)];
    if (i == 0) g_rowptr[NN] = EE;
}
__global__ void k_scatter(const int* __restrict__ src, const int* __restrict__ dst) {
    int e = blockIdx.x * blockDim.x + threadIdx.x;
    if (e >= EE) return;
    int d = dst[e];
    int s = src[e];
    int pos = g_rowptr[d] + atomicAdd(&g_cursor[d], 1);
    float nm = g_dinv[s] * g_dinv[d];
    g_epack[pos] = make_int2(s, __float_as_int(nm));
}

// ============ all weight splits in one kernel: W[K][128] -> Bh/Bl [128][K] ============
#define SPLIT_TOT (768*128 + 256*128 + 3*128*128)
__global__ void k_split_all(const float* __restrict__ encW, const float* __restrict__ projW,
                            const float* __restrict__ W0, const float* __restrict__ W1,
                            const float* __restrict__ W2) {
    int idx = blockIdx.x * blockDim.x + threadIdx.x;
    if (idx >= SPLIT_TOT) return;
    const float* W; __nv_bfloat16 *Bh, *Bl; int K; int local = idx;
    if (local < 768*128)              { W = encW;  Bh = g_bh_enc;  Bl = g_bl_enc;  K = 768; }
    else if ((local -= 768*128) < 256*128) { W = projW; Bh = g_bh_proj; Bl = g_bl_proj; K = 256; }
    else if ((local -= 256*128) < 128*128) { W = W0;    Bh = g_bh_w0;   Bl = g_bl_w0;   K = 128; }
    else if ((local -= 128*128) < 128*128) { W = W1;    Bh = g_bh_w1;   Bl = g_bl_w1;   K = 128; }
    else  { local -= 128*128;           W = W2;    Bh = g_bh_w2;   Bl = g_bl_w2;   K = 128; }
    int k = local >> 7;
    int n = local & 127;
    float w = W[local];
    __nv_bfloat16 h = __float2bfloat16_rn(w);
    float r = w - __bfloat162float(h);
    Bh[n * K + k] = h;
    Bl[n * K + k] = __float2bfloat16_rn(r);
}

// ============ pipelined mma.sync split-bf16 GEMM: C[M,128] = [Aa|Ab] @ W[K,128] ============
// A and B both double-buffered; A convert interleaved into the MMA stream.
#define TILE_B 16384
#define GEMM_DYN (8 * TILE_B + 1024)

__global__ void __launch_bounds__(256, 1)
k_gemm_mma(const float* __restrict__ Aa, int strideA,
           const float* __restrict__ Ab, int strideB, int kSplit, int K,
           const __nv_bfloat16* __restrict__ Bh, const __nv_bfloat16* __restrict__ Bl,
           const float* __restrict__ bias, int relu,
           const float* __restrict__ lnG, const float* __restrict__ lnB,
           float* __restrict__ C)
{
    extern __shared__ char dyn[];
    const int tid = threadIdx.x;
    const int rowBase = blockIdx.x * 128;

    uint32_t dynb = smem_u32(dyn);
    char* sm = dyn + (((dynb + 1023u) & ~1023u) - dynb);
    // layout: Abuf0(h,l) Abuf1(h,l) Bbuf0(h,l) Bbuf1(h,l), each TILE_B
    const uint32_t uA0 = smem_u32(sm);
    const uint32_t uB0 = smem_u32(sm + 4 * TILE_B);

    const int lane = tid & 31;
    const int warp = tid >> 5;
    const int mBase = (warp & 3) * 32;
    const int nBase = (warp >> 2) * 64;

    const int aRowL = (lane & 7) + ((lane & 8) ? 8 : 0);
    const int aKbL  = (lane & 16) ? 16 : 0;
    const int bRowL = (lane & 7) + ((lane & 16) ? 8 : 0);
    const int bKbL  = (lane & 8) ? 16 : 0;

    float acc[2][8][4];
    #pragma unroll
    for (int mt = 0; mt < 2; mt++)
        #pragma unroll
        for (int nt = 0; nt < 8; nt++)
            #pragma unroll
            for (int j = 0; j < 4; j++) acc[mt][nt][j] = 0.0f;

    const int nChunks = K >> 6;
    float4 aF[8];

    auto prefetchA = [&](int c) {
        int k0 = c * 64;
        const float* base; int stride; int koff;
        if (k0 < kSplit) { base = Aa; stride = strideA; koff = k0; }
        else             { base = Ab; stride = strideB; koff = k0 - kSplit; }
        #pragma unroll
        for (int i = 0; i < 8; i++) {
            int fidx = i * 256 + tid;
            int r    = fidx >> 4;
            int kq   = fidx & 15;
            int gr   = rowBase + r;
            aF[i] = make_float4(0.f, 0.f, 0.f, 0.f);
            if (gr < NN) aF[i] = *(const float4*)(base + (size_t)gr * stride + koff + kq * 4);
        }
    };

    // convert half of aF regs into A buffer `buf` (half = 0 or 1)
    auto convertHalf = [&](int buf, int half) {
        char* dh = sm + buf * (2 * TILE_B);
        char* dl = dh + TILE_B;
        #pragma unroll
        for (int i = half * 4; i < half * 4 + 4; i++) {
            int fidx = i * 256 + tid;
            int r    = fidx >> 4;
            int kq   = fidx & 15;
            float r0, r1, r2, r3;
            uint32_t h0 = packbf2(aF[i].x, aF[i].y, &r0, &r1);
            uint32_t h1 = packbf2(aF[i].z, aF[i].w, &r2, &r3);
            uint32_t l0 = packbf2(r0, r1, nullptr, nullptr);
            uint32_t l1 = packbf2(r2, r3, nullptr, nullptr);
            uint32_t off = sw128((uint32_t)(r * 128 + kq * 8));
            *(uint2*)(dh + off) = make_uint2(h0, h1);
            *(uint2*)(dl + off) = make_uint2(l0, l1);
        }
    };

    auto issueB = [&](int c, int buf) {
        int k0 = c * 64;
        uint32_t dst = uB0 + (uint32_t)buf * (2 * TILE_B);
        #pragma unroll
        for (int i = 0; i < 4; i++) {
            int uidx = i * 256 + tid;
            int n    = uidx >> 3;
            int kq   = uidx & 7;
            uint32_t off = sw128((uint32_t)(n * 128 + kq * 16));
            CP_ASYNC16(dst + off,          (const char*)(Bh + (size_t)n * K + k0 + kq * 8));
            CP_ASYNC16(dst + TILE_B + off, (const char*)(Bl + (size_t)n * K + k0 + kq * 8));
        }
        asm volatile("cp.async.commit_group;" ::: "memory");
    };

    // ---- prologue: stage chunk 0, prefetch chunk 1 regs ----
    prefetchA(0);
    issueB(0, 0);
    convertHalf(0, 0);
    convertHalf(0, 1);
    if (nChunks > 1) prefetchA(1);

    for (int c = 0; c < nChunks; c++) {
        const int buf  = c & 1;
        const bool hasNext = (c + 1 < nChunks);

        asm volatile("cp.async.wait_group 0;" ::: "memory");   // B[c] landed
        __syncthreads();   // all warps done with previous chunk's buffers; stores visible

        if (hasNext) issueB(c + 1, buf ^ 1);   // safe post-sync; waited next iter

        const uint32_t uAh = uA0 + (uint32_t)buf * (2 * TILE_B);
        const uint32_t uAl = uAh + TILE_B;
        const uint32_t uBh = uB0 + (uint32_t)buf * (2 * TILE_B);
        const uint32_t uBl = uBh + TILE_B;

        // ---- compute 4 k16-steps, convert of chunk c+1 interleaved ----
        #pragma unroll
        for (int ks = 0; ks < 4; ks++) {
            const int kb = ks * 32;
            uint32_t ah[2][4], al[2][4], bq[4][4];

            #pragma unroll
            for (int mt = 0; mt < 2; mt++)
                ldsm_x4(ah[mt], uAh + sw128((uint32_t)((mBase + mt * 16 + aRowL) * 128 + kb + aKbL)));
            #pragma unroll
            for (int mt = 0; mt < 2; mt++)
                ldsm_x4(al[mt], uAl + sw128((uint32_t)((mBase + mt * 16 + aRowL) * 128 + kb + aKbL)));
            #pragma unroll
            for (int p = 0; p < 4; p++)
                ldsm_x4(bq[p], uBh + sw128((uint32_t)((nBase + p * 16 + bRowL) * 128 + kb + bKbL)));

            #pragma unroll
            for (int mt = 0; mt < 2; mt++)
                #pragma unroll
                for (int p = 0; p < 4; p++) {
                    mma16816(acc[mt][2 * p],     ah[mt], &bq[p][0]);
                    mma16816(acc[mt][2 * p + 1], ah[mt], &bq[p][2]);
                }
            #pragma unroll
            for (int mt = 0; mt < 2; mt++)
                #pragma unroll
                for (int p = 0; p < 4; p++) {
                    mma16816(acc[mt][2 * p],     al[mt], &bq[p][0]);
                    mma16816(acc[mt][2 * p + 1], al[mt], &bq[p][2]);
                }

            #pragma unroll
            for (int p = 0; p < 4; p++)
                ldsm_x4(bq[p], uBl + sw128((uint32_t)((nBase + p * 16 + bRowL) * 128 + kb + bKbL)));
            #pragma unroll
            for (int mt = 0; mt < 2; mt++)
                #pragma unroll
                for (int p = 0; p < 4; p++) {
                    mma16816(acc[mt][2 * p],     ah[mt], &bq[p][0]);
                    mma16816(acc[mt][2 * p + 1], ah[mt], &bq[p][2]);
                }

            // interleaved staging of chunk c+1 (FMA/ALU pipe under the MMA stream)
            if (ks == 0 && hasNext) convertHalf(buf ^ 1, 0);
            if (ks == 1 && hasNext) {
                convertHalf(buf ^ 1, 1);
                if (c + 2 < nChunks) prefetchA(c + 2);   // regs free after convert
            }
        }
        // no bottom sync: next iteration's top sync guards buffer reuse
    }

    const int rL = lane >> 2;
    const int cL = (lane & 3) * 2;

    if (lnG) {
        // ---- fused LayerNorm + ReLU epilogue (bias added pre-LN) ----
        __syncthreads();   // everyone done computing before smem reuse
        float* ssum = (float*)sm;            // [128][2]
        float* ssq  = (float*)(sm + 1024);   // [128][2]
        const int half = warp >> 2;

        #pragma unroll
        for (int mt = 0; mt < 2; mt++)
            #pragma unroll
            for (int hr = 0; hr < 2; hr++) {
                int lr = mBase + mt * 16 + rL + hr * 8;
                float s = 0.f, q = 0.f;
                #pragma unroll
                for (int nt = 0; nt < 8; nt++)
                    #pragma unroll
                    for (int cc = 0; cc < 2; cc++) {
                        float v = acc[mt][nt][hr * 2 + cc] + bias[nBase + nt * 8 + cL + cc];
                        s += v; q += v * v;
                    }
                s += __shfl_xor_sync(0xffffffffu, s, 1);
                q += __shfl_xor_sync(0xffffffffu, q, 1);
                s += __shfl_xor_sync(0xffffffffu, s, 2);
                q += __shfl_xor_sync(0xffffffffu, q, 2);
                if ((lane & 3) == 0) { ssum[lr * 2 + half] = s; ssq[lr * 2 + half] = q; }
            }
        __syncthreads();

        #pragma unroll
        for (int mt = 0; mt < 2; mt++)
            #pragma unroll
            for (int hr = 0; hr < 2; hr++) {
                int lr  = mBase + mt * 16 + rL + hr * 8;
                int row = rowBase + lr;
                float s = ssum[lr * 2] + ssum[lr * 2 + 1];
                float q = ssq [lr * 2] + ssq [lr * 2 + 1];
                float mu  = s * (1.0f / 128.0f);
                float var = q * (1.0f / 128.0f) - mu * mu;
                float rst = rsqrtf(var + EPSV);
                if (row < NN) {
                    #pragma unroll
                    for (int nt = 0; nt < 8; nt++) {
                        int col = nBase + nt * 8 + cL;
                        float v0 = acc[mt][nt][hr * 2]     + bias[col];
                        float v1 = acc[mt][nt][hr * 2 + 1] + bias[col + 1];
                        v0 = fmaxf((v0 - mu) * rst * lnG[col]     + lnB[col],     0.f);
                        v1 = fmaxf((v1 - mu) * rst * lnG[col + 1] + lnB[col + 1], 0.f);
                        *(float2*)&C[(size_t)row * 128 + col] = make_float2(v0, v1);
                    }
                }
            }
        return;
    }

    // ---- standard epilogue: bias/relu ----
    #pragma unroll
    for (int mt = 0; mt < 2; mt++) {
        #pragma unroll
        for (int hr = 0; hr < 2; hr++) {
            int row = rowBase + mBase + mt * 16 + rL + hr * 8;
            if (row >= NN) continue;
            #pragma unroll
            for (int nt = 0; nt < 8; nt++) {
                int col = nBase + nt * 8 + cL;
                float v0 = acc[mt][nt][hr * 2];
                float v1 = acc[mt][nt][hr * 2 + 1];
                if (bias) { v0 += bias[col]; v1 += bias[col + 1]; }
                if (relu) { v0 = fmaxf(v0, 0.f); v1 = fmaxf(v1, 0.f); }
                *(float2*)&C[(size_t)row * 128 + col] = make_float2(v0, v1);
            }
        }
    }
}

// ====== fused CSR SPMM: out[d] = act(dinv^2*xw[d] + sum norm*xw[src] + b) ======
__global__ void __launch_bounds__(256)
k_spmm_csr(const float* __restrict__ bias, float* __restrict__ out, int relu)
{
    int w = (blockIdx.x * blockDim.x + threadIdx.x) >> 5;
    if (w >= NN) return;
    int lane = threadIdx.x & 31;
    int c = lane * 4;

    float di = g_dinv[w];
    float wt = di * di;
    float4 acc = *(const float4*)&g_xw[(size_t)w * 128 + c];
    acc.x *= wt; acc.y *= wt; acc.z *= wt; acc.w *= wt;

    int start = g_rowptr[w];
    int end   = g_rowptr[w + 1];
    for (int base = start; base < end; base += 32) {
        int rem = end - base;
        int2 p = make_int2(0, 0);
        if (lane < rem) p = g_epack[base + lane];
        if (rem >= 32) {
            #pragma unroll
            for (int j = 0; j < 32; j++) {
                int   s  = __shfl_sync(0xffffffffu, p.x, j);
                float nm = __int_as_float(__shfl_sync(0xffffffffu, p.y, j));
                float4 v = *(const float4*)&g_xw[(size_t)s * 128 + c];
                acc.x = fmaf(nm, v.x, acc.x);
                acc.y = fmaf(nm, v.y, acc.y);
                acc.z = fmaf(nm, v.z, acc.z);
                acc.w = fmaf(nm, v.w, acc.w);
            }
        } else {
            for (int j = 0; j < rem; j++) {
                int   s  = __shfl_sync(0xffffffffu, p.x, j);
                float nm = __int_as_float(__shfl_sync(0xffffffffu, p.y, j));
                float4 v = *(const float4*)&g_xw[(size_t)s * 128 + c];
                acc.x = fmaf(nm, v.x, acc.x);
                acc.y = fmaf(nm, v.y, acc.y);
                acc.z = fmaf(nm, v.z, acc.z);
                acc.w = fmaf(nm, v.w, acc.w);
            }
        }
    }

    float4 bb = *(const float4*)&bias[c];
    acc.x += bb.x; acc.y += bb.y; acc.z += bb.z; acc.w += bb.w;
    if (relu) {
        acc.x = fmaxf(acc.x, 0.f); acc.y = fmaxf(acc.y, 0.f);
        acc.z = fmaxf(acc.z, 0.f); acc.w = fmaxf(acc.w, 0.f);
    }
    *(float4*)&out[(size_t)w * 128 + c] = acc;
}

// ================= launch =================
extern "C" void kernel_launch(void* const* d_in, const int* in_sizes, int n_in,
                              void* d_out, int out_size)
{
    (void)in_sizes; (void)n_in; (void)out_size;
    const int*   ei    = (const int*)  d_in[0];
    const float* ext   = (const float*)d_in[1];
    const float* emb   = (const float*)d_in[2];
    const float* encW  = (const float*)d_in[3];
    const float* encB  = (const float*)d_in[4];
    const float* lng   = (const float*)d_in[5];
    const float* lnb   = (const float*)d_in[6];
    const float* projW = (const float*)d_in[7];
    const float* projB = (const float*)d_in[8];
    const float* W0    = (const float*)d_in[9];
    const float* b0    = (const float*)d_in[10];
    const float* W1    = (const float*)d_in[11];
    const float* b1    = (const float*)d_in[12];
    const float* W2    = (const float*)d_in[13];
    const float* b2    = (const float*)d_in[14];
    float* out = (float*)d_out;

    const int* src = ei;
    const int* dst = ei + EE;

    float *p_tmp, *p_x, *p_xw;
    cudaGetSymbolAddress((void**)&p_tmp, g_tmp);
    cudaGetSymbolAddress((void**)&p_x,   g_x);
    cudaGetSymbolAddress((void**)&p_xw,  g_xw);

    __nv_bfloat16 *bh_enc, *bl_enc, *bh_proj, *bl_proj, *bh_w0, *bl_w0, *bh_w1, *bl_w1, *bh_w2, *bl_w2;
    cudaGetSymbolAddress((void**)&bh_enc,  g_bh_enc);
    cudaGetSymbolAddress((void**)&bl_enc,  g_bl_enc);
    cudaGetSymbolAddress((void**)&bh_proj, g_bh_proj);
    cudaGetSymbolAddress((void**)&bl_proj, g_bl_proj);
    cudaGetSymbolAddress((void**)&bh_w0,   g_bh_w0);
    cudaGetSymbolAddress((void**)&bl_w0,   g_bl_w0);
    cudaGetSymbolAddress((void**)&bh_w1,   g_bh_w1);
    cudaGetSymbolAddress((void**)&bl_w1,   g_bl_w1);
    cudaGetSymbolAddress((void**)&bh_w2,   g_bh_w2);
    cudaGetSymbolAddress((void**)&bl_w2,   g_bl_w2);

    cudaFuncSetAttribute(k_gemm_mma, cudaFuncAttributeMaxDynamicSharedMemorySize, GEMM_DYN);

    const int TB = 256;
    const int gN     = (NN + TB - 1) / TB;
    const int gE     = (EE + TB - 1) / TB;
    const int gRow   = (NN * 32 + TB - 1) / TB;
    const int gGemm  = (NN + 127) / 128;

    // ---- CSR build ----
    k_zero<<<gN, TB>>>();
    k_degree<<<gE, TB>>>(dst);
    k_scan1<<<SCAN_NB, SCAN_T>>>();
    k_scan2<<<1, 128>>>();
    k_scan3<<<gN, TB>>>();
    k_scatter<<<gE, TB>>>(src, dst);

    // ---- all weight splits (one launch) ----
    k_split_all<<<(SPLIT_TOT + TB - 1) / TB, TB>>>(encW, projW, W0, W1, W2);

    // ---- encoder GEMM with fused LN+ReLU ----
    k_gemm_mma<<<gGemm, TB, GEMM_DYN>>>(ext, EXTD, ext, EXTD, EXTD, EXTD,
                                        bh_enc, bl_enc, encB, 0, lng, lnb, p_tmp);

    // ---- projection: A = [emb | feat] read directly by k-range ----
    k_gemm_mma<<<gGemm, TB, GEMM_DYN>>>(emb, HH, p_tmp, HH, HH, 2 * HH,
                                        bh_proj, bl_proj, projB, 0, nullptr, nullptr, p_x);

    // ---- GCN layers ----
    k_gemm_mma<<<gGemm, TB, GEMM_DYN>>>(p_x, HH, p_x, HH, HH, HH,
                                        bh_w0, bl_w0, nullptr, 0, nullptr, nullptr, p_xw);
    k_spmm_csr<<<gRow, TB>>>(b0, p_x, 1);

    k_gemm_mma<<<gGemm, TB, GEMM_DYN>>>(p_x, HH, p_x, HH, HH, HH,
                                        bh_w1, bl_w1, nullptr, 0, nullptr, nullptr, p_xw);
    k_spmm_csr<<<gRow, TB>>>(b1, p_x, 1);

    k_gemm_mma<<<gGemm, TB, GEMM_DYN>>>(p_x, HH, p_x, HH, HH, HH,
                                        bh_w2, bl_w2, nullptr, 0, nullptr, nullptr, p_xw);
    k_spmm_csr<<<gRow, TB>>>(b2, out, 0);
}

// round 8
// speedup vs baseline: 3.5584x; 1.0489x over previous
#include <cuda_runtime.h>
#include <cuda_bf16.h>
#include <cstdint>

// Problem constants
#define NN   100000
#define HH   128
#define EE   1600000
#define EXTD 768
#define EPSV 1e-5f

// ================= device scratch (no allocations allowed) =================
__device__ float g_dinv[NN];
__device__ int   g_degi[NN];
__device__ int   g_cursor[NN];
__device__ int   g_rowptr[NN + 1];
__device__ int   g_bsum[128];
__device__ int   g_bsumx[128];
__device__ int2  g_epack[EE];          // (src, norm-bits) sorted by dst
__device__ float g_tmp [NN * HH];      // encoder LN+ReLU output
__device__ float g_x   [NN * HH];
__device__ float g_xw  [NN * HH];

// split-bf16 transposed weights: [N=128 rows][K cols]
__device__ __nv_bfloat16 g_bh_enc [128 * 768];
__device__ __nv_bfloat16 g_bl_enc [128 * 768];
__device__ __nv_bfloat16 g_bh_proj[128 * 256];
__device__ __nv_bfloat16 g_bl_proj[128 * 256];
__device__ __nv_bfloat16 g_bh_w0  [128 * 128];
__device__ __nv_bfloat16 g_bl_w0  [128 * 128];
__device__ __nv_bfloat16 g_bh_w1  [128 * 128];
__device__ __nv_bfloat16 g_bl_w1  [128 * 128];
__device__ __nv_bfloat16 g_bh_w2  [128 * 128];
__device__ __nv_bfloat16 g_bl_w2  [128 * 128];

// ================= helpers =================
__device__ __forceinline__ uint32_t smem_u32(const void* p) {
    uint32_t a;
    asm("{ .reg .u64 t; cvta.to.shared.u64 t, %1; cvt.u32.u64 %0, t; }" : "=r"(a) : "l"(p));
    return a;
}
__device__ __forceinline__ uint32_t sw128(uint32_t o) { return o ^ ((o >> 3) & 0x70); }

__device__ __forceinline__ void ldsm_x4(uint32_t* r, uint32_t addr) {
    asm volatile("ldmatrix.sync.aligned.m8n8.x4.shared.b16 {%0,%1,%2,%3}, [%4];"
        : "=r"(r[0]), "=r"(r[1]), "=r"(r[2]), "=r"(r[3]) : "r"(addr));
}
__device__ __forceinline__ void mma16816(float* c, const uint32_t* a, const uint32_t* b) {
    asm volatile(
        "mma.sync.aligned.m16n8k16.row.col.f32.bf16.bf16.f32 "
        "{%0,%1,%2,%3}, {%4,%5,%6,%7}, {%8,%9}, {%0,%1,%2,%3};"
        : "+f"(c[0]), "+f"(c[1]), "+f"(c[2]), "+f"(c[3])
        : "r"(a[0]), "r"(a[1]), "r"(a[2]), "r"(a[3]), "r"(b[0]), "r"(b[1]));
}
#define CP_ASYNC16(smem, gptr) \
    asm volatile("cp.async.cg.shared.global [%0], [%1], 16;" :: "r"(smem), "l"(gptr))

__device__ __forceinline__ uint32_t packbf2(float a, float b, float* ra, float* rb) {
    __nv_bfloat16 ha = __float2bfloat16_rn(a), hb = __float2bfloat16_rn(b);
    if (ra) { *ra = a - __bfloat162float(ha); *rb = b - __bfloat162float(hb); }
    return (uint32_t)__bfloat16_as_ushort(ha) | ((uint32_t)__bfloat16_as_ushort(hb) << 16);
}

// ================= graph prep: CSR build =================
__global__ void k_zero() {
    int i = blockIdx.x * blockDim.x + threadIdx.x;
    if (i < NN) { g_degi[i] = 0; g_cursor[i] = 0; }
}
__global__ void k_degree(const int* __restrict__ dst) {
    int e = blockIdx.x * blockDim.x + threadIdx.x;
    if (e < EE) atomicAdd(&g_degi[dst[e]], 1);
}

#define SCAN_T 256
#define SCAN_NB ((NN + SCAN_T * 4 - 1) / (SCAN_T * 4))   // 98
__global__ void __launch_bounds__(SCAN_T) k_scan1() {
    __shared__ int s[SCAN_T];
    int t = threadIdx.x;
    int base = blockIdx.x * SCAN_T * 4 + t * 4;
    int v[4];
    #pragma unroll
    for (int j = 0; j < 4; j++) {
        v[j] = (base + j < NN) ? g_degi[base + j] : 0;
        if (base + j < NN) g_dinv[base + j] = rsqrtf((float)(v[j] + 1));  // +1 self-loop
    }
    int tsum = v[0] + v[1] + v[2] + v[3];
    s[t] = tsum; __syncthreads();
    #pragma unroll
    for (int off = 1; off < SCAN_T; off <<= 1) {
        int x = (t >= off) ? s[t - off] : 0;
        __syncthreads();
        s[t] += x;
        __syncthreads();
    }
    int run = s[t] - tsum;
    #pragma unroll
    for (int j = 0; j < 4; j++) {
        if (base + j < NN) g_rowptr[base + j] = run;
        run += v[j];
    }
    if (t == SCAN_T - 1) g_bsum[blockIdx.x] = s[SCAN_T - 1];
}
__global__ void __launch_bounds__(128) k_scan2() {
    __shared__ int s[128];
    int t = threadIdx.x;
    int v = (t < SCAN_NB) ? g_bsum[t] : 0;
    s[t] = v; __syncthreads();
    #pragma unroll
    for (int off = 1; off < 128; off <<= 1) {
        int x = (t >= off) ? s[t - off] : 0;
        __syncthreads();
        s[t] += x;
        __syncthreads();
    }
    if (t < SCAN_NB) g_bsumx[t] = s[t] - v;
}
__global__ void k_scan3() {
    int i = blockIdx.x * blockDim.x + threadIdx.x;
    if (i < NN) g_rowptr[i] += g_bsumx[i / (SCAN_T * 4)];
    if (i == 0) g_rowptr[NN] = EE;
}
__global__ void k_scatter(const int* __restrict__ src, const int* __restrict__ dst) {
    int e = blockIdx.x * blockDim.x + threadIdx.x;
    if (e >= EE) return;
    int d = dst[e];
    int s = src[e];
    int pos = g_rowptr[d] + atomicAdd(&g_cursor[d], 1);
    float nm = g_dinv[s] * g_dinv[d];
    g_epack[pos] = make_int2(s, __float_as_int(nm));
}

// ============ all weight splits in one kernel: W[K][128] -> Bh/Bl [128][K] ============
#define SPLIT_TOT (768*128 + 256*128 + 3*128*128)
__global__ void k_split_all(const float* __restrict__ encW, const float* __restrict__ projW,
                            const float* __restrict__ W0, const float* __restrict__ W1,
                            const float* __restrict__ W2) {
    int idx = blockIdx.x * blockDim.x + threadIdx.x;
    if (idx >= SPLIT_TOT) return;
    const float* W; __nv_bfloat16 *Bh, *Bl; int K; int local = idx;
    if (local < 768*128)              { W = encW;  Bh = g_bh_enc;  Bl = g_bl_enc;  K = 768; }
    else if ((local -= 768*128) < 256*128) { W = projW; Bh = g_bh_proj; Bl = g_bl_proj; K = 256; }
    else if ((local -= 256*128) < 128*128) { W = W0;    Bh = g_bh_w0;   Bl = g_bl_w0;   K = 128; }
    else if ((local -= 128*128) < 128*128) { W = W1;    Bh = g_bh_w1;   Bl = g_bl_w1;   K = 128; }
    else  { local -= 128*128;           W = W2;    Bh = g_bh_w2;   Bl = g_bl_w2;   K = 128; }
    int k = local >> 7;
    int n = local & 127;
    float w = W[local];
    __nv_bfloat16 h = __float2bfloat16_rn(w);
    float r = w - __bfloat162float(h);
    Bh[n * K + k] = h;
    Bl[n * K + k] = __float2bfloat16_rn(r);
}

// ============ pipelined mma.sync split-bf16 GEMM: C[M,128] = [Aa|Ab] @ W[K,128] ============
// A and B both double-buffered; A convert interleaved into the MMA stream.
#define TILE_B 16384
#define GEMM_DYN (8 * TILE_B + 1024)

__global__ void __launch_bounds__(256, 1)
k_gemm_mma(const float* __restrict__ Aa, int strideA,
           const float* __restrict__ Ab, int strideB, int kSplit, int K,
           const __nv_bfloat16* __restrict__ Bh, const __nv_bfloat16* __restrict__ Bl,
           const float* __restrict__ bias, int relu,
           const float* __restrict__ lnG, const float* __restrict__ lnB,
           float* __restrict__ C)
{
    extern __shared__ char dyn[];
    const int tid = threadIdx.x;
    const int rowBase = blockIdx.x * 128;

    uint32_t dynb = smem_u32(dyn);
    char* sm = dyn + (((dynb + 1023u) & ~1023u) - dynb);
    const uint32_t uA0 = smem_u32(sm);
    const uint32_t uB0 = smem_u32(sm + 4 * TILE_B);

    const int lane = tid & 31;
    const int warp = tid >> 5;
    const int mBase = (warp & 3) * 32;
    const int nBase = (warp >> 2) * 64;

    const int aRowL = (lane & 7) + ((lane & 8) ? 8 : 0);
    const int aKbL  = (lane & 16) ? 16 : 0;
    const int bRowL = (lane & 7) + ((lane & 16) ? 8 : 0);
    const int bKbL  = (lane & 8) ? 16 : 0;

    float acc[2][8][4];
    #pragma unroll
    for (int mt = 0; mt < 2; mt++)
        #pragma unroll
        for (int nt = 0; nt < 8; nt++)
            #pragma unroll
            for (int j = 0; j < 4; j++) acc[mt][nt][j] = 0.0f;

    const int nChunks = K >> 6;
    float4 aF[8];

    auto prefetchA = [&](int c) {
        int k0 = c * 64;
        const float* base; int stride; int koff;
        if (k0 < kSplit) { base = Aa; stride = strideA; koff = k0; }
        else             { base = Ab; stride = strideB; koff = k0 - kSplit; }
        #pragma unroll
        for (int i = 0; i < 8; i++) {
            int fidx = i * 256 + tid;
            int r    = fidx >> 4;
            int kq   = fidx & 15;
            int gr   = rowBase + r;
            aF[i] = make_float4(0.f, 0.f, 0.f, 0.f);
            if (gr < NN) aF[i] = *(const float4*)(base + (size_t)gr * stride + koff + kq * 4);
        }
    };

    auto convertHalf = [&](int buf, int half) {
        char* dh = sm + buf * (2 * TILE_B);
        char* dl = dh + TILE_B;
        #pragma unroll
        for (int i = half * 4; i < half * 4 + 4; i++) {
            int fidx = i * 256 + tid;
            int r    = fidx >> 4;
            int kq   = fidx & 15;
            float r0, r1, r2, r3;
            uint32_t h0 = packbf2(aF[i].x, aF[i].y, &r0, &r1);
            uint32_t h1 = packbf2(aF[i].z, aF[i].w, &r2, &r3);
            uint32_t l0 = packbf2(r0, r1, nullptr, nullptr);
            uint32_t l1 = packbf2(r2, r3, nullptr, nullptr);
            uint32_t off = sw128((uint32_t)(r * 128 + kq * 8));
            *(uint2*)(dh + off) = make_uint2(h0, h1);
            *(uint2*)(dl + off) = make_uint2(l0, l1);
        }
    };

    auto issueB = [&](int c, int buf) {
        int k0 = c * 64;
        uint32_t dst = uB0 + (uint32_t)buf * (2 * TILE_B);
        #pragma unroll
        for (int i = 0; i < 4; i++) {
            int uidx = i * 256 + tid;
            int n    = uidx >> 3;
            int kq   = uidx & 7;
            uint32_t off = sw128((uint32_t)(n * 128 + kq * 16));
            CP_ASYNC16(dst + off,          (const char*)(Bh + (size_t)n * K + k0 + kq * 8));
            CP_ASYNC16(dst + TILE_B + off, (const char*)(Bl + (size_t)n * K + k0 + kq * 8));
        }
        asm volatile("cp.async.commit_group;" ::: "memory");
    };

    // ---- prologue: stage chunk 0, prefetch chunk 1 regs ----
    prefetchA(0);
    issueB(0, 0);
    convertHalf(0, 0);
    convertHalf(0, 1);
    if (nChunks > 1) prefetchA(1);

    for (int c = 0; c < nChunks; c++) {
        const int buf  = c & 1;
        const bool hasNext = (c + 1 < nChunks);

        asm volatile("cp.async.wait_group 0;" ::: "memory");
        __syncthreads();

        if (hasNext) issueB(c + 1, buf ^ 1);

        const uint32_t uAh = uA0 + (uint32_t)buf * (2 * TILE_B);
        const uint32_t uAl = uAh + TILE_B;
        const uint32_t uBh = uB0 + (uint32_t)buf * (2 * TILE_B);
        const uint32_t uBl = uBh + TILE_B;

        #pragma unroll
        for (int ks = 0; ks < 4; ks++) {
            const int kb = ks * 32;
            uint32_t ah[2][4], al[2][4], bq[4][4];

            #pragma unroll
            for (int mt = 0; mt < 2; mt++)
                ldsm_x4(ah[mt], uAh + sw128((uint32_t)((mBase + mt * 16 + aRowL) * 128 + kb + aKbL)));
            #pragma unroll
            for (int mt = 0; mt < 2; mt++)
                ldsm_x4(al[mt], uAl + sw128((uint32_t)((mBase + mt * 16 + aRowL) * 128 + kb + aKbL)));
            #pragma unroll
            for (int p = 0; p < 4; p++)
                ldsm_x4(bq[p], uBh + sw128((uint32_t)((nBase + p * 16 + bRowL) * 128 + kb + bKbL)));

            #pragma unroll
            for (int mt = 0; mt < 2; mt++)
                #pragma unroll
                for (int p = 0; p < 4; p++) {
                    mma16816(acc[mt][2 * p],     ah[mt], &bq[p][0]);
                    mma16816(acc[mt][2 * p + 1], ah[mt], &bq[p][2]);
                }
            #pragma unroll
            for (int mt = 0; mt < 2; mt++)
                #pragma unroll
                for (int p = 0; p < 4; p++) {
                    mma16816(acc[mt][2 * p],     al[mt], &bq[p][0]);
                    mma16816(acc[mt][2 * p + 1], al[mt], &bq[p][2]);
                }

            #pragma unroll
            for (int p = 0; p < 4; p++)
                ldsm_x4(bq[p], uBl + sw128((uint32_t)((nBase + p * 16 + bRowL) * 128 + kb + bKbL)));
            #pragma unroll
            for (int mt = 0; mt < 2; mt++)
                #pragma unroll
                for (int p = 0; p < 4; p++) {
                    mma16816(acc[mt][2 * p],     ah[mt], &bq[p][0]);
                    mma16816(acc[mt][2 * p + 1], ah[mt], &bq[p][2]);
                }

            if (ks == 0 && hasNext) convertHalf(buf ^ 1, 0);
            if (ks == 1 && hasNext) {
                convertHalf(buf ^ 1, 1);
                if (c + 2 < nChunks) prefetchA(c + 2);
            }
        }
    }

    const int rL = lane >> 2;
    const int cL = (lane & 3) * 2;

    if (lnG) {
        __syncthreads();
        float* ssum = (float*)sm;            // [128][2]
        float* ssq  = (float*)(sm + 1024);   // [128][2]
        const int half = warp >> 2;

        #pragma unroll
        for (int mt = 0; mt < 2; mt++)
            #pragma unroll
            for (int hr = 0; hr < 2; hr++) {
                int lr = mBase + mt * 16 + rL + hr * 8;
                float s = 0.f, q = 0.f;
                #pragma unroll
                for (int nt = 0; nt < 8; nt++)
                    #pragma unroll
                    for (int cc = 0; cc < 2; cc++) {
                        float v = acc[mt][nt][hr * 2 + cc] + bias[nBase + nt * 8 + cL + cc];
                        s += v; q += v * v;
                    }
                s += __shfl_xor_sync(0xffffffffu, s, 1);
                q += __shfl_xor_sync(0xffffffffu, q, 1);
                s += __shfl_xor_sync(0xffffffffu, s, 2);
                q += __shfl_xor_sync(0xffffffffu, q, 2);
                if ((lane & 3) == 0) { ssum[lr * 2 + half] = s; ssq[lr * 2 + half] = q; }
            }
        __syncthreads();

        #pragma unroll
        for (int mt = 0; mt < 2; mt++)
            #pragma unroll
            for (int hr = 0; hr < 2; hr++) {
                int lr  = mBase + mt * 16 + rL + hr * 8;
                int row = rowBase + lr;
                float s = ssum[lr * 2] + ssum[lr * 2 + 1];
                float q = ssq [lr * 2] + ssq [lr * 2 + 1];
                float mu  = s * (1.0f / 128.0f);
                float var = q * (1.0f / 128.0f) - mu * mu;
                float rst = rsqrtf(var + EPSV);
                if (row < NN) {
                    #pragma unroll
                    for (int nt = 0; nt < 8; nt++) {
                        int col = nBase + nt * 8 + cL;
                        float v0 = acc[mt][nt][hr * 2]     + bias[col];
                        float v1 = acc[mt][nt][hr * 2 + 1] + bias[col + 1];
                        v0 = fmaxf((v0 - mu) * rst * lnG[col]     + lnB[col],     0.f);
                        v1 = fmaxf((v1 - mu) * rst * lnG[col + 1] + lnB[col + 1], 0.f);
                        *(float2*)&C[(size_t)row * 128 + col] = make_float2(v0, v1);
                    }
                }
            }
        return;
    }

    #pragma unroll
    for (int mt = 0; mt < 2; mt++) {
        #pragma unroll
        for (int hr = 0; hr < 2; hr++) {
            int row = rowBase + mBase + mt * 16 + rL + hr * 8;
            if (row >= NN) continue;
            #pragma unroll
            for (int nt = 0; nt < 8; nt++) {
                int col = nBase + nt * 8 + cL;
                float v0 = acc[mt][nt][hr * 2];
                float v1 = acc[mt][nt][hr * 2 + 1];
                if (bias) { v0 += bias[col]; v1 += bias[col + 1]; }
                if (relu) { v0 = fmaxf(v0, 0.f); v1 = fmaxf(v1, 0.f); }
                *(float2*)&C[(size_t)row * 128 + col] = make_float2(v0, v1);
            }
        }
    }
}

// ====== fused CSR SPMM: out[d] = act(dinv^2*xw[d] + sum norm*xw[src] + b) ======
__global__ void __launch_bounds__(256)
k_spmm_csr(const float* __restrict__ bias, float* __restrict__ out, int relu)
{
    int w = (blockIdx.x * blockDim.x + threadIdx.x) >> 5;
    if (w >= NN) return;
    int lane = threadIdx.x & 31;
    int c = lane * 4;

    float di = g_dinv[w];
    float wt = di * di;
    float4 acc = *(const float4*)&g_xw[(size_t)w * 128 + c];
    acc.x *= wt; acc.y *= wt; acc.z *= wt; acc.w *= wt;
    float4 acc2 = make_float4(0.f, 0.f, 0.f, 0.f);

    int start = g_rowptr[w];
    int end   = g_rowptr[w + 1];
    for (int base = start; base < end; base += 32) {
        int rem = end - base;
        int2 p = make_int2(0, 0);
        if (lane < rem) p = g_epack[base + lane];
        if (rem >= 32) {
            #pragma unroll
            for (int j = 0; j < 32; j += 2) {
                int   s0  = __shfl_sync(0xffffffffu, p.x, j);
                float nm0 = __int_as_float(__shfl_sync(0xffffffffu, p.y, j));
                int   s1  = __shfl_sync(0xffffffffu, p.x, j + 1);
                float nm1 = __int_as_float(__shfl_sync(0xffffffffu, p.y, j + 1));
                float4 v0 = *(const float4*)&g_xw[(size_t)s0 * 128 + c];
                float4 v1 = *(const float4*)&g_xw[(size_t)s1 * 128 + c];
                acc.x  = fmaf(nm0, v0.x, acc.x);
                acc.y  = fmaf(nm0, v0.y, acc.y);
                acc.z  = fmaf(nm0, v0.z, acc.z);
                acc.w  = fmaf(nm0, v0.w, acc.w);
                acc2.x = fmaf(nm1, v1.x, acc2.x);
                acc2.y = fmaf(nm1, v1.y, acc2.y);
                acc2.z = fmaf(nm1, v1.z, acc2.z);
                acc2.w = fmaf(nm1, v1.w, acc2.w);
            }
        } else {
            for (int j = 0; j < rem; j++) {
                int   s  = __shfl_sync(0xffffffffu, p.x, j);
                float nm = __int_as_float(__shfl_sync(0xffffffffu, p.y, j));
                float4 v = *(const float4*)&g_xw[(size_t)s * 128 + c];
                acc.x = fmaf(nm, v.x, acc.x);
                acc.y = fmaf(nm, v.y, acc.y);
                acc.z = fmaf(nm, v.z, acc.z);
                acc.w = fmaf(nm, v.w, acc.w);
            }
        }
    }
    acc.x += acc2.x; acc.y += acc2.y; acc.z += acc2.z; acc.w += acc2.w;

    float4 bb = *(const float4*)&bias[c];
    acc.x += bb.x; acc.y += bb.y; acc.z += bb.z; acc.w += bb.w;
    if (relu) {
        acc.x = fmaxf(acc.x, 0.f); acc.y = fmaxf(acc.y, 0.f);
        acc.z = fmaxf(acc.z, 0.f); acc.w = fmaxf(acc.w, 0.f);
    }
    *(float4*)&out[(size_t)w * 128 + c] = acc;
}

// ================= launch =================
extern "C" void kernel_launch(void* const* d_in, const int* in_sizes, int n_in,
                              void* d_out, int out_size)
{
    (void)in_sizes; (void)n_in; (void)out_size;
    const int*   ei    = (const int*)  d_in[0];
    const float* ext   = (const float*)d_in[1];
    const float* emb   = (const float*)d_in[2];
    const float* encW  = (const float*)d_in[3];
    const float* encB  = (const float*)d_in[4];
    const float* lng   = (const float*)d_in[5];
    const float* lnb   = (const float*)d_in[6];
    const float* projW = (const float*)d_in[7];
    const float* projB = (const float*)d_in[8];
    const float* W0    = (const float*)d_in[9];
    const float* b0    = (const float*)d_in[10];
    const float* W1    = (const float*)d_in[11];
    const float* b1    = (const float*)d_in[12];
    const float* W2    = (const float*)d_in[13];
    const float* b2    = (const float*)d_in[14];
    float* out = (float*)d_out;

    const int* src = ei;
    const int* dst = ei + EE;

    float *p_tmp, *p_x, *p_xw;
    cudaGetSymbolAddress((void**)&p_tmp, g_tmp);
    cudaGetSymbolAddress((void**)&p_x,   g_x);
    cudaGetSymbolAddress((void**)&p_xw,  g_xw);

    __nv_bfloat16 *bh_enc, *bl_enc, *bh_proj, *bl_proj, *bh_w0, *bl_w0, *bh_w1, *bl_w1, *bh_w2, *bl_w2;
    cudaGetSymbolAddress((void**)&bh_enc,  g_bh_enc);
    cudaGetSymbolAddress((void**)&bl_enc,  g_bl_enc);
    cudaGetSymbolAddress((void**)&bh_proj, g_bh_proj);
    cudaGetSymbolAddress((void**)&bl_proj, g_bl_proj);
    cudaGetSymbolAddress((void**)&bh_w0,   g_bh_w0);
    cudaGetSymbolAddress((void**)&bl_w0,   g_bl_w0);
    cudaGetSymbolAddress((void**)&bh_w1,   g_bh_w1);
    cudaGetSymbolAddress((void**)&bl_w1,   g_bl_w1);
    cudaGetSymbolAddress((void**)&bh_w2,   g_bh_w2);
    cudaGetSymbolAddress((void**)&bl_w2,   g_bl_w2);

    cudaFuncSetAttribute(k_gemm_mma, cudaFuncAttributeMaxDynamicSharedMemorySize, GEMM_DYN);

    // side stream + fork/join events (created once, outside capture; DisableTiming
    // is required for events recorded inside a captured graph)
    static cudaStream_t sB = nullptr;
    static cudaEvent_t evF = nullptr, evJ = nullptr;
    if (!sB) {
        cudaStreamCreate(&sB);
        cudaEventCreateWithFlags(&evF, cudaEventDisableTiming);
        cudaEventCreateWithFlags(&evJ, cudaEventDisableTiming);
    }

    const int TB = 256;
    const int gN     = (NN + TB - 1) / TB;
    const int gE     = (EE + TB - 1) / TB;
    const int gRow   = (NN * 32 + TB - 1) / TB;
    const int gGemm  = (NN + 127) / 128;

    // ---- fork: CSR build on side stream, dense chain on main stream ----
    cudaEventRecord(evF, 0);
    cudaStreamWaitEvent(sB, evF, 0);

    k_zero<<<gN, TB, 0, sB>>>();
    k_degree<<<gE, TB, 0, sB>>>(dst);
    k_scan1<<<SCAN_NB, SCAN_T, 0, sB>>>();
    k_scan2<<<1, 128, 0, sB>>>();
    k_scan3<<<gN, TB, 0, sB>>>();
    k_scatter<<<gE, TB, 0, sB>>>(src, dst);
    cudaEventRecord(evJ, sB);

    // main stream: weight splits + encoder/proj/layer-0 GEMMs (independent of CSR)
    k_split_all<<<(SPLIT_TOT + TB - 1) / TB, TB>>>(encW, projW, W0, W1, W2);

    k_gemm_mma<<<gGemm, TB, GEMM_DYN>>>(ext, EXTD, ext, EXTD, EXTD, EXTD,
                                        bh_enc, bl_enc, encB, 0, lng, lnb, p_tmp);

    k_gemm_mma<<<gGemm, TB, GEMM_DYN>>>(emb, HH, p_tmp, HH, HH, 2 * HH,
                                        bh_proj, bl_proj, projB, 0, nullptr, nullptr, p_x);

    k_gemm_mma<<<gGemm, TB, GEMM_DYN>>>(p_x, HH, p_x, HH, HH, HH,
                                        bh_w0, bl_w0, nullptr, 0, nullptr, nullptr, p_xw);

    // ---- join: SPMM needs the CSR ----
    cudaStreamWaitEvent(0, evJ, 0);

    k_spmm_csr<<<gRow, TB>>>(b0, p_x, 1);

    k_gemm_mma<<<gGemm, TB, GEMM_DYN>>>(p_x, HH, p_x, HH, HH, HH,
                                        bh_w1, bl_w1, nullptr, 0, nullptr, nullptr, p_xw);
    k_spmm_csr<<<gRow, TB>>>(b1, p_x, 1);

    k_gemm_mma<<<gGemm, TB, GEMM_DYN>>>(p_x, HH, p_x, HH, HH, HH,
                                        bh_w2, bl_w2, nullptr, 0, nullptr, nullptr, p_xw);
    k_spmm_csr<<<gRow, TB>>>(b2, out, 0);
}

// round 9
// speedup vs baseline: 3.7757x; 1.0611x over previous
#include <cuda_runtime.h>
#include <cuda_bf16.h>
#include <cuda_fp16.h>
#include <cstdint>

// Problem constants
#define NN   100000
#define HH   128
#define EE   1600000
#define EXTD 768
#define EPSV 1e-5f

// ================= device scratch (no allocations allowed) =================
__device__ float g_dinv[NN];
__device__ int   g_degi[NN];
__device__ int   g_cursor[NN];
__device__ int   g_rowptr[NN + 1];
__device__ int   g_bsum[128];
__device__ int   g_bsumx[128];
__device__ int2  g_epack[EE];          // (src, norm-bits) sorted by dst
__device__ float g_tmp [NN * HH];      // encoder LN+ReLU output
__device__ float g_x   [NN * HH];
__device__ __half g_xwh[NN * HH];      // layer GEMM output, fp16 (SPMM gather source)

// split-bf16 transposed weights: [N=128 rows][K cols]
__device__ __nv_bfloat16 g_bh_enc [128 * 768];
__device__ __nv_bfloat16 g_bl_enc [128 * 768];
__device__ __nv_bfloat16 g_bh_proj[128 * 256];
__device__ __nv_bfloat16 g_bl_proj[128 * 256];
__device__ __nv_bfloat16 g_bh_w0  [128 * 128];
__device__ __nv_bfloat16 g_bl_w0  [128 * 128];
__device__ __nv_bfloat16 g_bh_w1  [128 * 128];
__device__ __nv_bfloat16 g_bl_w1  [128 * 128];
__device__ __nv_bfloat16 g_bh_w2  [128 * 128];
__device__ __nv_bfloat16 g_bl_w2  [128 * 128];

// ================= helpers =================
__device__ __forceinline__ uint32_t smem_u32(const void* p) {
    uint32_t a;
    asm("{ .reg .u64 t; cvta.to.shared.u64 t, %1; cvt.u32.u64 %0, t; }" : "=r"(a) : "l"(p));
    return a;
}
__device__ __forceinline__ uint32_t sw128(uint32_t o) { return o ^ ((o >> 3) & 0x70); }

__device__ __forceinline__ void ldsm_x4(uint32_t* r, uint32_t addr) {
    asm volatile("ldmatrix.sync.aligned.m8n8.x4.shared.b16 {%0,%1,%2,%3}, [%4];"
        : "=r"(r[0]), "=r"(r[1]), "=r"(r[2]), "=r"(r[3]) : "r"(addr));
}
__device__ __forceinline__ void mma16816(float* c, const uint32_t* a, const uint32_t* b) {
    asm volatile(
        "mma.sync.aligned.m16n8k16.row.col.f32.bf16.bf16.f32 "
        "{%0,%1,%2,%3}, {%4,%5,%6,%7}, {%8,%9}, {%0,%1,%2,%3};"
        : "+f"(c[0]), "+f"(c[1]), "+f"(c[2]), "+f"(c[3])
        : "r"(a[0]), "r"(a[1]), "r"(a[2]), "r"(a[3]), "r"(b[0]), "r"(b[1]));
}
#define CP_ASYNC16(smem, gptr) \
    asm volatile("cp.async.cg.shared.global [%0], [%1], 16;" :: "r"(smem), "l"(gptr))

__device__ __forceinline__ uint32_t packbf2(float a, float b, float* ra, float* rb) {
    __nv_bfloat16 ha = __float2bfloat16_rn(a), hb = __float2bfloat16_rn(b);
    if (ra) { *ra = a - __bfloat162float(ha); *rb = b - __bfloat162float(hb); }
    return (uint32_t)__bfloat16_as_ushort(ha) | ((uint32_t)__bfloat16_as_ushort(hb) << 16);
}

// load 4 fp16 (8B) from a row and widen to float4
__device__ __forceinline__ float4 ldh4(const __half* p, int c) {
    uint2 u = *(const uint2*)(p + c);
    __half2 h0 = *reinterpret_cast<__half2*>(&u.x);
    __half2 h1 = *reinterpret_cast<__half2*>(&u.y);
    float2 a = __half22float2(h0);
    float2 b = __half22float2(h1);
    return make_float4(a.x, a.y, b.x, b.y);
}

// ================= graph prep: CSR build =================
__global__ void k_zero() {
    int i = blockIdx.x * blockDim.x + threadIdx.x;
    if (i < NN) { g_degi[i] = 0; g_cursor[i] = 0; }
}
__global__ void k_degree(const int* __restrict__ dst) {
    int e = blockIdx.x * blockDim.x + threadIdx.x;
    if (e < EE) atomicAdd(&g_degi[dst[e]], 1);
}

#define SCAN_T 256
#define SCAN_NB ((NN + SCAN_T * 4 - 1) / (SCAN_T * 4))   // 98
__global__ void __launch_bounds__(SCAN_T) k_scan1() {
    __shared__ int s[SCAN_T];
    int t = threadIdx.x;
    int base = blockIdx.x * SCAN_T * 4 + t * 4;
    int v[4];
    #pragma unroll
    for (int j = 0; j < 4; j++) {
        v[j] = (base + j < NN) ? g_degi[base + j] : 0;
        if (base + j < NN) g_dinv[base + j] = rsqrtf((float)(v[j] + 1));  // +1 self-loop
    }
    int tsum = v[0] + v[1] + v[2] + v[3];
    s[t] = tsum; __syncthreads();
    #pragma unroll
    for (int off = 1; off < SCAN_T; off <<= 1) {
        int x = (t >= off) ? s[t - off] : 0;
        __syncthreads();
        s[t] += x;
        __syncthreads();
    }
    int run = s[t] - tsum;
    #pragma unroll
    for (int j = 0; j < 4; j++) {
        if (base + j < NN) g_rowptr[base + j] = run;
        run += v[j];
    }
    if (t == SCAN_T - 1) g_bsum[blockIdx.x] = s[SCAN_T - 1];
}
__global__ void __launch_bounds__(128) k_scan2() {
    __shared__ int s[128];
    int t = threadIdx.x;
    int v = (t < SCAN_NB) ? g_bsum[t] : 0;
    s[t] = v; __syncthreads();
    #pragma unroll
    for (int off = 1; off < 128; off <<= 1) {
        int x = (t >= off) ? s[t - off] : 0;
        __syncthreads();
        s[t] += x;
        __syncthreads();
    }
    if (t < SCAN_NB) g_bsumx[t] = s[t] - v;
}
__global__ void k_scan3() {
    int i = blockIdx.x * blockDim.x + threadIdx.x;
    if (i < NN) g_rowptr[i] += g_bsumx[i / (SCAN_T * 4)];
    if (i == 0) g_rowptr[NN] = EE;
}
__global__ void k_scatter(const int* __restrict__ src, const int* __restrict__ dst) {
    int e = blockIdx.x * blockDim.x + threadIdx.x;
    if (e >= EE) return;
    int d = dst[e];
    int s = src[e];
    int pos = g_rowptr[d] + atomicAdd(&g_cursor[d], 1);
    float nm = g_dinv[s] * g_dinv[d];
    g_epack[pos] = make_int2(s, __float_as_int(nm));
}

// ============ all weight splits in one kernel: W[K][128] -> Bh/Bl [128][K] ============
#define SPLIT_TOT (768*128 + 256*128 + 3*128*128)
__global__ void k_split_all(const float* __restrict__ encW, const float* __restrict__ projW,
                            const float* __restrict__ W0, const float* __restrict__ W1,
                            const float* __restrict__ W2) {
    int idx = blockIdx.x * blockDim.x + threadIdx.x;
    if (idx >= SPLIT_TOT) return;
    const float* W; __nv_bfloat16 *Bh, *Bl; int K; int local = idx;
    if (local < 768*128)              { W = encW;  Bh = g_bh_enc;  Bl = g_bl_enc;  K = 768; }
    else if ((local -= 768*128) < 256*128) { W = projW; Bh = g_bh_proj; Bl = g_bl_proj; K = 256; }
    else if ((local -= 256*128) < 128*128) { W = W0;    Bh = g_bh_w0;   Bl = g_bl_w0;   K = 128; }
    else if ((local -= 128*128) < 128*128) { W = W1;    Bh = g_bh_w1;   Bl = g_bl_w1;   K = 128; }
    else  { local -= 128*128;           W = W2;    Bh = g_bh_w2;   Bl = g_bl_w2;   K = 128; }
    int k = local >> 7;
    int n = local & 127;
    float w = W[local];
    __nv_bfloat16 h = __float2bfloat16_rn(w);
    float r = w - __bfloat162float(h);
    Bh[n * K + k] = h;
    Bl[n * K + k] = __float2bfloat16_rn(r);
}

// ============ pipelined mma.sync split-bf16 GEMM: C[M,128] = [Aa|Ab] @ W[K,128] ============
// A and B both double-buffered; A convert interleaved into the MMA stream.
// Optional outputs: C (fp32), Ch (fp16). Optional fused LN+ReLU (C only).
#define TILE_B 16384
#define GEMM_DYN (8 * TILE_B + 1024)

__global__ void __launch_bounds__(256, 1)
k_gemm_mma(const float* __restrict__ Aa, int strideA,
           const float* __restrict__ Ab, int strideB, int kSplit, int K,
           const __nv_bfloat16* __restrict__ Bh, const __nv_bfloat16* __restrict__ Bl,
           const float* __restrict__ bias, int relu,
           const float* __restrict__ lnG, const float* __restrict__ lnB,
           float* __restrict__ C, __half* __restrict__ Ch)
{
    extern __shared__ char dyn[];
    const int tid = threadIdx.x;
    const int rowBase = blockIdx.x * 128;

    uint32_t dynb = smem_u32(dyn);
    char* sm = dyn + (((dynb + 1023u) & ~1023u) - dynb);
    const uint32_t uA0 = smem_u32(sm);
    const uint32_t uB0 = smem_u32(sm + 4 * TILE_B);

    const int lane = tid & 31;
    const int warp = tid >> 5;
    const int mBase = (warp & 3) * 32;
    const int nBase = (warp >> 2) * 64;

    const int aRowL = (lane & 7) + ((lane & 8) ? 8 : 0);
    const int aKbL  = (lane & 16) ? 16 : 0;
    const int bRowL = (lane & 7) + ((lane & 16) ? 8 : 0);
    const int bKbL  = (lane & 8) ? 16 : 0;

    float acc[2][8][4];
    #pragma unroll
    for (int mt = 0; mt < 2; mt++)
        #pragma unroll
        for (int nt = 0; nt < 8; nt++)
            #pragma unroll
            for (int j = 0; j < 4; j++) acc[mt][nt][j] = 0.0f;

    const int nChunks = K >> 6;
    float4 aF[8];

    auto prefetchA = [&](int c) {
        int k0 = c * 64;
        const float* base; int stride; int koff;
        if (k0 < kSplit) { base = Aa; stride = strideA; koff = k0; }
        else             { base = Ab; stride = strideB; koff = k0 - kSplit; }
        #pragma unroll
        for (int i = 0; i < 8; i++) {
            int fidx = i * 256 + tid;
            int r    = fidx >> 4;
            int kq   = fidx & 15;
            int gr   = rowBase + r;
            aF[i] = make_float4(0.f, 0.f, 0.f, 0.f);
            if (gr < NN) aF[i] = *(const float4*)(base + (size_t)gr * stride + koff + kq * 4);
        }
    };

    auto convertHalf = [&](int buf, int half) {
        char* dh = sm + buf * (2 * TILE_B);
        char* dl = dh + TILE_B;
        #pragma unroll
        for (int i = half * 4; i < half * 4 + 4; i++) {
            int fidx = i * 256 + tid;
            int r    = fidx >> 4;
            int kq   = fidx & 15;
            float r0, r1, r2, r3;
            uint32_t h0 = packbf2(aF[i].x, aF[i].y, &r0, &r1);
            uint32_t h1 = packbf2(aF[i].z, aF[i].w, &r2, &r3);
            uint32_t l0 = packbf2(r0, r1, nullptr, nullptr);
            uint32_t l1 = packbf2(r2, r3, nullptr, nullptr);
            uint32_t off = sw128((uint32_t)(r * 128 + kq * 8));
            *(uint2*)(dh + off) = make_uint2(h0, h1);
            *(uint2*)(dl + off) = make_uint2(l0, l1);
        }
    };

    auto issueB = [&](int c, int buf) {
        int k0 = c * 64;
        uint32_t dst = uB0 + (uint32_t)buf * (2 * TILE_B);
        #pragma unroll
        for (int i = 0; i < 4; i++) {
            int uidx = i * 256 + tid;
            int n    = uidx >> 3;
            int kq   = uidx & 7;
            uint32_t off = sw128((uint32_t)(n * 128 + kq * 16));
            CP_ASYNC16(dst + off,          (const char*)(Bh + (size_t)n * K + k0 + kq * 8));
            CP_ASYNC16(dst + TILE_B + off, (const char*)(Bl + (size_t)n * K + k0 + kq * 8));
        }
        asm volatile("cp.async.commit_group;" ::: "memory");
    };

    // ---- prologue ----
    prefetchA(0);
    issueB(0, 0);
    convertHalf(0, 0);
    convertHalf(0, 1);
    if (nChunks > 1) prefetchA(1);

    for (int c = 0; c < nChunks; c++) {
        const int buf  = c & 1;
        const bool hasNext = (c + 1 < nChunks);

        asm volatile("cp.async.wait_group 0;" ::: "memory");
        __syncthreads();

        if (hasNext) issueB(c + 1, buf ^ 1);

        const uint32_t uAh = uA0 + (uint32_t)buf * (2 * TILE_B);
        const uint32_t uAl = uAh + TILE_B;
        const uint32_t uBh = uB0 + (uint32_t)buf * (2 * TILE_B);
        const uint32_t uBl = uBh + TILE_B;

        #pragma unroll
        for (int ks = 0; ks < 4; ks++) {
            const int kb = ks * 32;
            uint32_t ah[2][4], al[2][4], bq[4][4];

            #pragma unroll
            for (int mt = 0; mt < 2; mt++)
                ldsm_x4(ah[mt], uAh + sw128((uint32_t)((mBase + mt * 16 + aRowL) * 128 + kb + aKbL)));
            #pragma unroll
            for (int mt = 0; mt < 2; mt++)
                ldsm_x4(al[mt], uAl + sw128((uint32_t)((mBase + mt * 16 + aRowL) * 128 + kb + aKbL)));
            #pragma unroll
            for (int p = 0; p < 4; p++)
                ldsm_x4(bq[p], uBh + sw128((uint32_t)((nBase + p * 16 + bRowL) * 128 + kb + bKbL)));

            #pragma unroll
            for (int mt = 0; mt < 2; mt++)
                #pragma unroll
                for (int p = 0; p < 4; p++) {
                    mma16816(acc[mt][2 * p],     ah[mt], &bq[p][0]);
                    mma16816(acc[mt][2 * p + 1], ah[mt], &bq[p][2]);
                }
            #pragma unroll
            for (int mt = 0; mt < 2; mt++)
                #pragma unroll
                for (int p = 0; p < 4; p++) {
                    mma16816(acc[mt][2 * p],     al[mt], &bq[p][0]);
                    mma16816(acc[mt][2 * p + 1], al[mt], &bq[p][2]);
                }

            #pragma unroll
            for (int p = 0; p < 4; p++)
                ldsm_x4(bq[p], uBl + sw128((uint32_t)((nBase + p * 16 + bRowL) * 128 + kb + bKbL)));
            #pragma unroll
            for (int mt = 0; mt < 2; mt++)
                #pragma unroll
                for (int p = 0; p < 4; p++) {
                    mma16816(acc[mt][2 * p],     ah[mt], &bq[p][0]);
                    mma16816(acc[mt][2 * p + 1], ah[mt], &bq[p][2]);
                }

            if (ks == 0 && hasNext) convertHalf(buf ^ 1, 0);
            if (ks == 1 && hasNext) {
                convertHalf(buf ^ 1, 1);
                if (c + 2 < nChunks) prefetchA(c + 2);
            }
        }
    }

    const int rL = lane >> 2;
    const int cL = (lane & 3) * 2;

    if (lnG) {
        __syncthreads();
        float* ssum = (float*)sm;            // [128][2]
        float* ssq  = (float*)(sm + 1024);   // [128][2]
        const int half = warp >> 2;

        #pragma unroll
        for (int mt = 0; mt < 2; mt++)
            #pragma unroll
            for (int hr = 0; hr < 2; hr++) {
                int lr = mBase + mt * 16 + rL + hr * 8;
                float s = 0.f, q = 0.f;
                #pragma unroll
                for (int nt = 0; nt < 8; nt++)
                    #pragma unroll
                    for (int cc = 0; cc < 2; cc++) {
                        float v = acc[mt][nt][hr * 2 + cc] + bias[nBase + nt * 8 + cL + cc];
                        s += v; q += v * v;
                    }
                s += __shfl_xor_sync(0xffffffffu, s, 1);
                q += __shfl_xor_sync(0xffffffffu, q, 1);
                s += __shfl_xor_sync(0xffffffffu, s, 2);
                q += __shfl_xor_sync(0xffffffffu, q, 2);
                if ((lane & 3) == 0) { ssum[lr * 2 + half] = s; ssq[lr * 2 + half] = q; }
            }
        __syncthreads();

        #pragma unroll
        for (int mt = 0; mt < 2; mt++)
            #pragma unroll
            for (int hr = 0; hr < 2; hr++) {
                int lr  = mBase + mt * 16 + rL + hr * 8;
                int row = rowBase + lr;
                float s = ssum[lr * 2] + ssum[lr * 2 + 1];
                float q = ssq [lr * 2] + ssq [lr * 2 + 1];
                float mu  = s * (1.0f / 128.0f);
                float var = q * (1.0f / 128.0f) - mu * mu;
                float rst = rsqrtf(var + EPSV);
                if (row < NN) {
                    #pragma unroll
                    for (int nt = 0; nt < 8; nt++) {
                        int col = nBase + nt * 8 + cL;
                        float v0 = acc[mt][nt][hr * 2]     + bias[col];
                        float v1 = acc[mt][nt][hr * 2 + 1] + bias[col + 1];
                        v0 = fmaxf((v0 - mu) * rst * lnG[col]     + lnB[col],     0.f);
                        v1 = fmaxf((v1 - mu) * rst * lnG[col + 1] + lnB[col + 1], 0.f);
                        *(float2*)&C[(size_t)row * 128 + col] = make_float2(v0, v1);
                    }
                }
            }
        return;
    }

    #pragma unroll
    for (int mt = 0; mt < 2; mt++) {
        #pragma unroll
        for (int hr = 0; hr < 2; hr++) {
            int row = rowBase + mBase + mt * 16 + rL + hr * 8;
            if (row >= NN) continue;
            #pragma unroll
            for (int nt = 0; nt < 8; nt++) {
                int col = nBase + nt * 8 + cL;
                float v0 = acc[mt][nt][hr * 2];
                float v1 = acc[mt][nt][hr * 2 + 1];
                if (bias) { v0 += bias[col]; v1 += bias[col + 1]; }
                if (relu) { v0 = fmaxf(v0, 0.f); v1 = fmaxf(v1, 0.f); }
                if (C)  *(float2*)&C[(size_t)row * 128 + col] = make_float2(v0, v1);
                if (Ch) *(__half2*)&Ch[(size_t)row * 128 + col] = __floats2half2_rn(v0, v1);
            }
        }
    }
}

// ====== fused CSR SPMM (fp16 gather): out[d] = act(dinv^2*xw[d] + sum norm*xw[src] + b) ======
__global__ void __launch_bounds__(256)
k_spmm_csr(const float* __restrict__ bias, float* __restrict__ out, int relu)
{
    int w = (blockIdx.x * blockDim.x + threadIdx.x) >> 5;
    if (w >= NN) return;
    int lane = threadIdx.x & 31;
    int c = lane * 4;

    float di = g_dinv[w];
    float wt = di * di;
    float4 sv = ldh4(&g_xwh[(size_t)w * 128], c);
    float4 acc = make_float4(sv.x * wt, sv.y * wt, sv.z * wt, sv.w * wt);
    float4 acc2 = make_float4(0.f, 0.f, 0.f, 0.f);

    int start = g_rowptr[w];
    int end   = g_rowptr[w + 1];
    for (int base = start; base < end; base += 32) {
        int rem = end - base;
        int2 p = make_int2(0, 0);
        if (lane < rem) p = g_epack[base + lane];
        if (rem >= 32) {
            #pragma unroll
            for (int j = 0; j < 32; j += 2) {
                int   s0  = __shfl_sync(0xffffffffu, p.x, j);
                float nm0 = __int_as_float(__shfl_sync(0xffffffffu, p.y, j));
                int   s1  = __shfl_sync(0xffffffffu, p.x, j + 1);
                float nm1 = __int_as_float(__shfl_sync(0xffffffffu, p.y, j + 1));
                float4 v0 = ldh4(&g_xwh[(size_t)s0 * 128], c);
                float4 v1 = ldh4(&g_xwh[(size_t)s1 * 128], c);
                acc.x  = fmaf(nm0, v0.x, acc.x);
                acc.y  = fmaf(nm0, v0.y, acc.y);
                acc.z  = fmaf(nm0, v0.z, acc.z);
                acc.w  = fmaf(nm0, v0.w, acc.w);
                acc2.x = fmaf(nm1, v1.x, acc2.x);
                acc2.y = fmaf(nm1, v1.y, acc2.y);
                acc2.z = fmaf(nm1, v1.z, acc2.z);
                acc2.w = fmaf(nm1, v1.w, acc2.w);
            }
        } else {
            for (int j = 0; j < rem; j++) {
                int   s  = __shfl_sync(0xffffffffu, p.x, j);
                float nm = __int_as_float(__shfl_sync(0xffffffffu, p.y, j));
                float4 v = ldh4(&g_xwh[(size_t)s * 128], c);
                acc.x = fmaf(nm, v.x, acc.x);
                acc.y = fmaf(nm, v.y, acc.y);
                acc.z = fmaf(nm, v.z, acc.z);
                acc.w = fmaf(nm, v.w, acc.w);
            }
        }
    }
    acc.x += acc2.x; acc.y += acc2.y; acc.z += acc2.z; acc.w += acc2.w;

    float4 bb = *(const float4*)&bias[c];
    acc.x += bb.x; acc.y += bb.y; acc.z += bb.z; acc.w += bb.w;
    if (relu) {
        acc.x = fmaxf(acc.x, 0.f); acc.y = fmaxf(acc.y, 0.f);
        acc.z = fmaxf(acc.z, 0.f); acc.w = fmaxf(acc.w, 0.f);
    }
    *(float4*)&out[(size_t)w * 128 + c] = acc;
}

// ================= launch =================
extern "C" void kernel_launch(void* const* d_in, const int* in_sizes, int n_in,
                              void* d_out, int out_size)
{
    (void)in_sizes; (void)n_in; (void)out_size;
    const int*   ei    = (const int*)  d_in[0];
    const float* ext   = (const float*)d_in[1];
    const float* emb   = (const float*)d_in[2];
    const float* encW  = (const float*)d_in[3];
    const float* encB  = (const float*)d_in[4];
    const float* lng   = (const float*)d_in[5];
    const float* lnb   = (const float*)d_in[6];
    const float* projW = (const float*)d_in[7];
    const float* projB = (const float*)d_in[8];
    const float* W0    = (const float*)d_in[9];
    const float* b0    = (const float*)d_in[10];
    const float* W1    = (const float*)d_in[11];
    const float* b1    = (const float*)d_in[12];
    const float* W2    = (const float*)d_in[13];
    const float* b2    = (const float*)d_in[14];
    float* out = (float*)d_out;

    const int* src = ei;
    const int* dst = ei + EE;

    float *p_tmp, *p_x;
    __half* p_xwh;
    cudaGetSymbolAddress((void**)&p_tmp, g_tmp);
    cudaGetSymbolAddress((void**)&p_x,   g_x);
    cudaGetSymbolAddress((void**)&p_xwh, g_xwh);

    __nv_bfloat16 *bh_enc, *bl_enc, *bh_proj, *bl_proj, *bh_w0, *bl_w0, *bh_w1, *bl_w1, *bh_w2, *bl_w2;
    cudaGetSymbolAddress((void**)&bh_enc,  g_bh_enc);
    cudaGetSymbolAddress((void**)&bl_enc,  g_bl_enc);
    cudaGetSymbolAddress((void**)&bh_proj, g_bh_proj);
    cudaGetSymbolAddress((void**)&bl_proj, g_bl_proj);
    cudaGetSymbolAddress((void**)&bh_w0,   g_bh_w0);
    cudaGetSymbolAddress((void**)&bl_w0,   g_bl_w0);
    cudaGetSymbolAddress((void**)&bh_w1,   g_bh_w1);
    cudaGetSymbolAddress((void**)&bl_w1,   g_bl_w1);
    cudaGetSymbolAddress((void**)&bh_w2,   g_bh_w2);
    cudaGetSymbolAddress((void**)&bl_w2,   g_bl_w2);

    cudaFuncSetAttribute(k_gemm_mma, cudaFuncAttributeMaxDynamicSharedMemorySize, GEMM_DYN);

    static cudaStream_t sB = nullptr;
    static cudaEvent_t evF = nullptr, evJ = nullptr;
    if (!sB) {
        cudaStreamCreate(&sB);
        cudaEventCreateWithFlags(&evF, cudaEventDisableTiming);
        cudaEventCreateWithFlags(&evJ, cudaEventDisableTiming);
    }

    const int TB = 256;
    const int gN     = (NN + TB - 1) / TB;
    const int gE     = (EE + TB - 1) / TB;
    const int gRow   = (NN * 32 + TB - 1) / TB;
    const int gGemm  = (NN + 127) / 128;

    // ---- fork: CSR build on side stream ----
    cudaEventRecord(evF, 0);
    cudaStreamWaitEvent(sB, evF, 0);

    k_zero<<<gN, TB, 0, sB>>>();
    k_degree<<<gE, TB, 0, sB>>>(dst);
    k_scan1<<<SCAN_NB, SCAN_T, 0, sB>>>();
    k_scan2<<<1, 128, 0, sB>>>();
    k_scan3<<<gN, TB, 0, sB>>>();
    k_scatter<<<gE, TB, 0, sB>>>(src, dst);
    cudaEventRecord(evJ, sB);

    // main stream: splits + dense chain
    k_split_all<<<(SPLIT_TOT + TB - 1) / TB, TB>>>(encW, projW, W0, W1, W2);

    k_gemm_mma<<<gGemm, TB, GEMM_DYN>>>(ext, EXTD, ext, EXTD, EXTD, EXTD,
                                        bh_enc, bl_enc, encB, 0, lng, lnb, p_tmp, nullptr);

    k_gemm_mma<<<gGemm, TB, GEMM_DYN>>>(emb, HH, p_tmp, HH, HH, 2 * HH,
                                        bh_proj, bl_proj, projB, 0, nullptr, nullptr, p_x, nullptr);

    k_gemm_mma<<<gGemm, TB, GEMM_DYN>>>(p_x, HH, p_x, HH, HH, HH,
                                        bh_w0, bl_w0, nullptr, 0, nullptr, nullptr, nullptr, p_xwh);

    // ---- join: SPMM needs the CSR ----
    cudaStreamWaitEvent(0, evJ, 0);

    k_spmm_csr<<<gRow, TB>>>(b0, p_x, 1);

    k_gemm_mma<<<gGemm, TB, GEMM_DYN>>>(p_x, HH, p_x, HH, HH, HH,
                                        bh_w1, bl_w1, nullptr, 0, nullptr, nullptr, nullptr, p_xwh);
    k_spmm_csr<<<gRow, TB>>>(b1, p_x, 1);

    k_gemm_mma<<<gGemm, TB, GEMM_DYN>>>(p_x, HH, p_x, HH, HH, HH,
                                        bh_w2, bl_w2, nullptr, 0, nullptr, nullptr, nullptr, p_xwh);
    k_spmm_csr<<<gRow, TB>>>(b2, out, 0);
}

// round 10
// speedup vs baseline: 3.8321x; 1.0149x over previous
#include <cuda_runtime.h>
#include <cuda_bf16.h>
#include <cuda_fp16.h>
#include <cstdint>

// Problem constants
#define NN   100000
#define HH   128
#define EE   1600000
#define EXTD 768
#define EPSV 1e-5f

// ================= device scratch (no allocations allowed) =================
__device__ float g_dinv[NN];
__device__ int   g_degi[NN];
__device__ int   g_cursor[NN];
__device__ int   g_rowptr[NN + 1];
__device__ int   g_bsum[128];
__device__ int   g_bsumx[128];
__device__ int2  g_epack[EE];          // (src, norm-bits) sorted by dst
__device__ float g_tmp [NN * HH];      // encoder LN+ReLU output
__device__ float g_x   [NN * HH];
__device__ __half g_xwh[NN * HH];      // layer GEMM output, fp16 (SPMM gather source)

// encoder weights: transposed fp32 [128][768] (tf32 path reads raw fp32)
__device__ float g_bt_enc[128 * 768];
// split-bf16 transposed weights for remaining GEMMs: [N=128 rows][K cols]
__device__ __nv_bfloat16 g_bh_proj[128 * 256];
__device__ __nv_bfloat16 g_bl_proj[128 * 256];
__device__ __nv_bfloat16 g_bh_w0  [128 * 128];
__device__ __nv_bfloat16 g_bl_w0  [128 * 128];
__device__ __nv_bfloat16 g_bh_w1  [128 * 128];
__device__ __nv_bfloat16 g_bl_w1  [128 * 128];
__device__ __nv_bfloat16 g_bh_w2  [128 * 128];
__device__ __nv_bfloat16 g_bl_w2  [128 * 128];

// ================= helpers =================
__device__ __forceinline__ uint32_t smem_u32(const void* p) {
    uint32_t a;
    asm("{ .reg .u64 t; cvta.to.shared.u64 t, %1; cvt.u32.u64 %0, t; }" : "=r"(a) : "l"(p));
    return a;
}
__device__ __forceinline__ uint32_t sw128(uint32_t o) { return o ^ ((o >> 3) & 0x70); }

__device__ __forceinline__ void ldsm_x4(uint32_t* r, uint32_t addr) {
    asm volatile("ldmatrix.sync.aligned.m8n8.x4.shared.b16 {%0,%1,%2,%3}, [%4];"
        : "=r"(r[0]), "=r"(r[1]), "=r"(r[2]), "=r"(r[3]) : "r"(addr));
}
__device__ __forceinline__ void mma16816(float* c, const uint32_t* a, const uint32_t* b) {
    asm volatile(
        "mma.sync.aligned.m16n8k16.row.col.f32.bf16.bf16.f32 "
        "{%0,%1,%2,%3}, {%4,%5,%6,%7}, {%8,%9}, {%0,%1,%2,%3};"
        : "+f"(c[0]), "+f"(c[1]), "+f"(c[2]), "+f"(c[3])
        : "r"(a[0]), "r"(a[1]), "r"(a[2]), "r"(a[3]), "r"(b[0]), "r"(b[1]));
}
__device__ __forceinline__ void mma1688_tf32(float* c, const uint32_t* a, const uint32_t* b) {
    asm volatile(
        "mma.sync.aligned.m16n8k8.row.col.f32.tf32.tf32.f32 "
        "{%0,%1,%2,%3}, {%4,%5,%6,%7}, {%8,%9}, {%0,%1,%2,%3};"
        : "+f"(c[0]), "+f"(c[1]), "+f"(c[2]), "+f"(c[3])
        : "r"(a[0]), "r"(a[1]), "r"(a[2]), "r"(a[3]), "r"(b[0]), "r"(b[1]));
}
__device__ __forceinline__ uint32_t f2tf32(float x) {
    uint32_t u;
    asm("cvt.rna.tf32.f32 %0, %1;" : "=r"(u) : "f"(x));
    return u;
}
#define CP_ASYNC16(smem, gptr) \
    asm volatile("cp.async.cg.shared.global [%0], [%1], 16;" :: "r"(smem), "l"(gptr))

__device__ __forceinline__ uint32_t packbf2(float a, float b, float* ra, float* rb) {
    __nv_bfloat16 ha = __float2bfloat16_rn(a), hb = __float2bfloat16_rn(b);
    if (ra) { *ra = a - __bfloat162float(ha); *rb = b - __bfloat162float(hb); }
    return (uint32_t)__bfloat16_as_ushort(ha) | ((uint32_t)__bfloat16_as_ushort(hb) << 16);
}

// load 4 fp16 (8B) from a row and widen to float4
__device__ __forceinline__ float4 ldh4(const __half* p, int c) {
    uint2 u = *(const uint2*)(p + c);
    __half2 h0 = *reinterpret_cast<__half2*>(&u.x);
    __half2 h1 = *reinterpret_cast<__half2*>(&u.y);
    float2 a = __half22float2(h0);
    float2 b = __half22float2(h1);
    return make_float4(a.x, a.y, b.x, b.y);
}

// ================= graph prep: CSR build =================
__global__ void k_zero() {
    int i = blockIdx.x * blockDim.x + threadIdx.x;
    if (i < NN) { g_degi[i] = 0; g_cursor[i] = 0; }
}
__global__ void k_degree(const int* __restrict__ dst) {
    int e = blockIdx.x * blockDim.x + threadIdx.x;
    if (e < EE) atomicAdd(&g_degi[dst[e]], 1);
}

#define SCAN_T 256
#define SCAN_NB ((NN + SCAN_T * 4 - 1) / (SCAN_T * 4))   // 98
__global__ void __launch_bounds__(SCAN_T) k_scan1() {
    __shared__ int s[SCAN_T];
    int t = threadIdx.x;
    int base = blockIdx.x * SCAN_T * 4 + t * 4;
    int v[4];
    #pragma unroll
    for (int j = 0; j < 4; j++) {
        v[j] = (base + j < NN) ? g_degi[base + j] : 0;
        if (base + j < NN) g_dinv[base + j] = rsqrtf((float)(v[j] + 1));  // +1 self-loop
    }
    int tsum = v[0] + v[1] + v[2] + v[3];
    s[t] = tsum; __syncthreads();
    #pragma unroll
    for (int off = 1; off < SCAN_T; off <<= 1) {
        int x = (t >= off) ? s[t - off] : 0;
        __syncthreads();
        s[t] += x;
        __syncthreads();
    }
    int run = s[t] - tsum;
    #pragma unroll
    for (int j = 0; j < 4; j++) {
        if (base + j < NN) g_rowptr[base + j] = run;
        run += v[j];
    }
    if (t == SCAN_T - 1) g_bsum[blockIdx.x] = s[SCAN_T - 1];
}
__global__ void __launch_bounds__(128) k_scan2() {
    __shared__ int s[128];
    int t = threadIdx.x;
    int v = (t < SCAN_NB) ? g_bsum[t] : 0;
    s[t] = v; __syncthreads();
    #pragma unroll
    for (int off = 1; off < 128; off <<= 1) {
        int x = (t >= off) ? s[t - off] : 0;
        __syncthreads();
        s[t] += x;
        __syncthreads();
    }
    if (t < SCAN_NB) g_bsumx[t] = s[t] - v;
}
__global__ void k_scan3() {
    int i = blockIdx.x * blockDim.x + threadIdx.x;
    if (i < NN) g_rowptr[i] += g_bsumx[i / (SCAN_T * 4)];
    if (i == 0) g_rowptr[NN] = EE;
}
__global__ void k_scatter(const int* __restrict__ src, const int* __restrict__ dst) {
    int e = blockIdx.x * blockDim.x + threadIdx.x;
    if (e >= EE) return;
    int d = dst[e];
    int s = src[e];
    int pos = g_rowptr[d] + atomicAdd(&g_cursor[d], 1);
    float nm = g_dinv[s] * g_dinv[d];
    g_epack[pos] = make_int2(s, __float_as_int(nm));
}

// ============ weight prep: enc transpose (fp32) + bf16 splits for the rest ============
#define SPLIT_TOT (768*128 + 256*128 + 3*128*128)
__global__ void k_split_all(const float* __restrict__ encW, const float* __restrict__ projW,
                            const float* __restrict__ W0, const float* __restrict__ W1,
                            const float* __restrict__ W2) {
    int idx = blockIdx.x * blockDim.x + threadIdx.x;
    if (idx >= SPLIT_TOT) return;
    int local = idx;
    if (local < 768*128) {
        int k = local >> 7, n = local & 127;
        g_bt_enc[n * 768 + k] = encW[local];     // transposed fp32 (tf32 path)
        return;
    }
    local -= 768*128;
    const float* W; __nv_bfloat16 *Bh, *Bl; int K;
    if (local < 256*128)                   { W = projW; Bh = g_bh_proj; Bl = g_bl_proj; K = 256; }
    else if ((local -= 256*128) < 128*128) { W = W0;    Bh = g_bh_w0;   Bl = g_bl_w0;   K = 128; }
    else if ((local -= 128*128) < 128*128) { W = W1;    Bh = g_bh_w1;   Bl = g_bl_w1;   K = 128; }
    else  { local -= 128*128;                W = W2;    Bh = g_bh_w2;   Bl = g_bl_w2;   K = 128; }
    int k = local >> 7;
    int n = local & 127;
    float w = W[local];
    __nv_bfloat16 h = __float2bfloat16_rn(w);
    float r = w - __bfloat162float(h);
    Bh[n * K + k] = h;
    Bl[n * K + k] = __float2bfloat16_rn(r);
}

// ============ tf32 GEMM (encoder): C = LN(relu? no: LN+ReLU fused) of A[M,768] @ W ============
// chunk = k32 (128B rows), A and B double-buffered, 256 threads, 8 warps 32x64.
#define TILE32 16384      // 128 rows x 32 tf32 x 4B
#define DYN32  (4 * TILE32 + 1024)

__global__ void __launch_bounds__(256, 1)
k_gemm_tf32(const float* __restrict__ A, int K,
            const float* __restrict__ Bt,     // [128][K] fp32 transposed
            const float* __restrict__ bias,
            const float* __restrict__ lnG, const float* __restrict__ lnB,
            float* __restrict__ C)
{
    extern __shared__ char dyn[];
    const int tid = threadIdx.x;
    const int rowBase = blockIdx.x * 128;

    uint32_t dynb = smem_u32(dyn);
    char* sm = dyn + (((dynb + 1023u) & ~1023u) - dynb);
    const uint32_t uA0 = smem_u32(sm);                 // A buf0, buf1
    const uint32_t uB0 = smem_u32(sm + 2 * TILE32);    // B buf0, buf1

    const int lane = tid & 31;
    const int warp = tid >> 5;
    const int mBase = (warp & 3) * 32;
    const int nBase = (warp >> 2) * 64;

    // identical lane mappings to the (verified) bf16 kernel; rows are 128B
    const int aRowL = (lane & 7) + ((lane & 8) ? 8 : 0);
    const int aKbL  = (lane & 16) ? 16 : 0;
    const int bRowL = (lane & 7) + ((lane & 16) ? 8 : 0);
    const int bKbL  = (lane & 8) ? 16 : 0;

    float acc[2][8][4];
    #pragma unroll
    for (int mt = 0; mt < 2; mt++)
        #pragma unroll
        for (int nt = 0; nt < 8; nt++)
            #pragma unroll
            for (int j = 0; j < 4; j++) acc[mt][nt][j] = 0.0f;

    const int nChunks = K >> 5;          // k32 chunks
    const int aRow = tid >> 1;           // 0..127
    const int aCol = (tid & 1) * 16;     // 2 threads per 32-col row
    const int gr   = rowBase + aRow;
    float4 aF[4];

    auto prefetchA = [&](int c) {
        int k0 = c * 32;
        #pragma unroll
        for (int i = 0; i < 4; i++) {
            aF[i] = make_float4(0.f, 0.f, 0.f, 0.f);
            if (gr < NN) aF[i] = *(const float4*)(A + (size_t)gr * K + k0 + aCol + i * 4);
        }
    };
    auto convertHalf = [&](int buf, int half) {
        char* d = sm + buf * TILE32;
        #pragma unroll
        for (int i = half * 2; i < half * 2 + 2; i++) {
            uint4 u = make_uint4(f2tf32(aF[i].x), f2tf32(aF[i].y),
                                 f2tf32(aF[i].z), f2tf32(aF[i].w));
            *(uint4*)(d + sw128((uint32_t)(aRow * 128 + (aCol + i * 4) * 4))) = u;
        }
    };
    auto issueB = [&](int c, int buf) {
        int k0 = c * 32;
        uint32_t dst = uB0 + (uint32_t)buf * TILE32;
        #pragma unroll
        for (int i = 0; i < 4; i++) {
            int idx = i * 256 + tid;     // 0..1023 16B units
            int n   = idx >> 3;          // 0..127
            int kq  = idx & 7;           // 16B unit in 128B row
            CP_ASYNC16(dst + sw128((uint32_t)(n * 128 + kq * 16)),
                       (const char*)(Bt + (size_t)n * K + k0 + kq * 4));
        }
        asm volatile("cp.async.commit_group;" ::: "memory");
    };

    prefetchA(0);
    issueB(0, 0);
    convertHalf(0, 0);
    convertHalf(0, 1);
    if (nChunks > 1) prefetchA(1);

    for (int c = 0; c < nChunks; c++) {
        const int buf = c & 1;
        const bool hasNext = (c + 1 < nChunks);

        asm volatile("cp.async.wait_group 0;" ::: "memory");
        __syncthreads();

        if (hasNext) issueB(c + 1, buf ^ 1);

        const uint32_t uA = uA0 + (uint32_t)buf * TILE32;
        const uint32_t uB = uB0 + (uint32_t)buf * TILE32;

        #pragma unroll
        for (int ks = 0; ks < 4; ks++) {
            const int kb = ks * 32;      // 8 tf32 = 32 bytes per step
            uint32_t af[2][4], bq[4][4];

            #pragma unroll
            for (int mt = 0; mt < 2; mt++)
                ldsm_x4(af[mt], uA + sw128((uint32_t)((mBase + mt * 16 + aRowL) * 128 + kb + aKbL)));
            #pragma unroll
            for (int p = 0; p < 4; p++)
                ldsm_x4(bq[p], uB + sw128((uint32_t)((nBase + p * 16 + bRowL) * 128 + kb + bKbL)));

            #pragma unroll
            for (int mt = 0; mt < 2; mt++)
                #pragma unroll
                for (int p = 0; p < 4; p++) {
                    mma1688_tf32(acc[mt][2 * p],     af[mt], &bq[p][0]);
                    mma1688_tf32(acc[mt][2 * p + 1], af[mt], &bq[p][2]);
                }

            if (ks == 0 && hasNext) convertHalf(buf ^ 1, 0);
            if (ks == 1 && hasNext) {
                convertHalf(buf ^ 1, 1);
                if (c + 2 < nChunks) prefetchA(c + 2);
            }
        }
    }

    // ---- fused LayerNorm + ReLU epilogue (bias pre-LN) ----
    const int rL = lane >> 2;
    const int cL = (lane & 3) * 2;
    __syncthreads();
    float* ssum = (float*)sm;            // [128][2]
    float* ssq  = (float*)(sm + 1024);   // [128][2]
    const int half = warp >> 2;

    #pragma unroll
    for (int mt = 0; mt < 2; mt++)
        #pragma unroll
        for (int hr = 0; hr < 2; hr++) {
            int lr = mBase + mt * 16 + rL + hr * 8;
            float s = 0.f, q = 0.f;
            #pragma unroll
            for (int nt = 0; nt < 8; nt++)
                #pragma unroll
                for (int cc = 0; cc < 2; cc++) {
                    float v = acc[mt][nt][hr * 2 + cc] + bias[nBase + nt * 8 + cL + cc];
                    s += v; q += v * v;
                }
            s += __shfl_xor_sync(0xffffffffu, s, 1);
            q += __shfl_xor_sync(0xffffffffu, q, 1);
            s += __shfl_xor_sync(0xffffffffu, s, 2);
            q += __shfl_xor_sync(0xffffffffu, q, 2);
            if ((lane & 3) == 0) { ssum[lr * 2 + half] = s; ssq[lr * 2 + half] = q; }
        }
    __syncthreads();

    #pragma unroll
    for (int mt = 0; mt < 2; mt++)
        #pragma unroll
        for (int hr = 0; hr < 2; hr++) {
            int lr  = mBase + mt * 16 + rL + hr * 8;
            int row = rowBase + lr;
            float s = ssum[lr * 2] + ssum[lr * 2 + 1];
            float q = ssq [lr * 2] + ssq [lr * 2 + 1];
            float mu  = s * (1.0f / 128.0f);
            float var = q * (1.0f / 128.0f) - mu * mu;
            float rst = rsqrtf(var + EPSV);
            if (row < NN) {
                #pragma unroll
                for (int nt = 0; nt < 8; nt++) {
                    int col = nBase + nt * 8 + cL;
                    float v0 = acc[mt][nt][hr * 2]     + bias[col];
                    float v1 = acc[mt][nt][hr * 2 + 1] + bias[col + 1];
                    v0 = fmaxf((v0 - mu) * rst * lnG[col]     + lnB[col],     0.f);
                    v1 = fmaxf((v1 - mu) * rst * lnG[col + 1] + lnB[col + 1], 0.f);
                    *(float2*)&C[(size_t)row * 128 + col] = make_float2(v0, v1);
                }
            }
        }
}

// ============ pipelined mma.sync split-bf16 GEMM: C[M,128] = [Aa|Ab] @ W[K,128] ============
#define TILE_B 16384
#define GEMM_DYN (8 * TILE_B + 1024)

__global__ void __launch_bounds__(256, 1)
k_gemm_mma(const float* __restrict__ Aa, int strideA,
           const float* __restrict__ Ab, int strideB, int kSplit, int K,
           const __nv_bfloat16* __restrict__ Bh, const __nv_bfloat16* __restrict__ Bl,
           const float* __restrict__ bias, int relu,
           float* __restrict__ C, __half* __restrict__ Ch)
{
    extern __shared__ char dyn[];
    const int tid = threadIdx.x;
    const int rowBase = blockIdx.x * 128;

    uint32_t dynb = smem_u32(dyn);
    char* sm = dyn + (((dynb + 1023u) & ~1023u) - dynb);
    const uint32_t uA0 = smem_u32(sm);
    const uint32_t uB0 = smem_u32(sm + 4 * TILE_B);

    const int lane = tid & 31;
    const int warp = tid >> 5;
    const int mBase = (warp & 3) * 32;
    const int nBase = (warp >> 2) * 64;

    const int aRowL = (lane & 7) + ((lane & 8) ? 8 : 0);
    const int aKbL  = (lane & 16) ? 16 : 0;
    const int bRowL = (lane & 7) + ((lane & 16) ? 8 : 0);
    const int bKbL  = (lane & 8) ? 16 : 0;

    float acc[2][8][4];
    #pragma unroll
    for (int mt = 0; mt < 2; mt++)
        #pragma unroll
        for (int nt = 0; nt < 8; nt++)
            #pragma unroll
            for (int j = 0; j < 4; j++) acc[mt][nt][j] = 0.0f;

    const int nChunks = K >> 6;
    float4 aF[8];

    auto prefetchA = [&](int c) {
        int k0 = c * 64;
        const float* base; int stride; int koff;
        if (k0 < kSplit) { base = Aa; stride = strideA; koff = k0; }
        else             { base = Ab; stride = strideB; koff = k0 - kSplit; }
        #pragma unroll
        for (int i = 0; i < 8; i++) {
            int fidx = i * 256 + tid;
            int r    = fidx >> 4;
            int kq   = fidx & 15;
            int gr   = rowBase + r;
            aF[i] = make_float4(0.f, 0.f, 0.f, 0.f);
            if (gr < NN) aF[i] = *(const float4*)(base + (size_t)gr * stride + koff + kq * 4);
        }
    };

    auto convertHalf = [&](int buf, int half) {
        char* dh = sm + buf * (2 * TILE_B);
        char* dl = dh + TILE_B;
        #pragma unroll
        for (int i = half * 4; i < half * 4 + 4; i++) {
            int fidx = i * 256 + tid;
            int r    = fidx >> 4;
            int kq   = fidx & 15;
            float r0, r1, r2, r3;
            uint32_t h0 = packbf2(aF[i].x, aF[i].y, &r0, &r1);
            uint32_t h1 = packbf2(aF[i].z, aF[i].w, &r2, &r3);
            uint32_t l0 = packbf2(r0, r1, nullptr, nullptr);
            uint32_t l1 = packbf2(r2, r3, nullptr, nullptr);
            uint32_t off = sw128((uint32_t)(r * 128 + kq * 8));
            *(uint2*)(dh + off) = make_uint2(h0, h1);
            *(uint2*)(dl + off) = make_uint2(l0, l1);
        }
    };

    auto issueB = [&](int c, int buf) {
        int k0 = c * 64;
        uint32_t dst = uB0 + (uint32_t)buf * (2 * TILE_B);
        #pragma unroll
        for (int i = 0; i < 4; i++) {
            int uidx = i * 256 + tid;
            int n    = uidx >> 3;
            int kq   = uidx & 7;
            uint32_t off = sw128((uint32_t)(n * 128 + kq * 16));
            CP_ASYNC16(dst + off,          (const char*)(Bh + (size_t)n * K + k0 + kq * 8));
            CP_ASYNC16(dst + TILE_B + off, (const char*)(Bl + (size_t)n * K + k0 + kq * 8));
        }
        asm volatile("cp.async.commit_group;" ::: "memory");
    };

    prefetchA(0);
    issueB(0, 0);
    convertHalf(0, 0);
    convertHalf(0, 1);
    if (nChunks > 1) prefetchA(1);

    for (int c = 0; c < nChunks; c++) {
        const int buf  = c & 1;
        const bool hasNext = (c + 1 < nChunks);

        asm volatile("cp.async.wait_group 0;" ::: "memory");
        __syncthreads();

        if (hasNext) issueB(c + 1, buf ^ 1);

        const uint32_t uAh = uA0 + (uint32_t)buf * (2 * TILE_B);
        const uint32_t uAl = uAh + TILE_B;
        const uint32_t uBh = uB0 + (uint32_t)buf * (2 * TILE_B);
        const uint32_t uBl = uBh + TILE_B;

        #pragma unroll
        for (int ks = 0; ks < 4; ks++) {
            const int kb = ks * 32;
            uint32_t ah[2][4], al[2][4], bq[4][4];

            #pragma unroll
            for (int mt = 0; mt < 2; mt++)
                ldsm_x4(ah[mt], uAh + sw128((uint32_t)((mBase + mt * 16 + aRowL) * 128 + kb + aKbL)));
            #pragma unroll
            for (int mt = 0; mt < 2; mt++)
                ldsm_x4(al[mt], uAl + sw128((uint32_t)((mBase + mt * 16 + aRowL) * 128 + kb + aKbL)));
            #pragma unroll
            for (int p = 0; p < 4; p++)
                ldsm_x4(bq[p], uBh + sw128((uint32_t)((nBase + p * 16 + bRowL) * 128 + kb + bKbL)));

            #pragma unroll
            for (int mt = 0; mt < 2; mt++)
                #pragma unroll
                for (int p = 0; p < 4; p++) {
                    mma16816(acc[mt][2 * p],     ah[mt], &bq[p][0]);
                    mma16816(acc[mt][2 * p + 1], ah[mt], &bq[p][2]);
                }
            #pragma unroll
            for (int mt = 0; mt < 2; mt++)
                #pragma unroll
                for (int p = 0; p < 4; p++) {
                    mma16816(acc[mt][2 * p],     al[mt], &bq[p][0]);
                    mma16816(acc[mt][2 * p + 1], al[mt], &bq[p][2]);
                }

            #pragma unroll
            for (int p = 0; p < 4; p++)
                ldsm_x4(bq[p], uBl + sw128((uint32_t)((nBase + p * 16 + bRowL) * 128 + kb + bKbL)));
            #pragma unroll
            for (int mt = 0; mt < 2; mt++)
                #pragma unroll
                for (int p = 0; p < 4; p++) {
                    mma16816(acc[mt][2 * p],     ah[mt], &bq[p][0]);
                    mma16816(acc[mt][2 * p + 1], ah[mt], &bq[p][2]);
                }

            if (ks == 0 && hasNext) convertHalf(buf ^ 1, 0);
            if (ks == 1 && hasNext) {
                convertHalf(buf ^ 1, 1);
                if (c + 2 < nChunks) prefetchA(c + 2);
            }
        }
    }

    const int rL = lane >> 2;
    const int cL = (lane & 3) * 2;

    #pragma unroll
    for (int mt = 0; mt < 2; mt++) {
        #pragma unroll
        for (int hr = 0; hr < 2; hr++) {
            int row = rowBase + mBase + mt * 16 + rL + hr * 8;
            if (row >= NN) continue;
            #pragma unroll
            for (int nt = 0; nt < 8; nt++) {
                int col = nBase + nt * 8 + cL;
                float v0 = acc[mt][nt][hr * 2];
                float v1 = acc[mt][nt][hr * 2 + 1];
                if (bias) { v0 += bias[col]; v1 += bias[col + 1]; }
                if (relu) { v0 = fmaxf(v0, 0.f); v1 = fmaxf(v1, 0.f); }
                if (C)  *(float2*)&C[(size_t)row * 128 + col] = make_float2(v0, v1);
                if (Ch) *(__half2*)&Ch[(size_t)row * 128 + col] = __floats2half2_rn(v0, v1);
            }
        }
    }
}

// ====== fused CSR SPMM (fp16 gather): out[d] = act(dinv^2*xw[d] + sum norm*xw[src] + b) ======
__global__ void __launch_bounds__(256)
k_spmm_csr(const float* __restrict__ bias, float* __restrict__ out, int relu)
{
    int w = (blockIdx.x * blockDim.x + threadIdx.x) >> 5;
    if (w >= NN) return;
    int lane = threadIdx.x & 31;
    int c = lane * 4;

    float di = g_dinv[w];
    float wt = di * di;
    float4 sv = ldh4(&g_xwh[(size_t)w * 128], c);
    float4 acc = make_float4(sv.x * wt, sv.y * wt, sv.z * wt, sv.w * wt);
    float4 acc2 = make_float4(0.f, 0.f, 0.f, 0.f);

    int start = g_rowptr[w];
    int end   = g_rowptr[w + 1];
    for (int base = start; base < end; base += 32) {
        int rem = end - base;
        int2 p = make_int2(0, 0);
        if (lane < rem) p = g_epack[base + lane];
        if (rem >= 32) {
            #pragma unroll
            for (int j = 0; j < 32; j += 2) {
                int   s0  = __shfl_sync(0xffffffffu, p.x, j);
                float nm0 = __int_as_float(__shfl_sync(0xffffffffu, p.y, j));
                int   s1  = __shfl_sync(0xffffffffu, p.x, j + 1);
                float nm1 = __int_as_float(__shfl_sync(0xffffffffu, p.y, j + 1));
                float4 v0 = ldh4(&g_xwh[(size_t)s0 * 128], c);
                float4 v1 = ldh4(&g_xwh[(size_t)s1 * 128], c);
                acc.x  = fmaf(nm0, v0.x, acc.x);
                acc.y  = fmaf(nm0, v0.y, acc.y);
                acc.z  = fmaf(nm0, v0.z, acc.z);
                acc.w  = fmaf(nm0, v0.w, acc.w);
                acc2.x = fmaf(nm1, v1.x, acc2.x);
                acc2.y = fmaf(nm1, v1.y, acc2.y);
                acc2.z = fmaf(nm1, v1.z, acc2.z);
                acc2.w = fmaf(nm1, v1.w, acc2.w);
            }
        } else {
            for (int j = 0; j < rem; j++) {
                int   s  = __shfl_sync(0xffffffffu, p.x, j);
                float nm = __int_as_float(__shfl_sync(0xffffffffu, p.y, j));
                float4 v = ldh4(&g_xwh[(size_t)s * 128], c);
                acc.x = fmaf(nm, v.x, acc.x);
                acc.y = fmaf(nm, v.y, acc.y);
                acc.z = fmaf(nm, v.z, acc.z);
                acc.w = fmaf(nm, v.w, acc.w);
            }
        }
    }
    acc.x += acc2.x; acc.y += acc2.y; acc.z += acc2.z; acc.w += acc2.w;

    float4 bb = *(const float4*)&bias[c];
    acc.x += bb.x; acc.y += bb.y; acc.z += bb.z; acc.w += bb.w;
    if (relu) {
        acc.x = fmaxf(acc.x, 0.f); acc.y = fmaxf(acc.y, 0.f);
        acc.z = fmaxf(acc.z, 0.f); acc.w = fmaxf(acc.w, 0.f);
    }
    *(float4*)&out[(size_t)w * 128 + c] = acc;
}

// ================= launch =================
extern "C" void kernel_launch(void* const* d_in, const int* in_sizes, int n_in,
                              void* d_out, int out_size)
{
    (void)in_sizes; (void)n_in; (void)out_size;
    const int*   ei    = (const int*)  d_in[0];
    const float* ext   = (const float*)d_in[1];
    const float* emb   = (const float*)d_in[2];
    const float* encW  = (const float*)d_in[3];
    const float* encB  = (const float*)d_in[4];
    const float* lng   = (const float*)d_in[5];
    const float* lnb   = (const float*)d_in[6];
    const float* projW = (const float*)d_in[7];
    const float* projB = (const float*)d_in[8];
    const float* W0    = (const float*)d_in[9];
    const float* b0    = (const float*)d_in[10];
    const float* W1    = (const float*)d_in[11];
    const float* b1    = (const float*)d_in[12];
    const float* W2    = (const float*)d_in[13];
    const float* b2    = (const float*)d_in[14];
    float* out = (float*)d_out;

    const int* src = ei;
    const int* dst = ei + EE;

    float *p_tmp, *p_x, *p_bt;
    __half* p_xwh;
    cudaGetSymbolAddress((void**)&p_tmp, g_tmp);
    cudaGetSymbolAddress((void**)&p_x,   g_x);
    cudaGetSymbolAddress((void**)&p_xwh, g_xwh);
    cudaGetSymbolAddress((void**)&p_bt,  g_bt_enc);

    __nv_bfloat16 *bh_proj, *bl_proj, *bh_w0, *bl_w0, *bh_w1, *bl_w1, *bh_w2, *bl_w2;
    cudaGetSymbolAddress((void**)&bh_proj, g_bh_proj);
    cudaGetSymbolAddress((void**)&bl_proj, g_bl_proj);
    cudaGetSymbolAddress((void**)&bh_w0,   g_bh_w0);
    cudaGetSymbolAddress((void**)&bl_w0,   g_bl_w0);
    cudaGetSymbolAddress((void**)&bh_w1,   g_bh_w1);
    cudaGetSymbolAddress((void**)&bl_w1,   g_bl_w1);
    cudaGetSymbolAddress((void**)&bh_w2,   g_bh_w2);
    cudaGetSymbolAddress((void**)&bl_w2,   g_bl_w2);

    cudaFuncSetAttribute(k_gemm_mma,  cudaFuncAttributeMaxDynamicSharedMemorySize, GEMM_DYN);
    cudaFuncSetAttribute(k_gemm_tf32, cudaFuncAttributeMaxDynamicSharedMemorySize, DYN32);

    static cudaStream_t sB = nullptr;
    static cudaEvent_t evF = nullptr, evJ = nullptr;
    if (!sB) {
        cudaStreamCreate(&sB);
        cudaEventCreateWithFlags(&evF, cudaEventDisableTiming);
        cudaEventCreateWithFlags(&evJ, cudaEventDisableTiming);
    }

    const int TB = 256;
    const int gN     = (NN + TB - 1) / TB;
    const int gE     = (EE + TB - 1) / TB;
    const int gRow   = (NN * 32 + TB - 1) / TB;
    const int gGemm  = (NN + 127) / 128;

    // ---- fork: CSR build on side stream ----
    cudaEventRecord(evF, 0);
    cudaStreamWaitEvent(sB, evF, 0);

    k_zero<<<gN, TB, 0, sB>>>();
    k_degree<<<gE, TB, 0, sB>>>(dst);
    k_scan1<<<SCAN_NB, SCAN_T, 0, sB>>>();
    k_scan2<<<1, 128, 0, sB>>>();
    k_scan3<<<gN, TB, 0, sB>>>();
    k_scatter<<<gE, TB, 0, sB>>>(src, dst);
    cudaEventRecord(evJ, sB);

    // main stream: weight prep + dense chain
    k_split_all<<<(SPLIT_TOT + TB - 1) / TB, TB>>>(encW, projW, W0, W1, W2);

    // encoder GEMM (tf32 single-pass) with fused LN+ReLU
    k_gemm_tf32<<<gGemm, TB, DYN32>>>(ext, EXTD, p_bt, encB, lng, lnb, p_tmp);

    // projection: A = [emb | feat] read directly by k-range (split-bf16)
    k_gemm_mma<<<gGemm, TB, GEMM_DYN>>>(emb, HH, p_tmp, HH, HH, 2 * HH,
                                        bh_proj, bl_proj, projB, 0, p_x, nullptr);

    k_gemm_mma<<<gGemm, TB, GEMM_DYN>>>(p_x, HH, p_x, HH, HH, HH,
                                        bh_w0, bl_w0, nullptr, 0, nullptr, p_xwh);

    // ---- join: SPMM needs the CSR ----
    cudaStreamWaitEvent(0, evJ, 0);

    k_spmm_csr<<<gRow, TB>>>(b0, p_x, 1);

    k_gemm_mma<<<gGemm, TB, GEMM_DYN>>>(p_x, HH, p_x, HH, HH, HH,
                                        bh_w1, bl_w1, nullptr, 0, nullptr, p_xwh);
    k_spmm_csr<<<gRow, TB>>>(b1, p_x, 1);

    k_gemm_mma<<<gGemm, TB, GEMM_DYN>>>(p_x, HH, p_x, HH, HH, HH,
                                        bh_w2, bl_w2, nullptr, 0, nullptr, p_xwh);
    k_spmm_csr<<<gRow, TB>>>(b2, out, 0);
}

// round 14
// speedup vs baseline: 3.9275x; 1.0249x over previous
#include <cuda_runtime.h>
#include <cuda_bf16.h>
#include <cuda_fp16.h>
#include <cstdint>

// Problem constants
#define NN   100000
#define HH   128
#define EE   1600000
#define EXTD 768
#define EPSV 1e-5f

// ================= device scratch (no allocations allowed) =================
__device__ float g_dinv[NN];
__device__ int   g_degi[NN];
__device__ int   g_cursor[NN];
__device__ int   g_rowptr[NN + 1];
__device__ int   g_bsum[128];
__device__ int   g_bsumx[128];
__device__ int2  g_epack[EE];          // (src, norm-bits) sorted by dst
__device__ float g_tmp [NN * HH];      // encoder LN+ReLU output (fp32)
__device__ __half g_xh [NN * HH];      // intermediate x, fp16 (GEMM-A source)
__device__ __half g_xwh[NN * HH];      // layer GEMM output, fp16 (SPMM gather source)

// encoder weights: transposed fp32 [128][768] (tf32 path)
__device__ float g_bt_enc[128 * 768];
// split-bf16 transposed weights: [N=128 rows][K cols]
__device__ __nv_bfloat16 g_bh_proj[128 * 256];
__device__ __nv_bfloat16 g_bl_proj[128 * 256];
__device__ __nv_bfloat16 g_bh_w0  [128 * 128];
__device__ __nv_bfloat16 g_bl_w0  [128 * 128];
__device__ __nv_bfloat16 g_bh_w1  [128 * 128];
__device__ __nv_bfloat16 g_bl_w1  [128 * 128];
__device__ __nv_bfloat16 g_bh_w2  [128 * 128];
__device__ __nv_bfloat16 g_bl_w2  [128 * 128];

// ================= helpers =================
__device__ __forceinline__ uint32_t smem_u32(const void* p) {
    uint32_t a;
    asm("{ .reg .u64 t; cvta.to.shared.u64 t, %1; cvt.u32.u64 %0, t; }" : "=r"(a) : "l"(p));
    return a;
}
__device__ __forceinline__ uint32_t sw128(uint32_t o) { return o ^ ((o >> 3) & 0x70); }

__device__ __forceinline__ void ldsm_x4(uint32_t* r, uint32_t addr) {
    asm volatile("ldmatrix.sync.aligned.m8n8.x4.shared.b16 {%0,%1,%2,%3}, [%4];"
        : "=r"(r[0]), "=r"(r[1]), "=r"(r[2]), "=r"(r[3]) : "r"(addr));
}
__device__ __forceinline__ void mma16816(float* c, const uint32_t* a, const uint32_t* b) {
    asm volatile(
        "mma.sync.aligned.m16n8k16.row.col.f32.bf16.bf16.f32 "
        "{%0,%1,%2,%3}, {%4,%5,%6,%7}, {%8,%9}, {%0,%1,%2,%3};"
        : "+f"(c[0]), "+f"(c[1]), "+f"(c[2]), "+f"(c[3])
        : "r"(a[0]), "r"(a[1]), "r"(a[2]), "r"(a[3]), "r"(b[0]), "r"(b[1]));
}
__device__ __forceinline__ void mma1688_tf32(float* c, const uint32_t* a, const uint32_t* b) {
    asm volatile(
        "mma.sync.aligned.m16n8k8.row.col.f32.tf32.tf32.f32 "
        "{%0,%1,%2,%3}, {%4,%5,%6,%7}, {%8,%9}, {%0,%1,%2,%3};"
        : "+f"(c[0]), "+f"(c[1]), "+f"(c[2]), "+f"(c[3])
        : "r"(a[0]), "r"(a[1]), "r"(a[2]), "r"(a[3]), "r"(b[0]), "r"(b[1]));
}
__device__ __forceinline__ uint32_t f2tf32(float x) {
    uint32_t u;
    asm("cvt.rna.tf32.f32 %0, %1;" : "=r"(u) : "f"(x));
    return u;
}
#define CP_ASYNC16(smem, gptr) \
    asm volatile("cp.async.cg.shared.global [%0], [%1], 16;" :: "r"(smem), "l"(gptr))

__device__ __forceinline__ uint32_t packbf2(float a, float b, float* ra, float* rb) {
    __nv_bfloat16 ha = __float2bfloat16_rn(a), hb = __float2bfloat16_rn(b);
    if (ra) { *ra = a - __bfloat162float(ha); *rb = b - __bfloat162float(hb); }
    return (uint32_t)__bfloat16_as_ushort(ha) | ((uint32_t)__bfloat16_as_ushort(hb) << 16);
}

// load 4 fp16 (8B) from a row and widen to float4
__device__ __forceinline__ float4 ldh4(const __half* p, int c) {
    uint2 u = *(const uint2*)(p + c);
    __half2 h0 = *reinterpret_cast<__half2*>(&u.x);
    __half2 h1 = *reinterpret_cast<__half2*>(&u.y);
    float2 a = __half22float2(h0);
    float2 b = __half22float2(h1);
    return make_float4(a.x, a.y, b.x, b.y);
}

// ================= graph prep: CSR build =================
__global__ void k_zero() {
    int i = blockIdx.x * blockDim.x + threadIdx.x;
    if (i < NN) { g_degi[i] = 0; g_cursor[i] = 0; }
}
__global__ void k_degree(const int* __restrict__ dst) {
    int e = blockIdx.x * blockDim.x + threadIdx.x;
    if (e < EE) atomicAdd(&g_degi[dst[e]], 1);
}

#define SCAN_T 256
#define SCAN_NB ((NN + SCAN_T * 4 - 1) / (SCAN_T * 4))   // 98
__global__ void __launch_bounds__(SCAN_T) k_scan1() {
    __shared__ int s[SCAN_T];
    int t = threadIdx.x;
    int base = blockIdx.x * SCAN_T * 4 + t * 4;
    int v[4];
    #pragma unroll
    for (int j = 0; j < 4; j++) {
        v[j] = (base + j < NN) ? g_degi[base + j] : 0;
        if (base + j < NN) g_dinv[base + j] = rsqrtf((float)(v[j] + 1));  // +1 self-loop
    }
    int tsum = v[0] + v[1] + v[2] + v[3];
    s[t] = tsum; __syncthreads();
    #pragma unroll
    for (int off = 1; off < SCAN_T; off <<= 1) {
        int x = (t >= off) ? s[t - off] : 0;
        __syncthreads();
        s[t] += x;
        __syncthreads();
    }
    int run = s[t] - tsum;
    #pragma unroll
    for (int j = 0; j < 4; j++) {
        if (base + j < NN) g_rowptr[base + j] = run;
        run += v[j];
    }
    if (t == SCAN_T - 1) g_bsum[blockIdx.x] = s[SCAN_T - 1];
}
__global__ void __launch_bounds__(128) k_scan2() {
    __shared__ int s[128];
    int t = threadIdx.x;
    int v = (t < SCAN_NB) ? g_bsum[t] : 0;
    s[t] = v; __syncthreads();
    #pragma unroll
    for (int off = 1; off < 128; off <<= 1) {
        int x = (t >= off) ? s[t - off] : 0;
        __syncthreads();
        s[t] += x;
        __syncthreads();
    }
    if (t < SCAN_NB) g_bsumx[t] = s[t] - v;
}
__global__ void k_scan3() {
    int i = blockIdx.x * blockDim.x + threadIdx.x;
    if (i < NN) g_rowptr[i] += g_bsumx[i / (SCAN_T * 4)];
    if (i == 0) g_rowptr[NN] = EE;
}
__global__ void k_scatter(const int* __restrict__ src, const int* __restrict__ dst) {
    int e = blockIdx.x * blockDim.x + threadIdx.x;
    if (e >= EE) return;
    int d = dst[e];
    int s = src[e];
    int pos = g_rowptr[d] + atomicAdd(&g_cursor[d], 1);
    float nm = g_dinv[s] * g_dinv[d];
    g_epack[pos] = make_int2(s, __float_as_int(nm));
}

// ============ weight prep: enc transpose (fp32) + bf16 splits for the rest ============
#define SPLIT_TOT (768*128 + 256*128 + 3*128*128)
__global__ void k_split_all(const float* __restrict__ encW, const float* __restrict__ projW,
                            const float* __restrict__ W0, const float* __restrict__ W1,
                            const float* __restrict__ W2) {
    int idx = blockIdx.x * blockDim.x + threadIdx.x;
    if (idx >= SPLIT_TOT) return;
    int local = idx;
    if (local < 768*128) {
        int k = local >> 7, n = local & 127;
        g_bt_enc[n * 768 + k] = encW[local];     // transposed fp32 (tf32 path)
        return;
    }
    local -= 768*128;
    const float* W; __nv_bfloat16 *Bh, *Bl; int K;
    if (local < 256*128)                   { W = projW; Bh = g_bh_proj; Bl = g_bl_proj; K = 256; }
    else if ((local -= 256*128) < 128*128) { W = W0;    Bh = g_bh_w0;   Bl = g_bl_w0;   K = 128; }
    else if ((local -= 128*128) < 128*128) { W = W1;    Bh = g_bh_w1;   Bl = g_bl_w1;   K = 128; }
    else  { local -= 128*128;                W = W2;    Bh = g_bh_w2;   Bl = g_bl_w2;   K = 128; }
    int k = local >> 7;
    int n = local & 127;
    float w = W[local];
    __nv_bfloat16 h = __float2bfloat16_rn(w);
    float r = w - __bfloat162float(h);
    Bh[n * K + k] = h;
    Bl[n * K + k] = __float2bfloat16_rn(r);
}

// ============ tf32 GEMM (encoder only, pre-LN): C = LN+ReLU(A[M,768] @ W + b) ============
#define TILE32 16384
#define DYN32  (4 * TILE32 + 1024)

__global__ void __launch_bounds__(256, 1)
k_gemm_tf32(const float* __restrict__ A, int K,
            const float* __restrict__ Bt,
            const float* __restrict__ bias,
            const float* __restrict__ lnG, const float* __restrict__ lnB,
            float* __restrict__ C)
{
    extern __shared__ char dyn[];
    const int tid = threadIdx.x;
    const int rowBase = blockIdx.x * 128;

    uint32_t dynb = smem_u32(dyn);
    char* sm = dyn + (((dynb + 1023u) & ~1023u) - dynb);
    const uint32_t uA0 = smem_u32(sm);
    const uint32_t uB0 = smem_u32(sm + 2 * TILE32);

    const int lane = tid & 31;
    const int warp = tid >> 5;
    const int mBase = (warp & 3) * 32;
    const int nBase = (warp >> 2) * 64;

    const int aRowL = (lane & 7) + ((lane & 8) ? 8 : 0);
    const int aKbL  = (lane & 16) ? 16 : 0;
    const int bRowL = (lane & 7) + ((lane & 16) ? 8 : 0);
    const int bKbL  = (lane & 8) ? 16 : 0;

    float acc[2][8][4];
    #pragma unroll
    for (int mt = 0; mt < 2; mt++)
        #pragma unroll
        for (int nt = 0; nt < 8; nt++)
            #pragma unroll
            for (int j = 0; j < 4; j++) acc[mt][nt][j] = 0.0f;

    const int nChunks = K >> 5;
    const int aRow = tid >> 1;
    const int aCol = (tid & 1) * 16;
    const int gr   = rowBase + aRow;
    float4 aF[4];

    auto prefetchA = [&](int c) {
        int k0 = c * 32;
        #pragma unroll
        for (int i = 0; i < 4; i++) {
            aF[i] = make_float4(0.f, 0.f, 0.f, 0.f);
            if (gr < NN) aF[i] = *(const float4*)(A + (size_t)gr * K + k0 + aCol + i * 4);
        }
    };
    auto convertHalf = [&](int buf, int half) {
        char* d = sm + buf * TILE32;
        #pragma unroll
        for (int i = half * 2; i < half * 2 + 2; i++) {
            uint4 u = make_uint4(f2tf32(aF[i].x), f2tf32(aF[i].y),
                                 f2tf32(aF[i].z), f2tf32(aF[i].w));
            *(uint4*)(d + sw128((uint32_t)(aRow * 128 + (aCol + i * 4) * 4))) = u;
        }
    };
    auto issueB = [&](int c, int buf) {
        int k0 = c * 32;
        uint32_t dst = uB0 + (uint32_t)buf * TILE32;
        #pragma unroll
        for (int i = 0; i < 4; i++) {
            int idx = i * 256 + tid;
            int n   = idx >> 3;
            int kq  = idx & 7;
            CP_ASYNC16(dst + sw128((uint32_t)(n * 128 + kq * 16)),
                       (const char*)(Bt + (size_t)n * K + k0 + kq * 4));
        }
        asm volatile("cp.async.commit_group;" ::: "memory");
    };

    prefetchA(0);
    issueB(0, 0);
    convertHalf(0, 0);
    convertHalf(0, 1);
    if (nChunks > 1) prefetchA(1);

    for (int c = 0; c < nChunks; c++) {
        const int buf = c & 1;
        const bool hasNext = (c + 1 < nChunks);

        asm volatile("cp.async.wait_group 0;" ::: "memory");
        __syncthreads();

        if (hasNext) issueB(c + 1, buf ^ 1);

        const uint32_t uA = uA0 + (uint32_t)buf * TILE32;
        const uint32_t uB = uB0 + (uint32_t)buf * TILE32;

        #pragma unroll
        for (int ks = 0; ks < 4; ks++) {
            const int kb = ks * 32;
            uint32_t af[2][4], bq[4][4];

            #pragma unroll
            for (int mt = 0; mt < 2; mt++)
                ldsm_x4(af[mt], uA + sw128((uint32_t)((mBase + mt * 16 + aRowL) * 128 + kb + aKbL)));
            #pragma unroll
            for (int p = 0; p < 4; p++)
                ldsm_x4(bq[p], uB + sw128((uint32_t)((nBase + p * 16 + bRowL) * 128 + kb + bKbL)));

            #pragma unroll
            for (int mt = 0; mt < 2; mt++)
                #pragma unroll
                for (int p = 0; p < 4; p++) {
                    mma1688_tf32(acc[mt][2 * p],     af[mt], &bq[p][0]);
                    mma1688_tf32(acc[mt][2 * p + 1], af[mt], &bq[p][2]);
                }

            if (ks == 0 && hasNext) convertHalf(buf ^ 1, 0);
            if (ks == 1 && hasNext) {
                convertHalf(buf ^ 1, 1);
                if (c + 2 < nChunks) prefetchA(c + 2);
            }
        }
    }

    // ---- fused LayerNorm + ReLU epilogue (bias pre-LN) ----
    const int rL = lane >> 2;
    const int cL = (lane & 3) * 2;
    __syncthreads();
    float* ssum = (float*)sm;
    float* ssq  = (float*)(sm + 1024);
    const int half = warp >> 2;

    #pragma unroll
    for (int mt = 0; mt < 2; mt++)
        #pragma unroll
        for (int hr = 0; hr < 2; hr++) {
            int lr = mBase + mt * 16 + rL + hr * 8;
            float s = 0.f, q = 0.f;
            #pragma unroll
            for (int nt = 0; nt < 8; nt++)
                #pragma unroll
                for (int cc = 0; cc < 2; cc++) {
                    float v = acc[mt][nt][hr * 2 + cc] + bias[nBase + nt * 8 + cL + cc];
                    s += v; q += v * v;
                }
            s += __shfl_xor_sync(0xffffffffu, s, 1);
            q += __shfl_xor_sync(0xffffffffu, q, 1);
            s += __shfl_xor_sync(0xffffffffu, s, 2);
            q += __shfl_xor_sync(0xffffffffu, q, 2);
            if ((lane & 3) == 0) { ssum[lr * 2 + half] = s; ssq[lr * 2 + half] = q; }
        }
    __syncthreads();

    #pragma unroll
    for (int mt = 0; mt < 2; mt++)
        #pragma unroll
        for (int hr = 0; hr < 2; hr++) {
            int lr  = mBase + mt * 16 + rL + hr * 8;
            int row = rowBase + lr;
            float s = ssum[lr * 2] + ssum[lr * 2 + 1];
            float q = ssq [lr * 2] + ssq [lr * 2 + 1];
            float mu  = s * (1.0f / 128.0f);
            float var = q * (1.0f / 128.0f) - mu * mu;
            float rst = rsqrtf(var + EPSV);
            if (row < NN) {
                #pragma unroll
                for (int nt = 0; nt < 8; nt++) {
                    int col = nBase + nt * 8 + cL;
                    float v0 = acc[mt][nt][hr * 2]     + bias[col];
                    float v1 = acc[mt][nt][hr * 2 + 1] + bias[col + 1];
                    v0 = fmaxf((v0 - mu) * rst * lnG[col]     + lnB[col],     0.f);
                    v1 = fmaxf((v1 - mu) * rst * lnG[col + 1] + lnB[col + 1], 0.f);
                    *(float2*)&C[(size_t)row * 128 + col] = make_float2(v0, v1);
                }
            }
        }
}

// ============ pipelined mma.sync split-bf16 GEMM ============
// A sources: fp16 (A16 != null, stride 128) OR dual fp32 range [Aa | Ab] by kSplit.
#define TILE_B 16384
#define GEMM_DYN (8 * TILE_B + 1024)

__global__ void __launch_bounds__(256, 1)
k_gemm_mma(const float* __restrict__ Aa, int strideA,
           const float* __restrict__ Ab, int strideB, int kSplit,
           const __half* __restrict__ A16, int K,
           const __nv_bfloat16* __restrict__ Bh, const __nv_bfloat16* __restrict__ Bl,
           const float* __restrict__ bias, int relu,
           float* __restrict__ C, __half* __restrict__ Ch)
{
    extern __shared__ char dyn[];
    const int tid = threadIdx.x;
    const int rowBase = blockIdx.x * 128;

    uint32_t dynb = smem_u32(dyn);
    char* sm = dyn + (((dynb + 1023u) & ~1023u) - dynb);
    const uint32_t uA0 = smem_u32(sm);
    const uint32_t uB0 = smem_u32(sm + 4 * TILE_B);

    const int lane = tid & 31;
    const int warp = tid >> 5;
    const int mBase = (warp & 3) * 32;
    const int nBase = (warp >> 2) * 64;

    const int aRowL = (lane & 7) + ((lane & 8) ? 8 : 0);
    const int aKbL  = (lane & 16) ? 16 : 0;
    const int bRowL = (lane & 7) + ((lane & 16) ? 8 : 0);
    const int bKbL  = (lane & 8) ? 16 : 0;

    float acc[2][8][4];
    #pragma unroll
    for (int mt = 0; mt < 2; mt++)
        #pragma unroll
        for (int nt = 0; nt < 8; nt++)
            #pragma unroll
            for (int j = 0; j < 4; j++) acc[mt][nt][j] = 0.0f;

    const int nChunks = K >> 6;
    float4 aF[8];

    auto prefetchA = [&](int c) {
        int k0 = c * 64;
        #pragma unroll
        for (int i = 0; i < 8; i++) {
            int fidx = i * 256 + tid;
            int r    = fidx >> 4;
            int kq   = fidx & 15;
            int gr   = rowBase + r;
            aF[i] = make_float4(0.f, 0.f, 0.f, 0.f);
            if (gr < NN) {
                if (A16) {
                    aF[i] = ldh4(A16 + (size_t)gr * 128, k0 + kq * 4);
                } else {
                    const float* base; int stride; int koff;
                    if (k0 < kSplit) { base = Aa; stride = strideA; koff = k0; }
                    else             { base = Ab; stride = strideB; koff = k0 - kSplit; }
                    aF[i] = *(const float4*)(base + (size_t)gr * stride + koff + kq * 4);
                }
            }
        }
    };

    auto convertHalf = [&](int buf, int half) {
        char* dh = sm + buf * (2 * TILE_B);
        char* dl = dh + TILE_B;
        #pragma unroll
        for (int i = half * 4; i < half * 4 + 4; i++) {
            int fidx = i * 256 + tid;
            int r    = fidx >> 4;
            int kq   = fidx & 15;
            float r0, r1, r2, r3;
            uint32_t h0 = packbf2(aF[i].x, aF[i].y, &r0, &r1);
            uint32_t h1 = packbf2(aF[i].z, aF[i].w, &r2, &r3);
            uint32_t l0 = packbf2(r0, r1, nullptr, nullptr);
            uint32_t l1 = packbf2(r2, r3, nullptr, nullptr);
            uint32_t off = sw128((uint32_t)(r * 128 + kq * 8));
            *(uint2*)(dh + off) = make_uint2(h0, h1);
            *(uint2*)(dl + off) = make_uint2(l0, l1);
        }
    };

    auto issueB = [&](int c, int buf) {
        int k0 = c * 64;
        uint32_t dst = uB0 + (uint32_t)buf * (2 * TILE_B);
        #pragma unroll
        for (int i = 0; i < 4; i++) {
            int uidx = i * 256 + tid;
            int n    = uidx >> 3;
            int kq   = uidx & 7;
            uint32_t off = sw128((uint32_t)(n * 128 + kq * 16));
            CP_ASYNC16(dst + off,          (const char*)(Bh + (size_t)n * K + k0 + kq * 8));
            CP_ASYNC16(dst + TILE_B + off, (const char*)(Bl + (size_t)n * K + k0 + kq * 8));
        }
        asm volatile("cp.async.commit_group;" ::: "memory");
    };

    prefetchA(0);
    issueB(0, 0);
    convertHalf(0, 0);
    convertHalf(0, 1);
    if (nChunks > 1) prefetchA(1);

    for (int c = 0; c < nChunks; c++) {
        const int buf  = c & 1;
        const bool hasNext = (c + 1 < nChunks);

        asm volatile("cp.async.wait_group 0;" ::: "memory");
        __syncthreads();

        if (hasNext) issueB(c + 1, buf ^ 1);

        const uint32_t uAh = uA0 + (uint32_t)buf * (2 * TILE_B);
        const uint32_t uAl = uAh + TILE_B;
        const uint32_t uBh = uB0 + (uint32_t)buf * (2 * TILE_B);
        const uint32_t uBl = uBh + TILE_B;

        #pragma unroll
        for (int ks = 0; ks < 4; ks++) {
            const int kb = ks * 32;
            uint32_t ah[2][4], al[2][4], bq[4][4];

            #pragma unroll
            for (int mt = 0; mt < 2; mt++)
                ldsm_x4(ah[mt], uAh + sw128((uint32_t)((mBase + mt * 16 + aRowL) * 128 + kb + aKbL)));
            #pragma unroll
            for (int mt = 0; mt < 2; mt++)
                ldsm_x4(al[mt], uAl + sw128((uint32_t)((mBase + mt * 16 + aRowL) * 128 + kb + aKbL)));
            #pragma unroll
            for (int p = 0; p < 4; p++)
                ldsm_x4(bq[p], uBh + sw128((uint32_t)((nBase + p * 16 + bRowL) * 128 + kb + bKbL)));

            #pragma unroll
            for (int mt = 0; mt < 2; mt++)
                #pragma unroll
                for (int p = 0; p < 4; p++) {
                    mma16816(acc[mt][2 * p],     ah[mt], &bq[p][0]);
                    mma16816(acc[mt][2 * p + 1], ah[mt], &bq[p][2]);
                }
            #pragma unroll
            for (int mt = 0; mt < 2; mt++)
                #pragma unroll
                for (int p = 0; p < 4; p++) {
                    mma16816(acc[mt][2 * p],     al[mt], &bq[p][0]);
                    mma16816(acc[mt][2 * p + 1], al[mt], &bq[p][2]);
                }

            #pragma unroll
            for (int p = 0; p < 4; p++)
                ldsm_x4(bq[p], uBl + sw128((uint32_t)((nBase + p * 16 + bRowL) * 128 + kb + bKbL)));
            #pragma unroll
            for (int mt = 0; mt < 2; mt++)
                #pragma unroll
                for (int p = 0; p < 4; p++) {
                    mma16816(acc[mt][2 * p],     ah[mt], &bq[p][0]);
                    mma16816(acc[mt][2 * p + 1], ah[mt], &bq[p][2]);
                }

            if (ks == 0 && hasNext) convertHalf(buf ^ 1, 0);
            if (ks == 1 && hasNext) {
                convertHalf(buf ^ 1, 1);
                if (c + 2 < nChunks) prefetchA(c + 2);
            }
        }
    }

    const int rL = lane >> 2;
    const int cL = (lane & 3) * 2;

    #pragma unroll
    for (int mt = 0; mt < 2; mt++) {
        #pragma unroll
        for (int hr = 0; hr < 2; hr++) {
            int row = rowBase + mBase + mt * 16 + rL + hr * 8;
            if (row >= NN) continue;
            #pragma unroll
            for (int nt = 0; nt < 8; nt++) {
                int col = nBase + nt * 8 + cL;
                float v0 = acc[mt][nt][hr * 2];
                float v1 = acc[mt][nt][hr * 2 + 1];
                if (bias) { v0 += bias[col]; v1 += bias[col + 1]; }
                if (relu) { v0 = fmaxf(v0, 0.f); v1 = fmaxf(v1, 0.f); }
                if (C)  *(float2*)&C[(size_t)row * 128 + col] = make_float2(v0, v1);
                if (Ch) *(__half2*)&Ch[(size_t)row * 128 + col] = __floats2half2_rn(v0, v1);
            }
        }
    }
}

// ====== fused CSR SPMM (fp16 gather): out = act(dinv^2*xw[d] + sum norm*xw[src] + b) ======
// outputs: fp32 (outF) and/or fp16 (outH)
__global__ void __launch_bounds__(256)
k_spmm_csr(const float* __restrict__ bias,
           float* __restrict__ outF, __half* __restrict__ outH, int relu)
{
    int w = (blockIdx.x * blockDim.x + threadIdx.x) >> 5;
    if (w >= NN) return;
    int lane = threadIdx.x & 31;
    int c = lane * 4;

    float di = g_dinv[w];
    float wt = di * di;
    float4 sv = ldh4(&g_xwh[(size_t)w * 128], c);
    float4 acc = make_float4(sv.x * wt, sv.y * wt, sv.z * wt, sv.w * wt);
    float4 acc2 = make_float4(0.f, 0.f, 0.f, 0.f);

    int start = g_rowptr[w];
    int end   = g_rowptr[w + 1];
    for (int base = start; base < end; base += 32) {
        int rem = end - base;
        int2 p = make_int2(0, 0);
        if (lane < rem) p = g_epack[base + lane];
        if (rem >= 32) {
            #pragma unroll
            for (int j = 0; j < 32; j += 2) {
                int   s0  = __shfl_sync(0xffffffffu, p.x, j);
                float nm0 = __int_as_float(__shfl_sync(0xffffffffu, p.y, j));
                int   s1  = __shfl_sync(0xffffffffu, p.x, j + 1);
                float nm1 = __int_as_float(__shfl_sync(0xffffffffu, p.y, j + 1));
                float4 v0 = ldh4(&g_xwh[(size_t)s0 * 128], c);
                float4 v1 = ldh4(&g_xwh[(size_t)s1 * 128], c);
                acc.x  = fmaf(nm0, v0.x, acc.x);
                acc.y  = fmaf(nm0, v0.y, acc.y);
                acc.z  = fmaf(nm0, v0.z, acc.z);
                acc.w  = fmaf(nm0, v0.w, acc.w);
                acc2.x = fmaf(nm1, v1.x, acc2.x);
                acc2.y = fmaf(nm1, v1.y, acc2.y);
                acc2.z = fmaf(nm1, v1.z, acc2.z);
                acc2.w = fmaf(nm1, v1.w, acc2.w);
            }
        } else {
            for (int j = 0; j < rem; j++) {
                int   s  = __shfl_sync(0xffffffffu, p.x, j);
                float nm = __int_as_float(__shfl_sync(0xffffffffu, p.y, j));
                float4 v = ldh4(&g_xwh[(size_t)s * 128], c);
                acc.x = fmaf(nm, v.x, acc.x);
                acc.y = fmaf(nm, v.y, acc.y);
                acc.z = fmaf(nm, v.z, acc.z);
                acc.w = fmaf(nm, v.w, acc.w);
            }
        }
    }
    acc.x += acc2.x; acc.y += acc2.y; acc.z += acc2.z; acc.w += acc2.w;

    float4 bb = *(const float4*)&bias[c];
    acc.x += bb.x; acc.y += bb.y; acc.z += bb.z; acc.w += bb.w;
    if (relu) {
        acc.x = fmaxf(acc.x, 0.f); acc.y = fmaxf(acc.y, 0.f);
        acc.z = fmaxf(acc.z, 0.f); acc.w = fmaxf(acc.w, 0.f);
    }
    if (outF) *(float4*)&outF[(size_t)w * 128 + c] = acc;
    if (outH) {
        uint2 u;
        __half2 h0 = __floats2half2_rn(acc.x, acc.y);
        __half2 h1 = __floats2half2_rn(acc.z, acc.w);
        u.x = *reinterpret_cast<uint32_t*>(&h0);
        u.y = *reinterpret_cast<uint32_t*>(&h1);
        *(uint2*)&outH[(size_t)w * 128 + c] = u;
    }
}

// ================= launch =================
extern "C" void kernel_launch(void* const* d_in, const int* in_sizes, int n_in,
                              void* d_out, int out_size)
{
    (void)in_sizes; (void)n_in; (void)out_size;
    const int*   ei    = (const int*)  d_in[0];
    const float* ext   = (const float*)d_in[1];
    const float* emb   = (const float*)d_in[2];
    const float* encW  = (const float*)d_in[3];
    const float* encB  = (const float*)d_in[4];
    const float* lng   = (const float*)d_in[5];
    const float* lnb   = (const float*)d_in[6];
    const float* projW = (const float*)d_in[7];
    const float* projB = (const float*)d_in[8];
    const float* W0    = (const float*)d_in[9];
    const float* b0    = (const float*)d_in[10];
    const float* W1    = (const float*)d_in[11];
    const float* b1    = (const float*)d_in[12];
    const float* W2    = (const float*)d_in[13];
    const float* b2    = (const float*)d_in[14];
    float* out = (float*)d_out;

    const int* src = ei;
    const int* dst = ei + EE;

    float *p_tmp, *bt_enc;
    __half *p_xh, *p_xwh;
    cudaGetSymbolAddress((void**)&p_tmp, g_tmp);
    cudaGetSymbolAddress((void**)&p_xh,  g_xh);
    cudaGetSymbolAddress((void**)&p_xwh, g_xwh);
    cudaGetSymbolAddress((void**)&bt_enc, g_bt_enc);

    __nv_bfloat16 *bh_proj, *bl_proj, *bh_w0, *bl_w0, *bh_w1, *bl_w1, *bh_w2, *bl_w2;
    cudaGetSymbolAddress((void**)&bh_proj, g_bh_proj);
    cudaGetSymbolAddress((void**)&bl_proj, g_bl_proj);
    cudaGetSymbolAddress((void**)&bh_w0,   g_bh_w0);
    cudaGetSymbolAddress((void**)&bl_w0,   g_bl_w0);
    cudaGetSymbolAddress((void**)&bh_w1,   g_bh_w1);
    cudaGetSymbolAddress((void**)&bl_w1,   g_bl_w1);
    cudaGetSymbolAddress((void**)&bh_w2,   g_bh_w2);
    cudaGetSymbolAddress((void**)&bl_w2,   g_bl_w2);

    cudaFuncSetAttribute(k_gemm_mma,  cudaFuncAttributeMaxDynamicSharedMemorySize, GEMM_DYN);
    cudaFuncSetAttribute(k_gemm_tf32, cudaFuncAttributeMaxDynamicSharedMemorySize, DYN32);

    static cudaStream_t sB = nullptr;
    static cudaEvent_t evF = nullptr, evJ = nullptr;
    if (!sB) {
        cudaStreamCreate(&sB);
        cudaEventCreateWithFlags(&evF, cudaEventDisableTiming);
        cudaEventCreateWithFlags(&evJ, cudaEventDisableTiming);
    }

    const int TB = 256;
    const int gN     = (NN + TB - 1) / TB;
    const int gE     = (EE + TB - 1) / TB;
    const int gRow   = (NN * 32 + TB - 1) / TB;
    const int gGemm  = (NN + 127) / 128;

    // ---- fork: CSR build on side stream ----
    cudaEventRecord(evF, 0);
    cudaStreamWaitEvent(sB, evF, 0);

    k_zero<<<gN, TB, 0, sB>>>();
    k_degree<<<gE, TB, 0, sB>>>(dst);
    k_scan1<<<SCAN_NB, SCAN_T, 0, sB>>>();
    k_scan2<<<1, 128, 0, sB>>>();
    k_scan3<<<gN, TB, 0, sB>>>();
    k_scatter<<<gE, TB, 0, sB>>>(src, dst);
    cudaEventRecord(evJ, sB);

    // main stream: weight prep + dense chain
    k_split_all<<<(SPLIT_TOT + TB - 1) / TB, TB>>>(encW, projW, W0, W1, W2);

    // encoder GEMM (tf32, pre-LN so quantization washes out) with fused LN+ReLU
    k_gemm_tf32<<<gGemm, TB, DYN32>>>(ext, EXTD, bt_enc, encB, lng, lnb, p_tmp);

    // projection (split-bf16): A = [emb | feat] dual fp32 source -> fp16 x
    k_gemm_mma<<<gGemm, TB, GEMM_DYN>>>(emb, HH, p_tmp, HH, HH, nullptr, 2 * HH,
                                        bh_proj, bl_proj, projB, 0, nullptr, p_xh);

    // layer 0 GEMM (split-bf16, fp16 A) -> fp16 xw
    k_gemm_mma<<<gGemm, TB, GEMM_DYN>>>(nullptr, 0, nullptr, 0, 0, p_xh, HH,
                                        bh_w0, bl_w0, nullptr, 0, nullptr, p_xwh);

    // ---- join: SPMM needs the CSR ----
    cudaStreamWaitEvent(0, evJ, 0);

    k_spmm_csr<<<gRow, TB>>>(b0, nullptr, p_xh, 1);

    k_gemm_mma<<<gGemm, TB, GEMM_DYN>>>(nullptr, 0, nullptr, 0, 0, p_xh, HH,
                                        bh_w1, bl_w1, nullptr, 0, nullptr, p_xwh);
    k_spmm_csr<<<gRow, TB>>>(b1, nullptr, p_xh, 1);

    k_gemm_mma<<<gGemm, TB, GEMM_DYN>>>(nullptr, 0, nullptr, 0, 0, p_xh, HH,
                                        bh_w2, bl_w2, nullptr, 0, nullptr, p_xwh);
    k_spmm_csr<<<gRow, TB>>>(b2, out, nullptr, 0);
}

// round 16
// speedup vs baseline: 4.6635x; 1.1874x over previous
#include <cuda_runtime.h>
#include <cuda_bf16.h>
#include <cuda_fp16.h>
#include <cstdint>

// Problem constants
#define NN   100000
#define HH   128
#define EE   1600000
#define EXTD 768
#define EPSV 1e-5f

// ================= device scratch (no allocations allowed) =================
__device__ float g_dinv[NN];
__device__ int   g_degi[NN];
__device__ int   g_cursor[NN];
__device__ int   g_rowptr[NN + 1];
__device__ int   g_bsum[128];
__device__ int   g_bsumx[128];
__device__ int2  g_epack[EE];          // (src, norm-bits) sorted by dst
__device__ float g_tmp [NN * HH];      // encoder LN+ReLU output (fp32)
__device__ __half g_xh [NN * HH];      // intermediate x, fp16 (GEMM-A source)
__device__ __half g_xwh[NN * HH];      // layer GEMM output, fp16 (SPMM gather source)

// encoder weights: transposed fp32 [128][768] (tf32 path)
__device__ float g_bt_enc[128 * 768];
// proj: split-bf16 transposed [128][256]
__device__ __nv_bfloat16 g_bh_proj[128 * 256];
__device__ __nv_bfloat16 g_bl_proj[128 * 256];
// layers: fp16 transposed [128][128]
__device__ __half g_bw0h[128 * 128];
__device__ __half g_bw1h[128 * 128];
__device__ __half g_bw2h[128 * 128];

// ================= helpers =================
__device__ __forceinline__ uint32_t smem_u32(const void* p) {
    uint32_t a;
    asm("{ .reg .u64 t; cvta.to.shared.u64 t, %1; cvt.u32.u64 %0, t; }" : "=r"(a) : "l"(p));
    return a;
}
__device__ __forceinline__ uint32_t sw128(uint32_t o) { return o ^ ((o >> 3) & 0x70); }

__device__ __forceinline__ void ldsm_x4(uint32_t* r, uint32_t addr) {
    asm volatile("ldmatrix.sync.aligned.m8n8.x4.shared.b16 {%0,%1,%2,%3}, [%4];"
        : "=r"(r[0]), "=r"(r[1]), "=r"(r[2]), "=r"(r[3]) : "r"(addr));
}
__device__ __forceinline__ void mma16816_bf16(float* c, const uint32_t* a, const uint32_t* b) {
    asm volatile(
        "mma.sync.aligned.m16n8k16.row.col.f32.bf16.bf16.f32 "
        "{%0,%1,%2,%3}, {%4,%5,%6,%7}, {%8,%9}, {%0,%1,%2,%3};"
        : "+f"(c[0]), "+f"(c[1]), "+f"(c[2]), "+f"(c[3])
        : "r"(a[0]), "r"(a[1]), "r"(a[2]), "r"(a[3]), "r"(b[0]), "r"(b[1]));
}
__device__ __forceinline__ void mma16816_f16(float* c, const uint32_t* a, const uint32_t* b) {
    asm volatile(
        "mma.sync.aligned.m16n8k16.row.col.f32.f16.f16.f32 "
        "{%0,%1,%2,%3}, {%4,%5,%6,%7}, {%8,%9}, {%0,%1,%2,%3};"
        : "+f"(c[0]), "+f"(c[1]), "+f"(c[2]), "+f"(c[3])
        : "r"(a[0]), "r"(a[1]), "r"(a[2]), "r"(a[3]), "r"(b[0]), "r"(b[1]));
}
__device__ __forceinline__ void mma1688_tf32(float* c, const uint32_t* a, const uint32_t* b) {
    asm volatile(
        "mma.sync.aligned.m16n8k8.row.col.f32.tf32.tf32.f32 "
        "{%0,%1,%2,%3}, {%4,%5,%6,%7}, {%8,%9}, {%0,%1,%2,%3};"
        : "+f"(c[0]), "+f"(c[1]), "+f"(c[2]), "+f"(c[3])
        : "r"(a[0]), "r"(a[1]), "r"(a[2]), "r"(a[3]), "r"(b[0]), "r"(b[1]));
}
#define CP_ASYNC16(smem, gptr) \
    asm volatile("cp.async.cg.shared.global [%0], [%1], 16;" :: "r"(smem), "l"(gptr))

__device__ __forceinline__ uint32_t packbf2(float a, float b, float* ra, float* rb) {
    __nv_bfloat16 ha = __float2bfloat16_rn(a), hb = __float2bfloat16_rn(b);
    if (ra) { *ra = a - __bfloat162float(ha); *rb = b - __bfloat162float(hb); }
    return (uint32_t)__bfloat16_as_ushort(ha) | ((uint32_t)__bfloat16_as_ushort(hb) << 16);
}

// load 4 fp16 (8B) from a row and widen to float4
__device__ __forceinline__ float4 ldh4(const __half* p, int c) {
    uint2 u = *(const uint2*)(p + c);
    __half2 h0 = *reinterpret_cast<__half2*>(&u.x);
    __half2 h1 = *reinterpret_cast<__half2*>(&u.y);
    float2 a = __half22float2(h0);
    float2 b = __half22float2(h1);
    return make_float4(a.x, a.y, b.x, b.y);
}

// ================= graph prep: CSR build =================
__global__ void k_zero() {
    int i = blockIdx.x * blockDim.x + threadIdx.x;
    if (i < NN) { g_degi[i] = 0; g_cursor[i] = 0; }
}
__global__ void k_degree(const int* __restrict__ dst) {
    int e = blockIdx.x * blockDim.x + threadIdx.x;
    if (e < EE) atomicAdd(&g_degi[dst[e]], 1);
}

#define SCAN_T 256
#define SCAN_NB ((NN + SCAN_T * 4 - 1) / (SCAN_T * 4))   // 98
__global__ void __launch_bounds__(SCAN_T) k_scan1() {
    __shared__ int s[SCAN_T];
    int t = threadIdx.x;
    int base = blockIdx.x * SCAN_T * 4 + t * 4;
    int v[4];
    #pragma unroll
    for (int j = 0; j < 4; j++) {
        v[j] = (base + j < NN) ? g_degi[base + j] : 0;
        if (base + j < NN) g_dinv[base + j] = rsqrtf((float)(v[j] + 1));  // +1 self-loop
    }
    int tsum = v[0] + v[1] + v[2] + v[3];
    s[t] = tsum; __syncthreads();
    #pragma unroll
    for (int off = 1; off < SCAN_T; off <<= 1) {
        int x = (t >= off) ? s[t - off] : 0;
        __syncthreads();
        s[t] += x;
        __syncthreads();
    }
    int run = s[t] - tsum;
    #pragma unroll
    for (int j = 0; j < 4; j++) {
        if (base + j < NN) g_rowptr[base + j] = run;
        run += v[j];
    }
    if (t == SCAN_T - 1) g_bsum[blockIdx.x] = s[SCAN_T - 1];
}
__global__ void __launch_bounds__(128) k_scan2() {
    __shared__ int s[128];
    int t = threadIdx.x;
    int v = (t < SCAN_NB) ? g_bsum[t] : 0;
    s[t] = v; __syncthreads();
    #pragma unroll
    for (int off = 1; off < 128; off <<= 1) {
        int x = (t >= off) ? s[t - off] : 0;
        __syncthreads();
        s[t] += x;
        __syncthreads();
    }
    if (t < SCAN_NB) g_bsumx[t] = s[t] - v;
}
__global__ void k_scan3() {
    int i = blockIdx.x * blockDim.x + threadIdx.x;
    if (i < NN) g_rowptr[i] += g_bsumx[i / (SCAN_T * 4)];
    if (i == 0) g_rowptr[NN] = EE;
}
__global__ void k_scatter(const int* __restrict__ src, const int* __restrict__ dst) {
    int e = blockIdx.x * blockDim.x + threadIdx.x;
    if (e >= EE) return;
    int d = dst[e];
    int s = src[e];
    int pos = g_rowptr[d] + atomicAdd(&g_cursor[d], 1);
    float nm = g_dinv[s] * g_dinv[d];
    g_epack[pos] = make_int2(s, __float_as_int(nm));
}

// ============ weight prep: enc transpose (fp32), proj bf16 split, layers fp16 ============
#define SPLIT_TOT (768*128 + 256*128 + 3*128*128)
__global__ void k_split_all(const float* __restrict__ encW, const float* __restrict__ projW,
                            const float* __restrict__ W0, const float* __restrict__ W1,
                            const float* __restrict__ W2) {
    int idx = blockIdx.x * blockDim.x + threadIdx.x;
    if (idx >= SPLIT_TOT) return;
    int local = idx;
    if (local < 768*128) {
        int k = local >> 7, n = local & 127;
        g_bt_enc[n * 768 + k] = encW[local];
        return;
    }
    local -= 768*128;
    if (local < 256*128) {
        int k = local >> 7, n = local & 127;
        float w = projW[local];
        __nv_bfloat16 h = __float2bfloat16_rn(w);
        g_bh_proj[n * 256 + k] = h;
        g_bl_proj[n * 256 + k] = __float2bfloat16_rn(w - __bfloat162float(h));
        return;
    }
    local -= 256*128;
    const float* W; __half* Bt;
    if (local < 128*128)                   { W = W0; Bt = g_bw0h; }
    else if ((local -= 128*128) < 128*128) { W = W1; Bt = g_bw1h; }
    else  { local -= 128*128;                W = W2; Bt = g_bw2h; }
    int k = local >> 7;
    int n = local & 127;
    Bt[n * 128 + k] = __float2half_rn(W[local]);
}

// ============ tf32 GEMM (encoder, pre-LN): C = LN+ReLU(A[M,768] @ W + b) ============
// A raw fp32 via cp.async (tf32 truncation in HW); A+B double-buffered, one group/chunk.
#define TILE32 16384      // 128 rows x 32 fp32 x 4B
#define DYN32  (4 * TILE32 + 1024)

__global__ void __launch_bounds__(256, 1)
k_gemm_tf32(const float* __restrict__ A, int K,
            const float* __restrict__ Bt,
            const float* __restrict__ bias,
            const float* __restrict__ lnG, const float* __restrict__ lnB,
            float* __restrict__ C)
{
    extern __shared__ char dyn[];
    const int tid = threadIdx.x;
    const int rowBase = blockIdx.x * 128;

    uint32_t dynb = smem_u32(dyn);
    char* sm = dyn + (((dynb + 1023u) & ~1023u) - dynb);
    const uint32_t uA0 = smem_u32(sm);
    const uint32_t uB0 = smem_u32(sm + 2 * TILE32);

    const int lane = tid & 31;
    const int warp = tid >> 5;
    const int mBase = (warp & 3) * 32;
    const int nBase = (warp >> 2) * 64;

    const int aRowL = (lane & 7) + ((lane & 8) ? 8 : 0);
    const int aKbL  = (lane & 16) ? 16 : 0;
    const int bRowL = (lane & 7) + ((lane & 16) ? 8 : 0);
    const int bKbL  = (lane & 8) ? 16 : 0;

    float acc[2][8][4];
    #pragma unroll
    for (int mt = 0; mt < 2; mt++)
        #pragma unroll
        for (int nt = 0; nt < 8; nt++)
            #pragma unroll
            for (int j = 0; j < 4; j++) acc[mt][nt][j] = 0.0f;

    const int nChunks = K >> 5;

    auto issueAB = [&](int c, int buf) {
        int k0 = c * 32;
        uint32_t dstA = uA0 + (uint32_t)buf * TILE32;
        uint32_t dstB = uB0 + (uint32_t)buf * TILE32;
        #pragma unroll
        for (int i = 0; i < 4; i++) {
            int idx = i * 256 + tid;     // 0..1023 16B units
            int n   = idx >> 3;          // row 0..127
            int kq  = idx & 7;
            uint32_t off = sw128((uint32_t)(n * 128 + kq * 16));
            if (rowBase + n < NN)
                CP_ASYNC16(dstA + off, (const char*)(A + (size_t)(rowBase + n) * K + k0 + kq * 4));
            CP_ASYNC16(dstB + off, (const char*)(Bt + (size_t)n * K + k0 + kq * 4));
        }
        asm volatile("cp.async.commit_group;" ::: "memory");
    };

    issueAB(0, 0);

    for (int c = 0; c < nChunks; c++) {
        const int buf = c & 1;
        const bool hasNext = (c + 1 < nChunks);

        asm volatile("cp.async.wait_group 0;" ::: "memory");
        __syncthreads();

        if (hasNext) issueAB(c + 1, buf ^ 1);

        const uint32_t uA = uA0 + (uint32_t)buf * TILE32;
        const uint32_t uB = uB0 + (uint32_t)buf * TILE32;

        #pragma unroll
        for (int ks = 0; ks < 4; ks++) {
            const int kb = ks * 32;
            uint32_t af[2][4], bq[4][4];

            #pragma unroll
            for (int mt = 0; mt < 2; mt++)
                ldsm_x4(af[mt], uA + sw128((uint32_t)((mBase + mt * 16 + aRowL) * 128 + kb + aKbL)));
            #pragma unroll
            for (int p = 0; p < 4; p++)
                ldsm_x4(bq[p], uB + sw128((uint32_t)((nBase + p * 16 + bRowL) * 128 + kb + bKbL)));

            #pragma unroll
            for (int mt = 0; mt < 2; mt++)
                #pragma unroll
                for (int p = 0; p < 4; p++) {
                    mma1688_tf32(acc[mt][2 * p],     af[mt], &bq[p][0]);
                    mma1688_tf32(acc[mt][2 * p + 1], af[mt], &bq[p][2]);
                }
        }
        __syncthreads();   // all reads done before next issue overwrites this buf
    }

    // ---- fused LayerNorm + ReLU epilogue (bias pre-LN) ----
    const int rL = lane >> 2;
    const int cL = (lane & 3) * 2;
    float* ssum = (float*)sm;
    float* ssq  = (float*)(sm + 1024);
    const int half = warp >> 2;

    #pragma unroll
    for (int mt = 0; mt < 2; mt++)
        #pragma unroll
        for (int hr = 0; hr < 2; hr++) {
            int lr = mBase + mt * 16 + rL + hr * 8;
            float s = 0.f, q = 0.f;
            #pragma unroll
            for (int nt = 0; nt < 8; nt++)
                #pragma unroll
                for (int cc = 0; cc < 2; cc++) {
                    float v = acc[mt][nt][hr * 2 + cc] + bias[nBase + nt * 8 + cL + cc];
                    s += v; q += v * v;
                }
            s += __shfl_xor_sync(0xffffffffu, s, 1);
            q += __shfl_xor_sync(0xffffffffu, q, 1);
            s += __shfl_xor_sync(0xffffffffu, s, 2);
            q += __shfl_xor_sync(0xffffffffu, q, 2);
            if ((lane & 3) == 0) { ssum[lr * 2 + half] = s; ssq[lr * 2 + half] = q; }
        }
    __syncthreads();

    #pragma unroll
    for (int mt = 0; mt < 2; mt++)
        #pragma unroll
        for (int hr = 0; hr < 2; hr++) {
            int lr  = mBase + mt * 16 + rL + hr * 8;
            int row = rowBase + lr;
            float s = ssum[lr * 2] + ssum[lr * 2 + 1];
            float q = ssq [lr * 2] + ssq [lr * 2 + 1];
            float mu  = s * (1.0f / 128.0f);
            float var = q * (1.0f / 128.0f) - mu * mu;
            float rst = rsqrtf(var + EPSV);
            if (row < NN) {
                #pragma unroll
                for (int nt = 0; nt < 8; nt++) {
                    int col = nBase + nt * 8 + cL;
                    float v0 = acc[mt][nt][hr * 2]     + bias[col];
                    float v1 = acc[mt][nt][hr * 2 + 1] + bias[col + 1];
                    v0 = fmaxf((v0 - mu) * rst * lnG[col]     + lnB[col],     0.f);
                    v1 = fmaxf((v1 - mu) * rst * lnG[col + 1] + lnB[col + 1], 0.f);
                    *(float2*)&C[(size_t)row * 128 + col] = make_float2(v0, v1);
                }
            }
        }
}

// ============ fp16 GEMM (layers): Ch[M,128] = A16[M,128] @ W16, fp32 acc ============
// K=128 fixed (2 k64 chunks). A and B fp16 via cp.async, no conversion anywhere.
#define TILEH 16384      // 128 rows x 64 fp16
#define DYNH  (4 * TILEH + 1024)

__global__ void __launch_bounds__(256, 1)
k_gemm_f16(const __half* __restrict__ A16, const __half* __restrict__ Bt16,
           __half* __restrict__ Ch)
{
    extern __shared__ char dyn[];
    const int tid = threadIdx.x;
    const int rowBase = blockIdx.x * 128;

    uint32_t dynb = smem_u32(dyn);
    char* sm = dyn + (((dynb + 1023u) & ~1023u) - dynb);
    const uint32_t uA0 = smem_u32(sm);
    const uint32_t uB0 = smem_u32(sm + 2 * TILEH);

    const int lane = tid & 31;
    const int warp = tid >> 5;
    const int mBase = (warp & 3) * 32;
    const int nBase = (warp >> 2) * 64;

    const int aRowL = (lane & 7) + ((lane & 8) ? 8 : 0);
    const int aKbL  = (lane & 16) ? 16 : 0;
    const int bRowL = (lane & 7) + ((lane & 16) ? 8 : 0);
    const int bKbL  = (lane & 8) ? 16 : 0;

    float acc[2][8][4];
    #pragma unroll
    for (int mt = 0; mt < 2; mt++)
        #pragma unroll
        for (int nt = 0; nt < 8; nt++)
            #pragma unroll
            for (int j = 0; j < 4; j++) acc[mt][nt][j] = 0.0f;

    auto issueAB = [&](int c, int buf) {
        int k0 = c * 64;
        uint32_t dstA = uA0 + (uint32_t)buf * TILEH;
        uint32_t dstB = uB0 + (uint32_t)buf * TILEH;
        #pragma unroll
        for (int i = 0; i < 4; i++) {
            int idx = i * 256 + tid;     // 0..1023 16B units (128 rows x 8)
            int n   = idx >> 3;
            int kq  = idx & 7;
            uint32_t off = sw128((uint32_t)(n * 128 + kq * 16));
            if (rowBase + n < NN)
                CP_ASYNC16(dstA + off, (const char*)(A16 + (size_t)(rowBase + n) * 128 + k0 + kq * 8));
            CP_ASYNC16(dstB + off, (const char*)(Bt16 + (size_t)n * 128 + k0 + kq * 8));
        }
        asm volatile("cp.async.commit_group;" ::: "memory");
    };

    issueAB(0, 0);
    issueAB(1, 1);

    #pragma unroll
    for (int c = 0; c < 2; c++) {
        if (c == 0) asm volatile("cp.async.wait_group 1;" ::: "memory");
        else        asm volatile("cp.async.wait_group 0;" ::: "memory");
        __syncthreads();

        const uint32_t uA = uA0 + (uint32_t)c * TILEH;
        const uint32_t uB = uB0 + (uint32_t)c * TILEH;

        #pragma unroll
        for (int ks = 0; ks < 4; ks++) {
            const int kb = ks * 32;
            uint32_t af[2][4], bq[4][4];

            #pragma unroll
            for (int mt = 0; mt < 2; mt++)
                ldsm_x4(af[mt], uA + sw128((uint32_t)((mBase + mt * 16 + aRowL) * 128 + kb + aKbL)));
            #pragma unroll
            for (int p = 0; p < 4; p++)
                ldsm_x4(bq[p], uB + sw128((uint32_t)((nBase + p * 16 + bRowL) * 128 + kb + bKbL)));

            #pragma unroll
            for (int mt = 0; mt < 2; mt++)
                #pragma unroll
                for (int p = 0; p < 4; p++) {
                    mma16816_f16(acc[mt][2 * p],     af[mt], &bq[p][0]);
                    mma16816_f16(acc[mt][2 * p + 1], af[mt], &bq[p][2]);
                }
        }
    }

    const int rL = lane >> 2;
    const int cL = (lane & 3) * 2;
    #pragma unroll
    for (int mt = 0; mt < 2; mt++) {
        #pragma unroll
        for (int hr = 0; hr < 2; hr++) {
            int row = rowBase + mBase + mt * 16 + rL + hr * 8;
            if (row >= NN) continue;
            #pragma unroll
            for (int nt = 0; nt < 8; nt++) {
                int col = nBase + nt * 8 + cL;
                *(__half2*)&Ch[(size_t)row * 128 + col] =
                    __floats2half2_rn(acc[mt][nt][hr * 2], acc[mt][nt][hr * 2 + 1]);
            }
        }
    }
}

// ============ pipelined split-bf16 GEMM (projection): fp16 out ============
#define TILE_B 16384
#define GEMM_DYN (8 * TILE_B + 1024)

__global__ void __launch_bounds__(256, 1)
k_gemm_mma(const float* __restrict__ Aa, int strideA,
           const float* __restrict__ Ab, int strideB, int kSplit, int K,
           const __nv_bfloat16* __restrict__ Bh, const __nv_bfloat16* __restrict__ Bl,
           const float* __restrict__ bias,
           __half* __restrict__ Ch)
{
    extern __shared__ char dyn[];
    const int tid = threadIdx.x;
    const int rowBase = blockIdx.x * 128;

    uint32_t dynb = smem_u32(dyn);
    char* sm = dyn + (((dynb + 1023u) & ~1023u) - dynb);
    const uint32_t uA0 = smem_u32(sm);
    const uint32_t uB0 = smem_u32(sm + 4 * TILE_B);

    const int lane = tid & 31;
    const int warp = tid >> 5;
    const int mBase = (warp & 3) * 32;
    const int nBase = (warp >> 2) * 64;

    const int aRowL = (lane & 7) + ((lane & 8) ? 8 : 0);
    const int aKbL  = (lane & 16) ? 16 : 0;
    const int bRowL = (lane & 7) + ((lane & 16) ? 8 : 0);
    const int bKbL  = (lane & 8) ? 16 : 0;

    float acc[2][8][4];
    #pragma unroll
    for (int mt = 0; mt < 2; mt++)
        #pragma unroll
        for (int nt = 0; nt < 8; nt++)
            #pragma unroll
            for (int j = 0; j < 4; j++) acc[mt][nt][j] = 0.0f;

    const int nChunks = K >> 6;
    float4 aF[8];

    auto prefetchA = [&](int c) {
        int k0 = c * 64;
        const float* base; int stride; int koff;
        if (k0 < kSplit) { base = Aa; stride = strideA; koff = k0; }
        else             { base = Ab; stride = strideB; koff = k0 - kSplit; }
        #pragma unroll
        for (int i = 0; i < 8; i++) {
            int fidx = i * 256 + tid;
            int r    = fidx >> 4;
            int kq   = fidx & 15;
            int gr   = rowBase + r;
            aF[i] = make_float4(0.f, 0.f, 0.f, 0.f);
            if (gr < NN) aF[i] = *(const float4*)(base + (size_t)gr * stride + koff + kq * 4);
        }
    };

    auto convertHalf = [&](int buf, int half) {
        char* dh = sm + buf * (2 * TILE_B);
        char* dl = dh + TILE_B;
        #pragma unroll
        for (int i = half * 4; i < half * 4 + 4; i++) {
            int fidx = i * 256 + tid;
            int r    = fidx >> 4;
            int kq   = fidx & 15;
            float r0, r1, r2, r3;
            uint32_t h0 = packbf2(aF[i].x, aF[i].y, &r0, &r1);
            uint32_t h1 = packbf2(aF[i].z, aF[i].w, &r2, &r3);
            uint32_t l0 = packbf2(r0, r1, nullptr, nullptr);
            uint32_t l1 = packbf2(r2, r3, nullptr, nullptr);
            uint32_t off = sw128((uint32_t)(r * 128 + kq * 8));
            *(uint2*)(dh + off) = make_uint2(h0, h1);
            *(uint2*)(dl + off) = make_uint2(l0, l1);
        }
    };

    auto issueB = [&](int c, int buf) {
        int k0 = c * 64;
        uint32_t dst = uB0 + (uint32_t)buf * (2 * TILE_B);
        #pragma unroll
        for (int i = 0; i < 4; i++) {
            int uidx = i * 256 + tid;
            int n    = uidx >> 3;
            int kq   = uidx & 7;
            uint32_t off = sw128((uint32_t)(n * 128 + kq * 16));
            CP_ASYNC16(dst + off,          (const char*)(Bh + (size_t)n * K + k0 + kq * 8));
            CP_ASYNC16(dst + TILE_B + off, (const char*)(Bl + (size_t)n * K + k0 + kq * 8));
        }
        asm volatile("cp.async.commit_group;" ::: "memory");
    };

    prefetchA(0);
    issueB(0, 0);
    convertHalf(0, 0);
    convertHalf(0, 1);
    if (nChunks > 1) prefetchA(1);

    for (int c = 0; c < nChunks; c++) {
        const int buf  = c & 1;
        const bool hasNext = (c + 1 < nChunks);

        asm volatile("cp.async.wait_group 0;" ::: "memory");
        __syncthreads();

        if (hasNext) issueB(c + 1, buf ^ 1);

        const uint32_t uAh = uA0 + (uint32_t)buf * (2 * TILE_B);
        const uint32_t uAl = uAh + TILE_B;
        const uint32_t uBh = uB0 + (uint32_t)buf * (2 * TILE_B);
        const uint32_t uBl = uBh + TILE_B;

        #pragma unroll
        for (int ks = 0; ks < 4; ks++) {
            const int kb = ks * 32;
            uint32_t ah[2][4], al[2][4], bq[4][4];

            #pragma unroll
            for (int mt = 0; mt < 2; mt++)
                ldsm_x4(ah[mt], uAh + sw128((uint32_t)((mBase + mt * 16 + aRowL) * 128 + kb + aKbL)));
            #pragma unroll
            for (int mt = 0; mt < 2; mt++)
                ldsm_x4(al[mt], uAl + sw128((uint32_t)((mBase + mt * 16 + aRowL) * 128 + kb + aKbL)));
            #pragma unroll
            for (int p = 0; p < 4; p++)
                ldsm_x4(bq[p], uBh + sw128((uint32_t)((nBase + p * 16 + bRowL) * 128 + kb + bKbL)));

            #pragma unroll
            for (int mt = 0; mt < 2; mt++)
                #pragma unroll
                for (int p = 0; p < 4; p++) {
                    mma16816_bf16(acc[mt][2 * p],     ah[mt], &bq[p][0]);
                    mma16816_bf16(acc[mt][2 * p + 1], ah[mt], &bq[p][2]);
                }
            #pragma unroll
            for (int mt = 0; mt < 2; mt++)
                #pragma unroll
                for (int p = 0; p < 4; p++) {
                    mma16816_bf16(acc[mt][2 * p],     al[mt], &bq[p][0]);
                    mma16816_bf16(acc[mt][2 * p + 1], al[mt], &bq[p][2]);
                }

            #pragma unroll
            for (int p = 0; p < 4; p++)
                ldsm_x4(bq[p], uBl + sw128((uint32_t)((nBase + p * 16 + bRowL) * 128 + kb + bKbL)));
            #pragma unroll
            for (int mt = 0; mt < 2; mt++)
                #pragma unroll
                for (int p = 0; p < 4; p++) {
                    mma16816_bf16(acc[mt][2 * p],     ah[mt], &bq[p][0]);
                    mma16816_bf16(acc[mt][2 * p + 1], ah[mt], &bq[p][2]);
                }

            if (ks == 0 && hasNext) convertHalf(buf ^ 1, 0);
            if (ks == 1 && hasNext) {
                convertHalf(buf ^ 1, 1);
                if (c + 2 < nChunks) prefetchA(c + 2);
            }
        }
    }

    const int rL = lane >> 2;
    const int cL = (lane & 3) * 2;
    #pragma unroll
    for (int mt = 0; mt < 2; mt++) {
        #pragma unroll
        for (int hr = 0; hr < 2; hr++) {
            int row = rowBase + mBase + mt * 16 + rL + hr * 8;
            if (row >= NN) continue;
            #pragma unroll
            for (int nt = 0; nt < 8; nt++) {
                int col = nBase + nt * 8 + cL;
                float v0 = acc[mt][nt][hr * 2]     + bias[col];
                float v1 = acc[mt][nt][hr * 2 + 1] + bias[col + 1];
                *(__half2*)&Ch[(size_t)row * 128 + col] = __floats2half2_rn(v0, v1);
            }
        }
    }
}

// ====== fused CSR SPMM (fp16 gather): out = act(dinv^2*xw[d] + sum norm*xw[src] + b) ======
__global__ void __launch_bounds__(256)
k_spmm_csr(const float* __restrict__ bias,
           float* __restrict__ outF, __half* __restrict__ outH, int relu)
{
    int w = (blockIdx.x * blockDim.x + threadIdx.x) >> 5;
    if (w >= NN) return;
    int lane = threadIdx.x & 31;
    int c = lane * 4;

    float di = g_dinv[w];
    float wt = di * di;
    float4 sv = ldh4(&g_xwh[(size_t)w * 128], c);
    float4 acc = make_float4(sv.x * wt, sv.y * wt, sv.z * wt, sv.w * wt);
    float4 acc2 = make_float4(0.f, 0.f, 0.f, 0.f);

    int start = g_rowptr[w];
    int end   = g_rowptr[w + 1];
    for (int base = start; base < end; base += 32) {
        int rem = end - base;
        int2 p = make_int2(0, 0);
        if (lane < rem) p = g_epack[base + lane];
        if (rem >= 32) {
            #pragma unroll
            for (int j = 0; j < 32; j += 2) {
                int   s0  = __shfl_sync(0xffffffffu, p.x, j);
                float nm0 = __int_as_float(__shfl_sync(0xffffffffu, p.y, j));
                int   s1  = __shfl_sync(0xffffffffu, p.x, j + 1);
                float nm1 = __int_as_float(__shfl_sync(0xffffffffu, p.y, j + 1));
                float4 v0 = ldh4(&g_xwh[(size_t)s0 * 128], c);
                float4 v1 = ldh4(&g_xwh[(size_t)s1 * 128], c);
                acc.x  = fmaf(nm0, v0.x, acc.x);
                acc.y  = fmaf(nm0, v0.y, acc.y);
                acc.z  = fmaf(nm0, v0.z, acc.z);
                acc.w  = fmaf(nm0, v0.w, acc.w);
                acc2.x = fmaf(nm1, v1.x, acc2.x);
                acc2.y = fmaf(nm1, v1.y, acc2.y);
                acc2.z = fmaf(nm1, v1.z, acc2.z);
                acc2.w = fmaf(nm1, v1.w, acc2.w);
            }
        } else {
            for (int j = 0; j < rem; j++) {
                int   s  = __shfl_sync(0xffffffffu, p.x, j);
                float nm = __int_as_float(__shfl_sync(0xffffffffu, p.y, j));
                float4 v = ldh4(&g_xwh[(size_t)s * 128], c);
                acc.x = fmaf(nm, v.x, acc.x);
                acc.y = fmaf(nm, v.y, acc.y);
                acc.z = fmaf(nm, v.z, acc.z);
                acc.w = fmaf(nm, v.w, acc.w);
            }
        }
    }
    acc.x += acc2.x; acc.y += acc2.y; acc.z += acc2.z; acc.w += acc2.w;

    float4 bb = *(const float4*)&bias[c];
    acc.x += bb.x; acc.y += bb.y; acc.z += bb.z; acc.w += bb.w;
    if (relu) {
        acc.x = fmaxf(acc.x, 0.f); acc.y = fmaxf(acc.y, 0.f);
        acc.z = fmaxf(acc.z, 0.f); acc.w = fmaxf(acc.w, 0.f);
    }
    if (outF) *(float4*)&outF[(size_t)w * 128 + c] = acc;
    if (outH) {
        uint2 u;
        __half2 h0 = __floats2half2_rn(acc.x, acc.y);
        __half2 h1 = __floats2half2_rn(acc.z, acc.w);
        u.x = *reinterpret_cast<uint32_t*>(&h0);
        u.y = *reinterpret_cast<uint32_t*>(&h1);
        *(uint2*)&outH[(size_t)w * 128 + c] = u;
    }
}

// ================= launch =================
extern "C" void kernel_launch(void* const* d_in, const int* in_sizes, int n_in,
                              void* d_out, int out_size)
{
    (void)in_sizes; (void)n_in; (void)out_size;
    const int*   ei    = (const int*)  d_in[0];
    const float* ext   = (const float*)d_in[1];
    const float* emb   = (const float*)d_in[2];
    const float* encW  = (const float*)d_in[3];
    const float* encB  = (const float*)d_in[4];
    const float* lng   = (const float*)d_in[5];
    const float* lnb   = (const float*)d_in[6];
    const float* projW = (const float*)d_in[7];
    const float* projB = (const float*)d_in[8];
    const float* W0    = (const float*)d_in[9];
    const float* b0    = (const float*)d_in[10];
    const float* W1    = (const float*)d_in[11];
    const float* b1    = (const float*)d_in[12];
    const float* W2    = (const float*)d_in[13];
    const float* b2    = (const float*)d_in[14];
    float* out = (float*)d_out;

    const int* src = ei;
    const int* dst = ei + EE;

    float *p_tmp, *bt_enc;
    __half *p_xh, *p_xwh, *w0h, *w1h, *w2h;
    cudaGetSymbolAddress((void**)&p_tmp, g_tmp);
    cudaGetSymbolAddress((void**)&p_xh,  g_xh);
    cudaGetSymbolAddress((void**)&p_xwh, g_xwh);
    cudaGetSymbolAddress((void**)&bt_enc, g_bt_enc);
    cudaGetSymbolAddress((void**)&w0h, g_bw0h);
    cudaGetSymbolAddress((void**)&w1h, g_bw1h);
    cudaGetSymbolAddress((void**)&w2h, g_bw2h);

    __nv_bfloat16 *bh_proj, *bl_proj;
    cudaGetSymbolAddress((void**)&bh_proj, g_bh_proj);
    cudaGetSymbolAddress((void**)&bl_proj, g_bl_proj);

    cudaFuncSetAttribute(k_gemm_mma,  cudaFuncAttributeMaxDynamicSharedMemorySize, GEMM_DYN);
    cudaFuncSetAttribute(k_gemm_tf32, cudaFuncAttributeMaxDynamicSharedMemorySize, DYN32);
    cudaFuncSetAttribute(k_gemm_f16,  cudaFuncAttributeMaxDynamicSharedMemorySize, DYNH);

    static cudaStream_t sB = nullptr;
    static cudaEvent_t evF = nullptr, evJ = nullptr;
    if (!sB) {
        cudaStreamCreate(&sB);
        cudaEventCreateWithFlags(&evF, cudaEventDisableTiming);
        cudaEventCreateWithFlags(&evJ, cudaEventDisableTiming);
    }

    const int TB = 256;
    const int gN     = (NN + TB - 1) / TB;
    const int gE     = (EE + TB - 1) / TB;
    const int gRow   = (NN * 32 + TB - 1) / TB;
    const int gGemm  = (NN + 127) / 128;

    // ---- fork: CSR build on side stream ----
    cudaEventRecord(evF, 0);
    cudaStreamWaitEvent(sB, evF, 0);

    k_zero<<<gN, TB, 0, sB>>>();
    k_degree<<<gE, TB, 0, sB>>>(dst);
    k_scan1<<<SCAN_NB, SCAN_T, 0, sB>>>();
    k_scan2<<<1, 128, 0, sB>>>();
    k_scan3<<<gN, TB, 0, sB>>>();
    k_scatter<<<gE, TB, 0, sB>>>(src, dst);
    cudaEventRecord(evJ, sB);

    // main stream: weight prep + dense chain
    k_split_all<<<(SPLIT_TOT + TB - 1) / TB, TB>>>(encW, projW, W0, W1, W2);

    // encoder GEMM (tf32, pre-LN) with fused LN+ReLU
    k_gemm_tf32<<<gGemm, TB, DYN32>>>(ext, EXTD, bt_enc, encB, lng, lnb, p_tmp);

    // projection (split-bf16): A = [emb | feat] dual fp32 source -> fp16 x
    k_gemm_mma<<<gGemm, TB, GEMM_DYN>>>(emb, HH, p_tmp, HH, HH, 2 * HH,
                                        bh_proj, bl_proj, projB, p_xh);

    // layer 0 GEMM (fp16) -> fp16 xw
    k_gemm_f16<<<gGemm, TB, DYNH>>>(p_xh, w0h, p_xwh);

    // ---- join: SPMM needs the CSR ----
    cudaStreamWaitEvent(0, evJ, 0);

    k_spmm_csr<<<gRow, TB>>>(b0, nullptr, p_xh, 1);

    k_gemm_f16<<<gGemm, TB, DYNH>>>(p_xh, w1h, p_xwh);
    k_spmm_csr<<<gRow, TB>>>(b1, nullptr, p_xh, 1);

    k_gemm_f16<<<gGemm, TB, DYNH>>>(p_xh, w2h, p_xwh);
    k_spmm_csr<<<gRow, TB>>>(b2, out, nullptr, 0);
}